// round 2
// baseline (speedup 1.0000x reference)
#include <cuda_runtime.h>
#include <math.h>

#define Bq 2
#define Tq 2048
#define Hq 12
#define Eq 64
#define Mq 256
#define NB 32            // T / 64
#define BH 24            // B*H
#define ROWSTRIDE (Hq*Eq)  // 768 floats between consecutive t

#define DN 0.35355339059327379f         // sqrt(1/sqrt(E))
#define TEMP 0.125f                     // 1/sqrt(E)
#define HALF_LOG_M 2.7725887222397811f  // 0.5*log(256)
#define NEG_INF __int_as_float(0xff800000)

// ---------------- device scratch ----------------
__device__ float g_projT[Eq*Mq];                 // [e][m], dn folded
__device__ float g_qT  [BH*Tq*Eq];               // per block: [e][i], temp folded
__device__ float g_kT  [BH*Tq*Eq];               // per block: [e][j], raw k
__device__ float g_ksh [BH*NB*Mq*64];            // per block: [m][j]; k_shift then k_prime
__device__ float g_qpT [BH*NB*Mq*64];            // per block: [m][i]; q_prime
__device__ float g_qls [BH*Tq];                  // q_log_scale
__device__ float g_sk  [BH];                     // per-(b,h) max of k_shift
__device__ float g_kv  [BH*Mq*Eq];               // [m][d]
__device__ float g_kps [BH*Mq];
__device__ float g_kvpart [BH*8*Mq*Eq];
__device__ float g_kpspart[BH*8*Mq];

// ---------------- helpers ----------------
__device__ __forceinline__ void atomicMaxFloat(float* addr, float val) {
    int* ia = (int*)addr;
    int old = *ia;
    while (__int_as_float(old) < val) {
        int assumed = old;
        old = atomicCAS(ia, assumed, __float_as_int(val));
        if (old == assumed) break;
    }
}

__device__ __forceinline__ float grpMax16(float v) {
    v = fmaxf(v, __shfl_xor_sync(0xffffffffu, v, 1));
    v = fmaxf(v, __shfl_xor_sync(0xffffffffu, v, 2));
    v = fmaxf(v, __shfl_xor_sync(0xffffffffu, v, 4));
    v = fmaxf(v, __shfl_xor_sync(0xffffffffu, v, 8));
    return v;
}
__device__ __forceinline__ float grpSum16(float v) {
    v += __shfl_xor_sync(0xffffffffu, v, 1);
    v += __shfl_xor_sync(0xffffffffu, v, 2);
    v += __shfl_xor_sync(0xffffffffu, v, 4);
    v += __shfl_xor_sync(0xffffffffu, v, 8);
    return v;
}

// C[r][c] += sum_k A[k*lda + ty*4 + r] * B[k*ldb + tx*4 + c]; both k-major.
__device__ __forceinline__ void gemm_acc(float C[4][4],
        const float* __restrict__ A, int lda,
        const float* __restrict__ Bm, int ldb, int K, int tx, int ty)
{
    const float* ap = A + ty*4;
    const float* bp = Bm + tx*4;
#pragma unroll 8
    for (int k = 0; k < K; ++k) {
        float4 a = *(const float4*)(ap + (size_t)k*lda);
        float4 b = *(const float4*)(bp + (size_t)k*ldb);
        C[0][0] += a.x*b.x; C[0][1] += a.x*b.y; C[0][2] += a.x*b.z; C[0][3] += a.x*b.w;
        C[1][0] += a.y*b.x; C[1][1] += a.y*b.y; C[1][2] += a.y*b.z; C[1][3] += a.y*b.w;
        C[2][0] += a.z*b.x; C[2][1] += a.z*b.y; C[2][2] += a.z*b.z; C[2][3] += a.z*b.w;
        C[3][0] += a.w*b.x; C[3][1] += a.w*b.y; C[3][2] += a.w*b.z; C[3][3] += a.w*b.w;
    }
}

// ---------------- kernel 0: init ----------------
__global__ void init_kernel(const float* __restrict__ proj) {
    int idx = blockIdx.x*256 + threadIdx.x;
    if (idx < Eq*Mq) {
        int e = idx >> 8;
        int m = idx & 255;
        g_projT[idx] = proj[m*Eq + e] * DN;
    }
    if (idx < BH) g_sk[idx] = NEG_INF;
}

// ---------------- kernel 1: k side ----------------
__global__ __launch_bounds__(256,1) void kside_kernel(const float* __restrict__ key) {
    extern __shared__ float sm[];
    float* sP    = sm;            // 16384 : projT [e][m]
    float* sA    = sm + 16384;    // 4096  : k tile transposed [e][j]
    float* sDiag = sm + 20480;    // 64
    float* sRed  = sm + 20544;    // 8 (+pad)
    int tid = threadIdx.x, tx = tid & 15, ty = tid >> 4;
    int bidx = blockIdx.x, blk = bidx & 31, bh = bidx >> 5;
    int b = bh / Hq, h = bh % Hq;
    int t0 = blk * 64;

    for (int i = tid; i < 16384; i += 256) sP[i] = g_projT[i];
    const float* kb = key + ((size_t)(b*Tq + t0)*Hq + h)*Eq;
    for (int i = tid; i < 4096; i += 256) {
        int j = i >> 6, e = i & 63;
        sA[e*64 + j] = kb[(size_t)j*ROWSTRIDE + e];
    }
    __syncthreads();
    float* ktg = g_kT + (size_t)bidx * 4096;
    for (int i = tid; i < 4096; i += 256) ktg[i] = sA[i];
    if (tid < 64) {
        float s = 0.f;
#pragma unroll
        for (int e = 0; e < 64; ++e) { float v = sA[e*64 + tid]; s += v*v; }
        sDiag[tid] = 0.0625f * s;   // 0.5 * temp * sum(k^2)
    }
    __syncthreads();

    float dg0 = sDiag[ty*4+0], dg1 = sDiag[ty*4+1], dg2 = sDiag[ty*4+2], dg3 = sDiag[ty*4+3];
    float lmax = NEG_INF;
    float* og = g_ksh + (size_t)bidx * 16384;
#pragma unroll
    for (int cg = 0; cg < 4; ++cg) {
        float C[4][4] = {};
        gemm_acc(C, sA, 64, sP + cg*64, 256, 64, tx, ty);  // C[j][m_local]
#pragma unroll
        for (int c = 0; c < 4; ++c) {
            float4 o;
            o.x = C[0][c] - dg0; o.y = C[1][c] - dg1; o.z = C[2][c] - dg2; o.w = C[3][c] - dg3;
            lmax = fmaxf(lmax, fmaxf(fmaxf(o.x, o.y), fmaxf(o.z, o.w)));
            *(float4*)(og + (size_t)(cg*64 + tx*4 + c)*64 + ty*4) = o;   // [m][j]
        }
    }
#pragma unroll
    for (int off = 16; off; off >>= 1) lmax = fmaxf(lmax, __shfl_xor_sync(0xffffffffu, lmax, off));
    if ((tid & 31) == 0) sRed[tid >> 5] = lmax;
    __syncthreads();
    if (tid == 0) {
        float m = sRed[0];
#pragma unroll
        for (int i = 1; i < 8; ++i) m = fmaxf(m, sRed[i]);
        atomicMaxFloat(&g_sk[bh], m);
    }
}

// ---------------- kernel 2: k_prime (in place) + partial kpsum / kv ----------------
__global__ __launch_bounds__(256,1) void k2_kernel(const float* __restrict__ value) {
    __shared__ __align__(16) float sV[4096];   // [j][d]
    int tid = threadIdx.x;
    int bh = blockIdx.x >> 3, qc = blockIdx.x & 7;
    int b = bh / Hq, h = bh % Hq;
    float sk = g_sk[bh];
    float acc[64];
#pragma unroll
    for (int d = 0; d < 64; ++d) acc[d] = 0.f;
    float ksum = 0.f;

    for (int sb = 0; sb < 4; ++sb) {
        int sblk = qc*4 + sb;
        const float* vb = value + ((size_t)(b*Tq + sblk*64)*Hq + h)*Eq;
        __syncthreads();
        for (int i = tid; i < 4096; i += 256)
            sV[i] = vb[(size_t)(i>>6)*ROWSTRIDE + (i&63)];
        __syncthreads();
        float* kbuf = g_ksh + ((size_t)((bh*32 + sblk)*256 + tid))*64;
        for (int j = 0; j < 64; j += 4) {
            float4 kv4 = *(float4*)(kbuf + j);
            float p0 = __expf(kv4.x - sk);
            float p1 = __expf(kv4.y - sk);
            float p2 = __expf(kv4.z - sk);
            float p3 = __expf(kv4.w - sk);
            *(float4*)(kbuf + j) = make_float4(p0, p1, p2, p3);
            ksum += p0 + p1 + p2 + p3;
            float pj[4] = {p0, p1, p2, p3};
#pragma unroll
            for (int jj = 0; jj < 4; ++jj) {
                const float4* vr = (const float4*)(sV + (j+jj)*64);
                float p = pj[jj];
#pragma unroll
                for (int d4 = 0; d4 < 16; ++d4) {
                    float4 vv = vr[d4];
                    acc[d4*4+0] += p*vv.x;
                    acc[d4*4+1] += p*vv.y;
                    acc[d4*4+2] += p*vv.z;
                    acc[d4*4+3] += p*vv.w;
                }
            }
        }
    }
    float* kvout = g_kvpart + ((size_t)(bh*8 + qc)*256 + tid)*64;
#pragma unroll
    for (int d4 = 0; d4 < 16; ++d4)
        ((float4*)kvout)[d4] = make_float4(acc[d4*4], acc[d4*4+1], acc[d4*4+2], acc[d4*4+3]);
    g_kpspart[(bh*8 + qc)*256 + tid] = ksum;
}

// ---------------- kernel 2b: reduce partials ----------------
__global__ void reduce_kernel() {
    int idx = blockIdx.x*256 + threadIdx.x;
    if (idx < BH*Mq*Eq) {
        int bh = idx >> 14;
        int rem = idx & 16383;
        float s = 0.f;
#pragma unroll
        for (int qc = 0; qc < 8; ++qc) s += g_kvpart[(size_t)(bh*8 + qc)*16384 + rem];
        g_kv[idx] = s;
    }
    if (idx < BH*Mq) {
        int bh = idx >> 8; int m = idx & 255;
        float s = 0.f;
#pragma unroll
        for (int qc = 0; qc < 8; ++qc) s += g_kpspart[(bh*8 + qc)*256 + m];
        g_kps[idx] = s;
    }
}

// ---------------- kernel 3: q side ----------------
__global__ __launch_bounds__(256,1) void qside_kernel(const float* __restrict__ query) {
    extern __shared__ float sm[];
    float* sP    = sm;            // 16384 : projT [e][m]
    float* sA    = sm + 16384;    // 4096  : q tile transposed [e][i]
    float* sDiag = sm + 20480;    // 64
    int tid = threadIdx.x, tx = tid & 15, ty = tid >> 4;
    int bidx = blockIdx.x, blk = bidx & 31, bh = bidx >> 5;
    int b = bh / Hq, h = bh % Hq;
    int t0 = blk * 64;

    for (int i = tid; i < 16384; i += 256) sP[i] = g_projT[i];
    const float* qb = query + ((size_t)(b*Tq + t0)*Hq + h)*Eq;
    for (int i = tid; i < 4096; i += 256) {
        int j = i >> 6, e = i & 63;
        sA[e*64 + j] = qb[(size_t)j*ROWSTRIDE + e];
    }
    __syncthreads();
    float* qtg = g_qT + (size_t)bidx * 4096;
    for (int i = tid; i < 4096; i += 256) qtg[i] = sA[i] * TEMP;
    if (tid < 64) {
        float s = 0.f;
#pragma unroll
        for (int e = 0; e < 64; ++e) { float v = sA[e*64 + tid]; s += v*v; }
        sDiag[tid] = 0.0625f * s;   // q_diag
    }
    __syncthreads();

    float C4[4][4][4] = {};
#pragma unroll
    for (int cg = 0; cg < 4; ++cg)
        gemm_acc(C4[cg], sA, 64, sP + cg*64, 256, 64, tx, ty);  // C[i][m_local]

    float rm[4];
#pragma unroll
    for (int r = 0; r < 4; ++r) {
        float mx = NEG_INF;
#pragma unroll
        for (int cg = 0; cg < 4; ++cg)
#pragma unroll
            for (int c = 0; c < 4; ++c) mx = fmaxf(mx, C4[cg][r][c]);
        rm[r] = grpMax16(mx);
    }
    float* qg = g_qpT + (size_t)bidx * 16384;
#pragma unroll
    for (int cg = 0; cg < 4; ++cg)
#pragma unroll
        for (int c = 0; c < 4; ++c) {
            float4 o;
            o.x = __expf(C4[cg][0][c] - rm[0]);
            o.y = __expf(C4[cg][1][c] - rm[1]);
            o.z = __expf(C4[cg][2][c] - rm[2]);
            o.w = __expf(C4[cg][3][c] - rm[3]);
            *(float4*)(qg + (size_t)(cg*64 + tx*4 + c)*64 + ty*4) = o;  // [m][i]
        }
    if (tx == 0) {
#pragma unroll
        for (int r = 0; r < 4; ++r) {
            int i = ty*4 + r;
            g_qls[bh*Tq + t0 + i] = rm[r] - sDiag[i] - HALF_LOG_M;
        }
    }
}

// ---------------- kernel 4: main fused block-local + combine ----------------
__global__ __launch_bounds__(256,1) void main_kernel(const float* __restrict__ value,
                                                     float* __restrict__ out) {
    extern __shared__ float sm[];
    float* sQT  = sm;            // 4096  [e][i]
    float* sQP  = sm + 4096;     // 16384 [m][i]
    float* sKT  = sm + 20480;    // 4096  [e][j] / reused as sD [j][i]
    float* sKP  = sm + 24576;    // 16384 [m][j] / reused: sV [j][d] then sKV [m][d]
    float* sKps = sm + 40960;    // 256
    float* sQls = sm + 41216;    // 64
    float* sLse = sm + 41280;    // 64
    float* sDp  = sm + 41344;    // 64
    float* sQpk = sm + 41408;    // 256
    float* sLn  = sm + 41664;    // 64
    float* sPs  = sm + 41728;    // 64

    int tid = threadIdx.x, tx = tid & 15, ty = tid >> 4;
    int bidx = blockIdx.x, blk = bidx & 31, bh = bidx >> 5;
    int b = bh / Hq, h = bh % Hq;
    int t0 = blk * 64;
    float sk = g_sk[bh];

    // persistent operand loads
    {
        const float4* s1 = (const float4*)(g_qT + (size_t)bidx*4096);
        for (int i = tid; i < 1024; i += 256) ((float4*)sQT)[i] = s1[i];
        const float4* s2 = (const float4*)(g_qpT + (size_t)bidx*16384);
        for (int i = tid; i < 4096; i += 256) ((float4*)sQP)[i] = s2[i];
        sKps[tid] = g_kps[bh*Mq + tid];
        if (tid < 64) sQls[tid] = g_qls[bh*Tq + t0 + tid];
    }

    bool val[3];
    float Cqk[3][4][4] = {};
    float Cdp[3][4][4] = {};
#pragma unroll
    for (int w = 0; w < 3; ++w) {
        int nb = blk - 1 + w;
        val[w] = (nb >= 0) && (nb < NB);
        if (!val[w]) continue;
        __syncthreads();
        size_t kb = (size_t)(bh*32 + nb);
        const float4* k1 = (const float4*)(g_kT  + kb*4096);
        for (int i = tid; i < 1024; i += 256) ((float4*)sKT)[i] = k1[i];
        const float4* k2 = (const float4*)(g_ksh + kb*16384);
        for (int i = tid; i < 4096; i += 256) ((float4*)sKP)[i] = k2[i];
        __syncthreads();
        gemm_acc(Cqk[w], sQT, 64, sKT, 64, 64,  tx, ty);   // temp*q.k
        gemm_acc(Cdp[w], sQP, 64, sKP, 64, 256, tx, ty);   // q'.k'
    }

    // ---- phase 2: per-row stats ----
#pragma unroll
    for (int r = 0; r < 4; ++r) {
        float mx = NEG_INF;
        float dp = 0.f;
#pragma unroll
        for (int w = 0; w < 3; ++w) {
            if (!val[w]) continue;
#pragma unroll
            for (int c = 0; c < 4; ++c) { mx = fmaxf(mx, Cqk[w][r][c]); dp += Cdp[w][r][c]; }
        }
        mx = grpMax16(mx);
        float se = 0.f;
#pragma unroll
        for (int w = 0; w < 3; ++w) {
            if (!val[w]) continue;
#pragma unroll
            for (int c = 0; c < 4; ++c) se += __expf(Cqk[w][r][c] - mx);
        }
        se = grpSum16(se);
        dp = grpSum16(dp);
        if (tx == 0) { sLse[ty*4+r] = mx + __logf(se); sDp[ty*4+r] = dp; }
    }
    __syncthreads();

    // qp_kp_1 partials
    {
        int i = tid & 63, part = tid >> 6;
        float s = 0.f;
#pragma unroll 16
        for (int mm = 0; mm < 64; ++mm) {
            int m = part*64 + mm;
            s += sQP[m*64 + i] * sKps[m];
        }
        sQpk[part*64 + i] = s;
    }
    __syncthreads();
    if (tid < 64) {
        float qpk1 = sQpk[tid] + sQpk[64+tid] + sQpk[128+tid] + sQpk[192+tid];
        float lse = sLse[tid], dp = sDp[tid];
        float pls = sQls[tid] + sk - HALF_LOG_M;
        float lr  = __logf(fmaxf(qpk1 - dp, 1e-24f)) + pls;
        float mxv = fmaxf(lse, lr);
        float ln  = mxv + log1pf(__expf(-fabsf(lse - lr)));
        sLn[tid] = ln;
        sPs[tid] = __expf(pls - ln);
    }
    __syncthreads();

    float lnr[4], psr[4];
#pragma unroll
    for (int r = 0; r < 4; ++r) { lnr[r] = sLn[ty*4+r]; psr[r] = sPs[ty*4+r]; }

    // ---- phase 3: dots -> out_bs ----
    float Cout[4][4] = {};
#pragma unroll
    for (int w = 0; w < 3; ++w) {
        if (!val[w]) continue;
        int nb = blk - 1 + w;
        __syncthreads();
#pragma unroll
        for (int c = 0; c < 4; ++c) {
            int j = tx*4 + c;
            float4 o;
            o.x = __expf(Cqk[w][0][c] - lnr[0]) - Cdp[w][0][c]*psr[0];
            o.y = __expf(Cqk[w][1][c] - lnr[1]) - Cdp[w][1][c]*psr[1];
            o.z = __expf(Cqk[w][2][c] - lnr[2]) - Cdp[w][2][c]*psr[2];
            o.w = __expf(Cqk[w][3][c] - lnr[3]) - Cdp[w][3][c]*psr[3];
            *(float4*)(sKT + (size_t)j*64 + ty*4) = o;    // sD[j][i]
        }
        const float* vb = value + ((size_t)(b*Tq + nb*64)*Hq + h)*Eq;
        for (int i2 = tid; i2 < 1024; i2 += 256) {
            int j = i2 >> 4, dd = (i2 & 15)*4;
            *(float4*)(sKP + (size_t)j*64 + dd) = *(const float4*)(vb + (size_t)j*ROWSTRIDE + dd);
        }
        __syncthreads();
        gemm_acc(Cout, sKT, 64, sKP, 64, 64, tx, ty);     // dots . v
    }

    // ---- phase 4: qp_kp_v ----
    __syncthreads();
    {
        const float4* kvsrc = (const float4*)(g_kv + (size_t)bh*16384);
        for (int i = tid; i < 4096; i += 256) ((float4*)sKP)[i] = kvsrc[i];
    }
    __syncthreads();
    float C2[4][4] = {};
    gemm_acc(C2, sQP, 64, sKP, 64, 256, tx, ty);          // q'. kv

    float* ob = out + ((size_t)(b*Tq + t0)*Hq + h)*Eq;
#pragma unroll
    for (int r = 0; r < 4; ++r) {
        int i = ty*4 + r;
        float4 o;
        o.x = Cout[r][0] + C2[r][0]*psr[r];
        o.y = Cout[r][1] + C2[r][1]*psr[r];
        o.z = Cout[r][2] + C2[r][2]*psr[r];
        o.w = Cout[r][3] + C2[r][3]*psr[r];
        *(float4*)(ob + (size_t)i*ROWSTRIDE + tx*4) = o;
    }
}

// ---------------- launch ----------------
extern "C" void kernel_launch(void* const* d_in, const int* in_sizes, int n_in,
                              void* d_out, int out_size) {
    const float* query = (const float*)d_in[0];
    const float* key   = (const float*)d_in[1];
    const float* value = (const float*)d_in[2];
    const float* proj  = (const float*)d_in[3];
    float* out = (float*)d_out;

    const int SM_SIDE = (16384 + 4096 + 64 + 32) * 4;        // 82304
    const int SM_MAIN = 41792 * 4;                            // 167168

    cudaFuncSetAttribute(kside_kernel, cudaFuncAttributeMaxDynamicSharedMemorySize, SM_SIDE);
    cudaFuncSetAttribute(qside_kernel, cudaFuncAttributeMaxDynamicSharedMemorySize, SM_SIDE);
    cudaFuncSetAttribute(main_kernel,  cudaFuncAttributeMaxDynamicSharedMemorySize, SM_MAIN);

    init_kernel<<<64, 256>>>(proj);
    kside_kernel<<<BH*NB, 256, SM_SIDE>>>(key);
    k2_kernel<<<BH*8, 256>>>(value);
    reduce_kernel<<<(BH*Mq*Eq + 255)/256, 256>>>();
    qside_kernel<<<BH*NB, 256, SM_SIDE>>>(query);
    main_kernel<<<BH*NB, 256, SM_MAIN>>>(value, out);
}

// round 3
// speedup vs baseline: 1.0839x; 1.0839x over previous
#include <cuda_runtime.h>
#include <math.h>
#include <stdint.h>

#define Bq 2
#define Tq 2048
#define Hq 12
#define Eq 64
#define Mq 256
#define NB 32            // T / 64
#define BH 24            // B*H
#define ROWSTRIDE (Hq*Eq)  // 768 floats between consecutive t
#define SP 72            // padded smem stride (conflict-free MMA fragment loads)

#define DN 0.35355339059327379f         // sqrt(1/sqrt(E))
#define TEMP 0.125f                     // 1/sqrt(E)
#define HALF_LOG_M 2.7725887222397811f  // 0.5*log(256)
#define NEG_INF __int_as_float(0xff800000)

// ---------------- device scratch ----------------
__device__ float g_projT[Eq*Mq];                 // [e][m], dn folded
__device__ float g_qT  [BH*Tq*Eq];               // per block: [e][i], temp folded
__device__ float g_kT  [BH*Tq*Eq];               // per block: [e][j], raw k
__device__ float g_ksh [BH*NB*Mq*64];            // per block: [m][j]; k_shift then k_prime
__device__ float g_qpT [BH*NB*Mq*64];            // per block: [m][i]; q_prime (tf32-rounded)
__device__ float g_qls [BH*Tq];                  // q_log_scale
__device__ float g_sk  [BH];                     // per-(b,h) max of k_shift
__device__ float g_kv  [BH*Mq*Eq];               // [m][d]
__device__ float g_kps [BH*Mq];
__device__ float g_kvpart [BH*32*Mq*Eq];
__device__ float g_kpspart[BH*32*Mq];

// ---------------- helpers ----------------
__device__ __forceinline__ float tf32_rna(float x) {
    uint32_t r;
    asm("cvt.rna.tf32.f32 %0, %1;" : "=r"(r) : "f"(x));
    return __uint_as_float(r);
}

// D(16x8) += A(16x8) * B(8x8); tf32 inputs, f32 accum.
__device__ __forceinline__ void mma_tf32(float c[4],
        float a0, float a1, float a2, float a3, float b0, float b1)
{
    asm volatile(
        "mma.sync.aligned.m16n8k8.row.col.f32.tf32.tf32.f32 "
        "{%0,%1,%2,%3}, {%4,%5,%6,%7}, {%8,%9}, {%0,%1,%2,%3};\n"
        : "+f"(c[0]), "+f"(c[1]), "+f"(c[2]), "+f"(c[3])
        : "r"(__float_as_uint(a0)), "r"(__float_as_uint(a1)),
          "r"(__float_as_uint(a2)), "r"(__float_as_uint(a3)),
          "r"(__float_as_uint(b0)), "r"(__float_as_uint(b1)));
}

__device__ __forceinline__ void atomicMaxFloat(float* addr, float val) {
    int* ia = (int*)addr;
    int old = *ia;
    while (__int_as_float(old) < val) {
        int assumed = old;
        old = atomicCAS(ia, assumed, __float_as_int(val));
        if (old == assumed) break;
    }
}

__device__ __forceinline__ float grpMax16(float v) {
    v = fmaxf(v, __shfl_xor_sync(0xffffffffu, v, 1));
    v = fmaxf(v, __shfl_xor_sync(0xffffffffu, v, 2));
    v = fmaxf(v, __shfl_xor_sync(0xffffffffu, v, 4));
    v = fmaxf(v, __shfl_xor_sync(0xffffffffu, v, 8));
    return v;
}

// scalar register-tiled GEMM (used by side kernels)
__device__ __forceinline__ void gemm_acc(float C[4][4],
        const float* __restrict__ A, int lda,
        const float* __restrict__ Bm, int ldb, int K, int tx, int ty)
{
    const float* ap = A + ty*4;
    const float* bp = Bm + tx*4;
#pragma unroll 8
    for (int k = 0; k < K; ++k) {
        float4 a = *(const float4*)(ap + (size_t)k*lda);
        float4 b = *(const float4*)(bp + (size_t)k*ldb);
        C[0][0] += a.x*b.x; C[0][1] += a.x*b.y; C[0][2] += a.x*b.z; C[0][3] += a.x*b.w;
        C[1][0] += a.y*b.x; C[1][1] += a.y*b.y; C[1][2] += a.y*b.z; C[1][3] += a.y*b.w;
        C[2][0] += a.z*b.x; C[2][1] += a.z*b.y; C[2][2] += a.z*b.z; C[2][3] += a.z*b.w;
        C[3][0] += a.w*b.x; C[3][1] += a.w*b.y; C[3][2] += a.w*b.z; C[3][3] += a.w*b.w;
    }
}

// ---------------- kernel 0: init ----------------
__global__ void init_kernel(const float* __restrict__ proj) {
    int idx = blockIdx.x*256 + threadIdx.x;
    if (idx < Eq*Mq) {
        int e = idx >> 8;
        int m = idx & 255;
        g_projT[idx] = proj[m*Eq + e] * DN;
    }
    if (idx < BH) g_sk[idx] = NEG_INF;
}

// ---------------- kernel 1: k side ----------------
__global__ __launch_bounds__(256,1) void kside_kernel(const float* __restrict__ key) {
    extern __shared__ float sm[];
    float* sP    = sm;            // 16384 : projT [e][m]
    float* sA    = sm + 16384;    // 4096  : k tile transposed [e][j]
    float* sDiag = sm + 20480;    // 64
    float* sRed  = sm + 20544;    // 8 (+pad)
    int tid = threadIdx.x, tx = tid & 15, ty = tid >> 4;
    int bidx = blockIdx.x, blk = bidx & 31, bh = bidx >> 5;
    int b = bh / Hq, h = bh % Hq;
    int t0 = blk * 64;

    for (int i = tid; i < 16384; i += 256) sP[i] = g_projT[i];
    const float* kb = key + ((size_t)(b*Tq + t0)*Hq + h)*Eq;
    for (int i = tid; i < 4096; i += 256) {
        int j = i >> 6, e = i & 63;
        sA[e*64 + j] = kb[(size_t)j*ROWSTRIDE + e];
    }
    __syncthreads();
    float* ktg = g_kT + (size_t)bidx * 4096;
    for (int i = tid; i < 4096; i += 256) ktg[i] = sA[i];
    if (tid < 64) {
        float s = 0.f;
#pragma unroll
        for (int e = 0; e < 64; ++e) { float v = sA[e*64 + tid]; s += v*v; }
        sDiag[tid] = 0.0625f * s;   // 0.5 * temp * sum(k^2)
    }
    __syncthreads();

    float dg0 = sDiag[ty*4+0], dg1 = sDiag[ty*4+1], dg2 = sDiag[ty*4+2], dg3 = sDiag[ty*4+3];
    float lmax = NEG_INF;
    float* og = g_ksh + (size_t)bidx * 16384;
#pragma unroll
    for (int cg = 0; cg < 4; ++cg) {
        float C[4][4] = {};
        gemm_acc(C, sA, 64, sP + cg*64, 256, 64, tx, ty);  // C[j][m_local]
#pragma unroll
        for (int c = 0; c < 4; ++c) {
            float4 o;
            o.x = C[0][c] - dg0; o.y = C[1][c] - dg1; o.z = C[2][c] - dg2; o.w = C[3][c] - dg3;
            lmax = fmaxf(lmax, fmaxf(fmaxf(o.x, o.y), fmaxf(o.z, o.w)));
            *(float4*)(og + (size_t)(cg*64 + tx*4 + c)*64 + ty*4) = o;   // [m][j]
        }
    }
#pragma unroll
    for (int off = 16; off; off >>= 1) lmax = fmaxf(lmax, __shfl_xor_sync(0xffffffffu, lmax, off));
    if ((tid & 31) == 0) sRed[tid >> 5] = lmax;
    __syncthreads();
    if (tid == 0) {
        float m = sRed[0];
#pragma unroll
        for (int i = 1; i < 8; ++i) m = fmaxf(m, sRed[i]);
        atomicMaxFloat(&g_sk[bh], m);
    }
}

// ---------------- kernel 2: k_prime (in place, tf32-rounded) + partial kpsum / kv ----------------
__global__ __launch_bounds__(256,1) void k2_kernel(const float* __restrict__ value) {
    __shared__ __align__(16) float sV[4096];   // [j][d]
    int tid = threadIdx.x;
    int bh = blockIdx.x >> 5, sblk = blockIdx.x & 31;
    int b = bh / Hq, h = bh % Hq;
    float sk = g_sk[bh];
    float acc[64];
#pragma unroll
    for (int d = 0; d < 64; ++d) acc[d] = 0.f;
    float ksum = 0.f;

    const float* vb = value + ((size_t)(b*Tq + sblk*64)*Hq + h)*Eq;
    for (int i = tid; i < 4096; i += 256)
        sV[i] = vb[(size_t)(i>>6)*ROWSTRIDE + (i&63)];
    __syncthreads();
    float* kbuf = g_ksh + ((size_t)((bh*32 + sblk)*256 + tid))*64;
    for (int j = 0; j < 64; j += 4) {
        float4 kv4 = *(float4*)(kbuf + j);
        float p0 = tf32_rna(__expf(kv4.x - sk));
        float p1 = tf32_rna(__expf(kv4.y - sk));
        float p2 = tf32_rna(__expf(kv4.z - sk));
        float p3 = tf32_rna(__expf(kv4.w - sk));
        *(float4*)(kbuf + j) = make_float4(p0, p1, p2, p3);
        ksum += p0 + p1 + p2 + p3;
        float pj[4] = {p0, p1, p2, p3};
#pragma unroll
        for (int jj = 0; jj < 4; ++jj) {
            const float4* vr = (const float4*)(sV + (j+jj)*64);
            float p = pj[jj];
#pragma unroll
            for (int d4 = 0; d4 < 16; ++d4) {
                float4 vv = vr[d4];
                acc[d4*4+0] += p*vv.x;
                acc[d4*4+1] += p*vv.y;
                acc[d4*4+2] += p*vv.z;
                acc[d4*4+3] += p*vv.w;
            }
        }
    }
    float* kvout = g_kvpart + ((size_t)(bh*32 + sblk)*256 + tid)*64;
#pragma unroll
    for (int d4 = 0; d4 < 16; ++d4)
        ((float4*)kvout)[d4] = make_float4(acc[d4*4], acc[d4*4+1], acc[d4*4+2], acc[d4*4+3]);
    g_kpspart[(bh*32 + sblk)*256 + tid] = ksum;
}

// ---------------- kernel 2b: reduce partials ----------------
__global__ void reduce_kernel() {
    int idx = blockIdx.x*256 + threadIdx.x;
    if (idx < BH*Mq*Eq) {
        int bh = idx >> 14;
        int rem = idx & 16383;
        float s = 0.f;
#pragma unroll
        for (int p = 0; p < 32; ++p) s += g_kvpart[(size_t)(bh*32 + p)*16384 + rem];
        g_kv[idx] = s;
    }
    if (idx < BH*Mq) {
        int bh = idx >> 8; int m = idx & 255;
        float s = 0.f;
#pragma unroll
        for (int p = 0; p < 32; ++p) s += g_kpspart[(bh*32 + p)*256 + m];
        g_kps[idx] = s;
    }
}

// ---------------- kernel 3: q side ----------------
__global__ __launch_bounds__(256,1) void qside_kernel(const float* __restrict__ query) {
    extern __shared__ float sm[];
    float* sP    = sm;            // 16384 : projT [e][m]
    float* sA    = sm + 16384;    // 4096  : q tile transposed [e][i]
    float* sDiag = sm + 20480;    // 64
    int tid = threadIdx.x, tx = tid & 15, ty = tid >> 4;
    int bidx = blockIdx.x, blk = bidx & 31, bh = bidx >> 5;
    int b = bh / Hq, h = bh % Hq;
    int t0 = blk * 64;

    for (int i = tid; i < 16384; i += 256) sP[i] = g_projT[i];
    const float* qb = query + ((size_t)(b*Tq + t0)*Hq + h)*Eq;
    for (int i = tid; i < 4096; i += 256) {
        int j = i >> 6, e = i & 63;
        sA[e*64 + j] = qb[(size_t)j*ROWSTRIDE + e];
    }
    __syncthreads();
    float* qtg = g_qT + (size_t)bidx * 4096;
    for (int i = tid; i < 4096; i += 256) qtg[i] = sA[i] * TEMP;
    if (tid < 64) {
        float s = 0.f;
#pragma unroll
        for (int e = 0; e < 64; ++e) { float v = sA[e*64 + tid]; s += v*v; }
        sDiag[tid] = 0.0625f * s;   // q_diag
    }
    __syncthreads();

    float C4[4][4][4] = {};
#pragma unroll
    for (int cg = 0; cg < 4; ++cg)
        gemm_acc(C4[cg], sA, 64, sP + cg*64, 256, 64, tx, ty);  // C[i][m_local]

    float rm[4];
#pragma unroll
    for (int r = 0; r < 4; ++r) {
        float mx = NEG_INF;
#pragma unroll
        for (int cg = 0; cg < 4; ++cg)
#pragma unroll
            for (int c = 0; c < 4; ++c) mx = fmaxf(mx, C4[cg][r][c]);
        rm[r] = grpMax16(mx);
    }
    float* qg = g_qpT + (size_t)bidx * 16384;
#pragma unroll
    for (int cg = 0; cg < 4; ++cg)
#pragma unroll
        for (int c = 0; c < 4; ++c) {
            float4 o;
            o.x = tf32_rna(__expf(C4[cg][0][c] - rm[0]));
            o.y = tf32_rna(__expf(C4[cg][1][c] - rm[1]));
            o.z = tf32_rna(__expf(C4[cg][2][c] - rm[2]));
            o.w = tf32_rna(__expf(C4[cg][3][c] - rm[3]));
            *(float4*)(qg + (size_t)(cg*64 + tx*4 + c)*64 + ty*4) = o;  // [m][i]
        }
    if (tx == 0) {
#pragma unroll
        for (int r = 0; r < 4; ++r) {
            int i = ty*4 + r;
            g_qls[bh*Tq + t0 + i] = rm[r] - sDiag[i] - HALF_LOG_M;
        }
    }
}

// ---------------- kernel 4: main fused (tensor-core tf32 MMA) ----------------
__global__ __launch_bounds__(256,1) void main_kernel(const float* __restrict__ value,
                                                     float* __restrict__ out) {
    extern __shared__ float smm[];
    float* sQTb = smm;            // 4608  q*temp hi  [e][i] stride 72
    float* sQTs = smm + 4608;     // 4608  q*temp lo
    float* sKTb = smm + 9216;     // 4608  k hi            | alias sD [j][i]
    float* sKTs = smm + 13824;    // 4608  k lo            | alias sV [j][d]
    float* sQP  = smm + 18432;    // 18432 q' [m][i]
    float* sKP  = smm + 36864;    // 18432 k' [m][j]       | alias sKV [m][d]
    float* sKps = smm + 55296;    // 256
    float* sQls = smm + 55552;    // 64
    float* sM   = smm + 55616;    // 128  [jh][row]
    float* sSe  = smm + 55744;    // 128
    float* sDp  = smm + 55872;    // 128
    float* sQpk = smm + 56000;    // 256
    float* sLn  = smm + 56256;    // 64
    float* sPs  = smm + 56320;    // 64
    float* sD = sKTb;
    float* sV = sKTs;
    float* sKV = sKP;

    int tid = threadIdx.x;
    int lane = tid & 31, wid = tid >> 5;
    int g = lane >> 2, t = lane & 3;
    int iw = wid & 3, jh = wid >> 2;
    int i0 = iw * 16;
    int bidx = blockIdx.x, blk = bidx & 31, bh = bidx >> 5;
    int b = bh / Hq, h = bh % Hq;
    int t0 = blk * 64;
    float sk = g_sk[bh];
    int r0 = i0 + g, r1 = i0 + g + 8;

    // ---- phase 0: persistent operand loads ----
    {
        const float* qt = g_qT + (size_t)bidx*4096;
        for (int i = tid; i < 4096; i += 256) {
            int e = i >> 6, c = i & 63;
            float x = qt[i];
            float hi = tf32_rna(x);
            sQTb[e*SP + c] = hi;
            sQTs[e*SP + c] = x - hi;
        }
        const float4* qp = (const float4*)(g_qpT + (size_t)bidx*16384);
        for (int i = tid; i < 4096; i += 256) {
            float4 v4 = qp[i];
            int m = i >> 4, c4 = (i & 15) * 4;
            *(float4*)(sQP + m*SP + c4) = v4;
        }
        sKps[tid] = g_kps[bh*Mq + tid];
        if (tid < 64) sQls[tid] = g_qls[bh*Tq + t0 + tid];
    }

    bool val[3];
    float Cqk[3][4][4], Cdp[3][4][4];
#pragma unroll
    for (int nw = 0; nw < 3; ++nw)
#pragma unroll
        for (int jt = 0; jt < 4; ++jt)
#pragma unroll
            for (int c = 0; c < 4; ++c) { Cqk[nw][jt][c] = 0.f; Cdp[nw][jt][c] = 0.f; }

    // ---- phase 1: QK (split tf32) + dots_prime GEMMs ----
#pragma unroll 1
    for (int nw = 0; nw < 3; ++nw) {
        int nb = blk - 1 + nw;
        val[nw] = (nb >= 0) && (nb < NB);
        if (!val[nw]) continue;
        __syncthreads();
        size_t kb = (size_t)(bh*32 + nb);
        const float* kt = g_kT + kb*4096;
        for (int i = tid; i < 4096; i += 256) {
            int e = i >> 6, c = i & 63;
            float x = kt[i];
            float hi = tf32_rna(x);
            sKTb[e*SP + c] = hi;
            sKTs[e*SP + c] = x - hi;
        }
        const float4* kp = (const float4*)(g_ksh + kb*16384);
        for (int i = tid; i < 4096; i += 256) {
            float4 v4 = kp[i];
            int m = i >> 4, c4 = (i & 15)*4;
            *(float4*)(sKP + m*SP + c4) = v4;
        }
        __syncthreads();

        // Cqk: K=64, split hi/lo (3 MMAs)
#pragma unroll
        for (int kc = 0; kc < 8; ++kc) {
            int k0 = kc*8;
            float ab0 = sQTb[(k0+t)*SP + i0+g],   ab1 = sQTb[(k0+t)*SP + i0+g+8];
            float ab2 = sQTb[(k0+t+4)*SP + i0+g], ab3 = sQTb[(k0+t+4)*SP + i0+g+8];
            float as0 = sQTs[(k0+t)*SP + i0+g],   as1 = sQTs[(k0+t)*SP + i0+g+8];
            float as2 = sQTs[(k0+t+4)*SP + i0+g], as3 = sQTs[(k0+t+4)*SP + i0+g+8];
#pragma unroll
            for (int jt = 0; jt < 4; ++jt) {
                int j = jh*32 + jt*8 + g;
                float bb0 = sKTb[(k0+t)*SP + j], bb1 = sKTb[(k0+t+4)*SP + j];
                float bs0 = sKTs[(k0+t)*SP + j], bs1 = sKTs[(k0+t+4)*SP + j];
                mma_tf32(Cqk[nw][jt], ab0,ab1,ab2,ab3, bb0,bb1);
                mma_tf32(Cqk[nw][jt], ab0,ab1,ab2,ab3, bs0,bs1);
                mma_tf32(Cqk[nw][jt], as0,as1,as2,as3, bb0,bb1);
            }
        }
        // Cdp: K=256
#pragma unroll 4
        for (int kc = 0; kc < 32; ++kc) {
            int k0 = kc*8;
            float a0 = sQP[(k0+t)*SP + i0+g],   a1 = sQP[(k0+t)*SP + i0+g+8];
            float a2 = sQP[(k0+t+4)*SP + i0+g], a3 = sQP[(k0+t+4)*SP + i0+g+8];
#pragma unroll
            for (int jt = 0; jt < 4; ++jt) {
                int j = jh*32 + jt*8 + g;
                float b0 = sKP[(k0+t)*SP + j], b1 = sKP[(k0+t+4)*SP + j];
                mma_tf32(Cdp[nw][jt], a0,a1,a2,a3, b0,b1);
            }
        }
    }

    // ---- phase 2: per-row stats ----
    {
        float mx0 = NEG_INF, mx1 = NEG_INF, dp0 = 0.f, dp1 = 0.f;
#pragma unroll
        for (int nw = 0; nw < 3; ++nw) {
            if (!val[nw]) continue;
#pragma unroll
            for (int jt = 0; jt < 4; ++jt) {
                mx0 = fmaxf(mx0, fmaxf(Cqk[nw][jt][0], Cqk[nw][jt][1]));
                mx1 = fmaxf(mx1, fmaxf(Cqk[nw][jt][2], Cqk[nw][jt][3]));
                dp0 += Cdp[nw][jt][0] + Cdp[nw][jt][1];
                dp1 += Cdp[nw][jt][2] + Cdp[nw][jt][3];
            }
        }
        mx0 = fmaxf(mx0, __shfl_xor_sync(0xffffffffu, mx0, 1));
        mx0 = fmaxf(mx0, __shfl_xor_sync(0xffffffffu, mx0, 2));
        mx1 = fmaxf(mx1, __shfl_xor_sync(0xffffffffu, mx1, 1));
        mx1 = fmaxf(mx1, __shfl_xor_sync(0xffffffffu, mx1, 2));
        dp0 += __shfl_xor_sync(0xffffffffu, dp0, 1);
        dp0 += __shfl_xor_sync(0xffffffffu, dp0, 2);
        dp1 += __shfl_xor_sync(0xffffffffu, dp1, 1);
        dp1 += __shfl_xor_sync(0xffffffffu, dp1, 2);
        if (t == 0) {
            sM[jh*64 + r0] = mx0; sM[jh*64 + r1] = mx1;
            sDp[jh*64 + r0] = dp0; sDp[jh*64 + r1] = dp1;
        }
    }
    __syncthreads();
    {
        float M0 = fmaxf(sM[r0], sM[64 + r0]);
        float M1 = fmaxf(sM[r1], sM[64 + r1]);
        float se0 = 0.f, se1 = 0.f;
#pragma unroll
        for (int nw = 0; nw < 3; ++nw) {
            if (!val[nw]) continue;
#pragma unroll
            for (int jt = 0; jt < 4; ++jt) {
                se0 += __expf(Cqk[nw][jt][0] - M0) + __expf(Cqk[nw][jt][1] - M0);
                se1 += __expf(Cqk[nw][jt][2] - M1) + __expf(Cqk[nw][jt][3] - M1);
            }
        }
        se0 += __shfl_xor_sync(0xffffffffu, se0, 1);
        se0 += __shfl_xor_sync(0xffffffffu, se0, 2);
        se1 += __shfl_xor_sync(0xffffffffu, se1, 1);
        se1 += __shfl_xor_sync(0xffffffffu, se1, 2);
        if (t == 0) { sSe[jh*64 + r0] = se0; sSe[jh*64 + r1] = se1; }
    }
    __syncthreads();
    // qp_kp_1 partials
    {
        int ii = tid & 63, part = tid >> 6;
        float s = 0.f;
#pragma unroll 16
        for (int mm = 0; mm < 64; ++mm) {
            int m = part*64 + mm;
            s += sQP[m*SP + ii] * sKps[m];
        }
        sQpk[part*64 + ii] = s;
    }
    __syncthreads();
    if (tid < 64) {
        float qpk1 = sQpk[tid] + sQpk[64+tid] + sQpk[128+tid] + sQpk[192+tid];
        float Mv = fmaxf(sM[tid], sM[64+tid]);
        float se = sSe[tid] + sSe[64+tid];
        float lse = Mv + __logf(se);
        float dp = sDp[tid] + sDp[64+tid];
        float pls = sQls[tid] + sk - HALF_LOG_M;
        float lr  = __logf(fmaxf(qpk1 - dp, 1e-24f)) + pls;
        float mxv = fmaxf(lse, lr);
        float ln  = mxv + log1pf(__expf(-fabsf(lse - lr)));
        sLn[tid] = ln;
        sPs[tid] = __expf(pls - ln);
    }
    __syncthreads();
    float ln0 = sLn[r0], ln1 = sLn[r1], ps0 = sPs[r0], ps1 = sPs[r1];

    // ---- phase 3: dots -> out_bs (MMA over j) ----
    float Cout[4][4];
#pragma unroll
    for (int dt = 0; dt < 4; ++dt)
#pragma unroll
        for (int c = 0; c < 4; ++c) Cout[dt][c] = 0.f;

#pragma unroll 1
    for (int nw = 0; nw < 3; ++nw) {
        if (!val[nw]) continue;
        int nb = blk - 1 + nw;
        __syncthreads();
#pragma unroll
        for (int jt = 0; jt < 4; ++jt) {
            int j = jh*32 + jt*8 + 2*t;
            sD[(size_t)j*SP + r0]     = tf32_rna(__expf(Cqk[nw][jt][0]-ln0) - Cdp[nw][jt][0]*ps0);
            sD[(size_t)(j+1)*SP + r0] = tf32_rna(__expf(Cqk[nw][jt][1]-ln0) - Cdp[nw][jt][1]*ps0);
            sD[(size_t)j*SP + r1]     = tf32_rna(__expf(Cqk[nw][jt][2]-ln1) - Cdp[nw][jt][2]*ps1);
            sD[(size_t)(j+1)*SP + r1] = tf32_rna(__expf(Cqk[nw][jt][3]-ln1) - Cdp[nw][jt][3]*ps1);
        }
        const float* vb = value + ((size_t)(b*Tq + nb*64)*Hq + h)*Eq;
        for (int i = tid; i < 1024; i += 256) {
            int j = i >> 4, d4 = (i & 15)*4;
            float4 v4 = *(const float4*)(vb + (size_t)j*ROWSTRIDE + d4);
            v4.x = tf32_rna(v4.x); v4.y = tf32_rna(v4.y);
            v4.z = tf32_rna(v4.z); v4.w = tf32_rna(v4.w);
            *(float4*)(sV + j*SP + d4) = v4;
        }
        __syncthreads();
#pragma unroll
        for (int kc = 0; kc < 8; ++kc) {
            int k0 = kc*8;
            float a0 = sD[(k0+t)*SP + i0+g],   a1 = sD[(k0+t)*SP + i0+g+8];
            float a2 = sD[(k0+t+4)*SP + i0+g], a3 = sD[(k0+t+4)*SP + i0+g+8];
#pragma unroll
            for (int dt = 0; dt < 4; ++dt) {
                int d = jh*32 + dt*8 + g;
                float b0 = sV[(k0+t)*SP + d], b1 = sV[(k0+t+4)*SP + d];
                mma_tf32(Cout[dt], a0,a1,a2,a3, b0,b1);
            }
        }
    }

    // ---- phase 4: qp_kp_v (MMA over m) ----
    __syncthreads();
    {
        const float4* kvsrc = (const float4*)(g_kv + (size_t)bh*16384);
        for (int i = tid; i < 4096; i += 256) {
            float4 v4 = kvsrc[i];
            v4.x = tf32_rna(v4.x); v4.y = tf32_rna(v4.y);
            v4.z = tf32_rna(v4.z); v4.w = tf32_rna(v4.w);
            int m = i >> 4, d4 = (i & 15)*4;
            *(float4*)(sKV + m*SP + d4) = v4;
        }
    }
    __syncthreads();
    float C2[4][4];
#pragma unroll
    for (int dt = 0; dt < 4; ++dt)
#pragma unroll
        for (int c = 0; c < 4; ++c) C2[dt][c] = 0.f;
#pragma unroll 4
    for (int kc = 0; kc < 32; ++kc) {
        int k0 = kc*8;
        float a0 = sQP[(k0+t)*SP + i0+g],   a1 = sQP[(k0+t)*SP + i0+g+8];
        float a2 = sQP[(k0+t+4)*SP + i0+g], a3 = sQP[(k0+t+4)*SP + i0+g+8];
#pragma unroll
        for (int dt = 0; dt < 4; ++dt) {
            int d = jh*32 + dt*8 + g;
            float b0 = sKV[(k0+t)*SP + d], b1 = sKV[(k0+t+4)*SP + d];
            mma_tf32(C2[dt], a0,a1,a2,a3, b0,b1);
        }
    }

    // ---- epilogue ----
    float* ob = out + ((size_t)(b*Tq + t0)*Hq + h)*Eq;
#pragma unroll
    for (int dt = 0; dt < 4; ++dt) {
        int d = jh*32 + dt*8 + 2*t;
        float2 o0, o1;
        o0.x = Cout[dt][0] + C2[dt][0]*ps0;
        o0.y = Cout[dt][1] + C2[dt][1]*ps0;
        o1.x = Cout[dt][2] + C2[dt][2]*ps1;
        o1.y = Cout[dt][3] + C2[dt][3]*ps1;
        *(float2*)(ob + (size_t)r0*ROWSTRIDE + d) = o0;
        *(float2*)(ob + (size_t)r1*ROWSTRIDE + d) = o1;
    }
}

// ---------------- launch ----------------
extern "C" void kernel_launch(void* const* d_in, const int* in_sizes, int n_in,
                              void* d_out, int out_size) {
    const float* query = (const float*)d_in[0];
    const float* key   = (const float*)d_in[1];
    const float* value = (const float*)d_in[2];
    const float* proj  = (const float*)d_in[3];
    float* out = (float*)d_out;

    const int SM_SIDE = (16384 + 4096 + 64 + 32) * 4;   // 82304
    const int SM_MAIN = 56384 * 4;                       // 225536

    cudaFuncSetAttribute(kside_kernel, cudaFuncAttributeMaxDynamicSharedMemorySize, SM_SIDE);
    cudaFuncSetAttribute(qside_kernel, cudaFuncAttributeMaxDynamicSharedMemorySize, SM_SIDE);
    cudaFuncSetAttribute(main_kernel,  cudaFuncAttributeMaxDynamicSharedMemorySize, SM_MAIN);

    init_kernel<<<64, 256>>>(proj);
    kside_kernel<<<BH*NB, 256, SM_SIDE>>>(key);
    k2_kernel<<<BH*NB, 256>>>(value);
    reduce_kernel<<<(BH*Mq*Eq + 255)/256, 256>>>();
    qside_kernel<<<BH*NB, 256, SM_SIDE>>>(query);
    main_kernel<<<BH*NB, 256, SM_MAIN>>>(value, out);
}

// round 4
// speedup vs baseline: 1.3489x; 1.2444x over previous
#include <cuda_runtime.h>
#include <math.h>
#include <stdint.h>

#define Bq 2
#define Tq 2048
#define Hq 12
#define Eq 64
#define Mq 256
#define NB 32            // T / 64
#define BH 24            // B*H
#define ROWSTRIDE (Hq*Eq)  // 768 floats between consecutive t
#define SP 72            // padded smem stride (conflict-free MMA fragment loads)

#define DN 0.35355339059327379f         // sqrt(1/sqrt(E))
#define TEMP 0.125f                     // 1/sqrt(E)
#define HALF_LOG_M 2.7725887222397811f  // 0.5*log(256)
#define NEG_INF __int_as_float(0xff800000)

// ---------------- device scratch ----------------
__device__ float g_projT[Eq*Mq];                 // [e][m], dn folded
__device__ float g_qT  [BH*Tq*Eq];               // per block: [e][i], temp folded
__device__ float g_kT  [BH*Tq*Eq];               // per block: [e][j], raw k
__device__ float g_kp  [BH*NB*Mq*64];            // per block: [m][j]; k_prime (s_k=0, tf32)
__device__ float g_qpT [BH*NB*Mq*64];            // per block: [m][i]; q_prime (tf32)
__device__ float g_qls [BH*Tq];                  // q_log_scale
__device__ float g_kv  [BH*Mq*Eq];               // [m][d]
__device__ float g_kps [BH*Mq];
__device__ float g_kvpart [BH*32*Mq*Eq];
__device__ float g_kpspart[BH*32*Mq];

// ---------------- helpers ----------------
__device__ __forceinline__ float tf32_rna(float x) {
    uint32_t r;
    asm("cvt.rna.tf32.f32 %0, %1;" : "=r"(r) : "f"(x));
    return __uint_as_float(r);
}

// D(16x8) += A(16x8) * B(8x8); tf32 inputs, f32 accum.
__device__ __forceinline__ void mma_tf32(float c[4],
        float a0, float a1, float a2, float a3, float b0, float b1)
{
    asm volatile(
        "mma.sync.aligned.m16n8k8.row.col.f32.tf32.tf32.f32 "
        "{%0,%1,%2,%3}, {%4,%5,%6,%7}, {%8,%9}, {%0,%1,%2,%3};\n"
        : "+f"(c[0]), "+f"(c[1]), "+f"(c[2]), "+f"(c[3])
        : "r"(__float_as_uint(a0)), "r"(__float_as_uint(a1)),
          "r"(__float_as_uint(a2)), "r"(__float_as_uint(a3)),
          "r"(__float_as_uint(b0)), "r"(__float_as_uint(b1)));
}

__device__ __forceinline__ float grpMax16(float v) {
    v = fmaxf(v, __shfl_xor_sync(0xffffffffu, v, 1));
    v = fmaxf(v, __shfl_xor_sync(0xffffffffu, v, 2));
    v = fmaxf(v, __shfl_xor_sync(0xffffffffu, v, 4));
    v = fmaxf(v, __shfl_xor_sync(0xffffffffu, v, 8));
    return v;
}

// scalar register-tiled GEMM (used by side kernels)
__device__ __forceinline__ void gemm_acc(float C[4][4],
        const float* __restrict__ A, int lda,
        const float* __restrict__ Bm, int ldb, int K, int tx, int ty)
{
    const float* ap = A + ty*4;
    const float* bp = Bm + tx*4;
#pragma unroll 8
    for (int k = 0; k < K; ++k) {
        float4 a = *(const float4*)(ap + (size_t)k*lda);
        float4 b = *(const float4*)(bp + (size_t)k*ldb);
        C[0][0] += a.x*b.x; C[0][1] += a.x*b.y; C[0][2] += a.x*b.z; C[0][3] += a.x*b.w;
        C[1][0] += a.y*b.x; C[1][1] += a.y*b.y; C[1][2] += a.y*b.z; C[1][3] += a.y*b.w;
        C[2][0] += a.z*b.x; C[2][1] += a.z*b.y; C[2][2] += a.z*b.z; C[2][3] += a.z*b.w;
        C[3][0] += a.w*b.x; C[3][1] += a.w*b.y; C[3][2] += a.w*b.z; C[3][3] += a.w*b.w;
    }
}

// ---------------- kernel 0: init ----------------
__global__ void init_kernel(const float* __restrict__ proj) {
    int idx = blockIdx.x*256 + threadIdx.x;
    if (idx < Eq*Mq) {
        int e = idx >> 8;
        int m = idx & 255;
        g_projT[idx] = proj[m*Eq + e] * DN;
    }
}

// ---------------- kernel 1: k side — k' = exp(k_dash - k_diag) directly (s_k = 0) ----------------
__global__ __launch_bounds__(256,1) void kside_kernel(const float* __restrict__ key) {
    extern __shared__ float sm[];
    float* sP    = sm;            // 16384 : projT [e][m]
    float* sA    = sm + 16384;    // 4096  : k tile transposed [e][j]
    float* sDiag = sm + 20480;    // 64
    int tid = threadIdx.x, tx = tid & 15, ty = tid >> 4;
    int bidx = blockIdx.x, blk = bidx & 31, bh = bidx >> 5;
    int b = bh / Hq, h = bh % Hq;
    int t0 = blk * 64;

    for (int i = tid; i < 16384; i += 256) sP[i] = g_projT[i];
    const float* kb = key + ((size_t)(b*Tq + t0)*Hq + h)*Eq;
    for (int i = tid; i < 4096; i += 256) {
        int j = i >> 6, e = i & 63;
        sA[e*64 + j] = kb[(size_t)j*ROWSTRIDE + e];
    }
    __syncthreads();
    float* ktg = g_kT + (size_t)bidx * 4096;
    for (int i = tid; i < 4096; i += 256) ktg[i] = sA[i];
    if (tid < 64) {
        float s = 0.f;
#pragma unroll
        for (int e = 0; e < 64; ++e) { float v = sA[e*64 + tid]; s += v*v; }
        sDiag[tid] = 0.0625f * s;   // 0.5 * temp * sum(k^2)
    }
    __syncthreads();

    float dg0 = sDiag[ty*4+0], dg1 = sDiag[ty*4+1], dg2 = sDiag[ty*4+2], dg3 = sDiag[ty*4+3];
    float* og = g_kp + (size_t)bidx * 16384;
#pragma unroll
    for (int cg = 0; cg < 4; ++cg) {
        float C[4][4] = {};
        gemm_acc(C, sA, 64, sP + cg*64, 256, 64, tx, ty);  // C[j][m_local]
#pragma unroll
        for (int c = 0; c < 4; ++c) {
            float4 o;
            o.x = tf32_rna(__expf(C[0][c] - dg0));
            o.y = tf32_rna(__expf(C[1][c] - dg1));
            o.z = tf32_rna(__expf(C[2][c] - dg2));
            o.w = tf32_rna(__expf(C[3][c] - dg3));
            *(float4*)(og + (size_t)(cg*64 + tx*4 + c)*64 + ty*4) = o;   // [m][j]
        }
    }
}

// ---------------- kernel 2: partial kpsum / kv (read-only k') ----------------
__global__ __launch_bounds__(256,1) void k2_kernel(const float* __restrict__ value) {
    __shared__ __align__(16) float sV[4096];   // [j][d]
    int tid = threadIdx.x;
    int bh = blockIdx.x >> 5, sblk = blockIdx.x & 31;
    int b = bh / Hq, h = bh % Hq;
    float acc[64];
#pragma unroll
    for (int d = 0; d < 64; ++d) acc[d] = 0.f;
    float ksum = 0.f;

    const float* vb = value + ((size_t)(b*Tq + sblk*64)*Hq + h)*Eq;
    for (int i = tid; i < 4096; i += 256)
        sV[i] = vb[(size_t)(i>>6)*ROWSTRIDE + (i&63)];
    __syncthreads();
    const float* kbuf = g_kp + ((size_t)((bh*32 + sblk)*256 + tid))*64;
    for (int j = 0; j < 64; j += 4) {
        float4 kv4 = *(const float4*)(kbuf + j);
        ksum += kv4.x + kv4.y + kv4.z + kv4.w;
        float pj[4] = {kv4.x, kv4.y, kv4.z, kv4.w};
#pragma unroll
        for (int jj = 0; jj < 4; ++jj) {
            const float4* vr = (const float4*)(sV + (j+jj)*64);
            float p = pj[jj];
#pragma unroll
            for (int d4 = 0; d4 < 16; ++d4) {
                float4 vv = vr[d4];
                acc[d4*4+0] += p*vv.x;
                acc[d4*4+1] += p*vv.y;
                acc[d4*4+2] += p*vv.z;
                acc[d4*4+3] += p*vv.w;
            }
        }
    }
    float* kvout = g_kvpart + ((size_t)(bh*32 + sblk)*256 + tid)*64;
#pragma unroll
    for (int d4 = 0; d4 < 16; ++d4)
        ((float4*)kvout)[d4] = make_float4(acc[d4*4], acc[d4*4+1], acc[d4*4+2], acc[d4*4+3]);
    g_kpspart[(bh*32 + sblk)*256 + tid] = ksum;
}

// ---------------- kernel 2b: reduce partials ----------------
__global__ void reduce_kernel() {
    int idx = blockIdx.x*256 + threadIdx.x;
    if (idx < BH*Mq*Eq) {
        int bh = idx >> 14;
        int rem = idx & 16383;
        float s = 0.f;
#pragma unroll
        for (int p = 0; p < 32; ++p) s += g_kvpart[(size_t)(bh*32 + p)*16384 + rem];
        g_kv[idx] = s;
    }
    if (idx < BH*Mq) {
        int bh = idx >> 8; int m = idx & 255;
        float s = 0.f;
#pragma unroll
        for (int p = 0; p < 32; ++p) s += g_kpspart[(bh*32 + p)*256 + m];
        g_kps[idx] = s;
    }
}

// ---------------- kernel 3: q side ----------------
__global__ __launch_bounds__(256,1) void qside_kernel(const float* __restrict__ query) {
    extern __shared__ float sm[];
    float* sP    = sm;            // 16384 : projT [e][m]
    float* sA    = sm + 16384;    // 4096  : q tile transposed [e][i]
    float* sDiag = sm + 20480;    // 64
    int tid = threadIdx.x, tx = tid & 15, ty = tid >> 4;
    int bidx = blockIdx.x, blk = bidx & 31, bh = bidx >> 5;
    int b = bh / Hq, h = bh % Hq;
    int t0 = blk * 64;

    for (int i = tid; i < 16384; i += 256) sP[i] = g_projT[i];
    const float* qb = query + ((size_t)(b*Tq + t0)*Hq + h)*Eq;
    for (int i = tid; i < 4096; i += 256) {
        int j = i >> 6, e = i & 63;
        sA[e*64 + j] = qb[(size_t)j*ROWSTRIDE + e];
    }
    __syncthreads();
    float* qtg = g_qT + (size_t)bidx * 4096;
    for (int i = tid; i < 4096; i += 256) qtg[i] = sA[i] * TEMP;
    if (tid < 64) {
        float s = 0.f;
#pragma unroll
        for (int e = 0; e < 64; ++e) { float v = sA[e*64 + tid]; s += v*v; }
        sDiag[tid] = 0.0625f * s;   // q_diag
    }
    __syncthreads();

    float C4[4][4][4] = {};
#pragma unroll
    for (int cg = 0; cg < 4; ++cg)
        gemm_acc(C4[cg], sA, 64, sP + cg*64, 256, 64, tx, ty);  // C[i][m_local]

    float rm[4];
#pragma unroll
    for (int r = 0; r < 4; ++r) {
        float mx = NEG_INF;
#pragma unroll
        for (int cg = 0; cg < 4; ++cg)
#pragma unroll
            for (int c = 0; c < 4; ++c) mx = fmaxf(mx, C4[cg][r][c]);
        rm[r] = grpMax16(mx);
    }
    float* qg = g_qpT + (size_t)bidx * 16384;
#pragma unroll
    for (int cg = 0; cg < 4; ++cg)
#pragma unroll
        for (int c = 0; c < 4; ++c) {
            float4 o;
            o.x = tf32_rna(__expf(C4[cg][0][c] - rm[0]));
            o.y = tf32_rna(__expf(C4[cg][1][c] - rm[1]));
            o.z = tf32_rna(__expf(C4[cg][2][c] - rm[2]));
            o.w = tf32_rna(__expf(C4[cg][3][c] - rm[3]));
            *(float4*)(qg + (size_t)(cg*64 + tx*4 + c)*64 + ty*4) = o;  // [m][i]
        }
    if (tx == 0) {
#pragma unroll
        for (int r = 0; r < 4; ++r) {
            int i = ty*4 + r;
            g_qls[bh*Tq + t0 + i] = rm[r] - sDiag[i] - HALF_LOG_M;
        }
    }
}

// ---------------- kernel 4: main fused, streaming, 512 threads ----------------
// smem float offsets
#define O_QTB 0        // 4608  q*temp hi [e][i]
#define O_QTS 4608     // 4608  q*temp lo
#define O_KTB 9216     // 4608  k hi [e][j]       | alias sE  [j][i]
#define O_KTS 13824    // 4608  k lo              | alias sDP [j][i]
#define O_QP  18432    // 18432 q' [m][i]
#define O_KP  36864    // 18432 k' [m][j]         | alias sV [j][d] (first 4608) / sKV [m][d]
#define O_KPS 55296    // 256
#define O_QLS 55552    // 64
#define O_SSE 55616    // 256  [jh][row]
#define O_SDP 55872    // 256
#define O_QPK 56128    // 512
#define O_LN  56640    // 64
#define O_PS  56704    // 64
#define SM_MAIN_FLOATS 56768

__global__ __launch_bounds__(512,1) void main_kernel(const float* __restrict__ value,
                                                     float* __restrict__ out) {
    extern __shared__ float smm[];
    float* sQTb = smm + O_QTB;
    float* sQTs = smm + O_QTS;
    float* sKTb = smm + O_KTB;
    float* sKTs = smm + O_KTS;
    float* sQP  = smm + O_QP;
    float* sKP  = smm + O_KP;
    float* sKps = smm + O_KPS;
    float* sQls = smm + O_QLS;
    float* sSe  = smm + O_SSE;
    float* sDp  = smm + O_SDP;
    float* sQpk = smm + O_QPK;
    float* sLn  = smm + O_LN;
    float* sPs  = smm + O_PS;
    float* sE   = sKTb;   // [j][i] exp(QK)
    float* sDPm = sKTs;   // [j][i] dots_prime
    float* sV   = sKP;    // [j][d]
    float* sKV  = sKP;    // [m][d]

    int tid = threadIdx.x;
    int lane = tid & 31, wid = tid >> 5;
    int g = lane >> 2, t = lane & 3;
    int iw = wid & 3, jh = wid >> 2;        // 4 x 4 warp grid
    int i0 = iw * 16;
    int bidx = blockIdx.x, blk = bidx & 31, bh = bidx >> 5;
    int b = bh / Hq, h = bh % Hq;
    int t0 = blk * 64;
    int r0 = i0 + g, r1 = i0 + g + 8;

    // ---- phase 0: persistent operand loads ----
    {
        const float* qt = g_qT + (size_t)bidx*4096;
        for (int i = tid; i < 4096; i += 512) {
            int e = i >> 6, c = i & 63;
            float x = qt[i];
            float hi = tf32_rna(x);
            sQTb[e*SP + c] = hi;
            sQTs[e*SP + c] = x - hi;
        }
        const float4* qp = (const float4*)(g_qpT + (size_t)bidx*16384);
        for (int i = tid; i < 4096; i += 512) {
            float4 v4 = qp[i];
            int m = i >> 4, c4 = (i & 15) * 4;
            *(float4*)(sQP + m*SP + c4) = v4;
        }
        if (tid < 256) sKps[tid] = g_kps[bh*Mq + tid];
        if (tid < 64)  sQls[tid] = g_qls[bh*Tq + t0 + tid];
    }

    float accE[2][4], accD[2][4];
#pragma unroll
    for (int dt = 0; dt < 2; ++dt)
#pragma unroll
        for (int c = 0; c < 4; ++c) { accE[dt][c] = 0.f; accD[dt][c] = 0.f; }
    float seR0 = 0.f, seR1 = 0.f, dpR0 = 0.f, dpR1 = 0.f;

    // ---- streaming neighbor loop ----
#pragma unroll 1
    for (int nw = 0; nw < 3; ++nw) {
        int nb = blk - 1 + nw;
        if (nb < 0 || nb >= NB) continue;
        __syncthreads();   // previous iteration's MMA reads done before overwrite
        size_t kb = (size_t)(bh*32 + nb);
        const float* kt = g_kT + kb*4096;
        for (int i = tid; i < 4096; i += 512) {
            int e = i >> 6, c = i & 63;
            float x = kt[i];
            float hi = tf32_rna(x);
            sKTb[e*SP + c] = hi;
            sKTs[e*SP + c] = x - hi;
        }
        const float4* kp = (const float4*)(g_kp + kb*16384);
        for (int i = tid; i < 4096; i += 512) {
            float4 v4 = kp[i];
            int m = i >> 4, c4 = (i & 15)*4;
            *(float4*)(sKP + m*SP + c4) = v4;
        }
        __syncthreads();

        float Cqk[2][4], Cdp[2][4];
#pragma unroll
        for (int jt = 0; jt < 2; ++jt)
#pragma unroll
            for (int c = 0; c < 4; ++c) { Cqk[jt][c] = 0.f; Cdp[jt][c] = 0.f; }

        // QK: K=64, split hi/lo (3 MMAs)
#pragma unroll
        for (int kc = 0; kc < 8; ++kc) {
            int k0 = kc*8;
            float ab0 = sQTb[(k0+t)*SP + i0+g],   ab1 = sQTb[(k0+t)*SP + i0+g+8];
            float ab2 = sQTb[(k0+t+4)*SP + i0+g], ab3 = sQTb[(k0+t+4)*SP + i0+g+8];
            float as0 = sQTs[(k0+t)*SP + i0+g],   as1 = sQTs[(k0+t)*SP + i0+g+8];
            float as2 = sQTs[(k0+t+4)*SP + i0+g], as3 = sQTs[(k0+t+4)*SP + i0+g+8];
#pragma unroll
            for (int jt = 0; jt < 2; ++jt) {
                int j = jh*16 + jt*8 + g;
                float bb0 = sKTb[(k0+t)*SP + j], bb1 = sKTb[(k0+t+4)*SP + j];
                float bs0 = sKTs[(k0+t)*SP + j], bs1 = sKTs[(k0+t+4)*SP + j];
                mma_tf32(Cqk[jt], ab0,ab1,ab2,ab3, bb0,bb1);
                mma_tf32(Cqk[jt], ab0,ab1,ab2,ab3, bs0,bs1);
                mma_tf32(Cqk[jt], as0,as1,as2,as3, bb0,bb1);
            }
        }
        // dots_prime: K=256
#pragma unroll 4
        for (int kc = 0; kc < 32; ++kc) {
            int k0 = kc*8;
            float a0 = sQP[(k0+t)*SP + i0+g],   a1 = sQP[(k0+t)*SP + i0+g+8];
            float a2 = sQP[(k0+t+4)*SP + i0+g], a3 = sQP[(k0+t+4)*SP + i0+g+8];
#pragma unroll
            for (int jt = 0; jt < 2; ++jt) {
                int j = jh*16 + jt*8 + g;
                float b0 = sKP[(k0+t)*SP + j], b1 = sKP[(k0+t+4)*SP + j];
                mma_tf32(Cdp[jt], a0,a1,a2,a3, b0,b1);
            }
        }
        __syncthreads();   // all warps done reading sKTb/sKTs/sKP

        // exp frags + running row sums; write E and dp tiles [j][i]
#pragma unroll
        for (int jt = 0; jt < 2; ++jt) {
            int j = jh*16 + jt*8 + 2*t;
            float e00 = __expf(Cqk[jt][0]);
            float e01 = __expf(Cqk[jt][1]);
            float e10 = __expf(Cqk[jt][2]);
            float e11 = __expf(Cqk[jt][3]);
            seR0 += e00 + e01;  seR1 += e10 + e11;
            dpR0 += Cdp[jt][0] + Cdp[jt][1];
            dpR1 += Cdp[jt][2] + Cdp[jt][3];
            sE[(size_t)j*SP + r0]     = tf32_rna(e00);
            sE[(size_t)(j+1)*SP + r0] = tf32_rna(e01);
            sE[(size_t)j*SP + r1]     = tf32_rna(e10);
            sE[(size_t)(j+1)*SP + r1] = tf32_rna(e11);
            sDPm[(size_t)j*SP + r0]     = tf32_rna(Cdp[jt][0]);
            sDPm[(size_t)(j+1)*SP + r0] = tf32_rna(Cdp[jt][1]);
            sDPm[(size_t)j*SP + r1]     = tf32_rna(Cdp[jt][2]);
            sDPm[(size_t)(j+1)*SP + r1] = tf32_rna(Cdp[jt][3]);
        }
        // v tile
        const float* vb = value + ((size_t)(b*Tq + nb*64)*Hq + h)*Eq;
        for (int i = tid; i < 1024; i += 512) {
            int j = i >> 4, d4 = (i & 15)*4;
            float4 v4 = *(const float4*)(vb + (size_t)j*ROWSTRIDE + d4);
            v4.x = tf32_rna(v4.x); v4.y = tf32_rna(v4.y);
            v4.z = tf32_rna(v4.z); v4.w = tf32_rna(v4.w);
            *(float4*)(sV + j*SP + d4) = v4;
        }
        __syncthreads();

        // accE += E . V ; accD += dp . V   (K = 64 over j)
#pragma unroll
        for (int kc = 0; kc < 8; ++kc) {
            int k0 = kc*8;
            float aE0 = sE[(k0+t)*SP + i0+g],   aE1 = sE[(k0+t)*SP + i0+g+8];
            float aE2 = sE[(k0+t+4)*SP + i0+g], aE3 = sE[(k0+t+4)*SP + i0+g+8];
            float aD0 = sDPm[(k0+t)*SP + i0+g],   aD1 = sDPm[(k0+t)*SP + i0+g+8];
            float aD2 = sDPm[(k0+t+4)*SP + i0+g], aD3 = sDPm[(k0+t+4)*SP + i0+g+8];
#pragma unroll
            for (int dt = 0; dt < 2; ++dt) {
                int d = jh*16 + dt*8 + g;
                float b0 = sV[(k0+t)*SP + d], b1 = sV[(k0+t+4)*SP + d];
                mma_tf32(accE[dt], aE0,aE1,aE2,aE3, b0,b1);
                mma_tf32(accD[dt], aD0,aD1,aD2,aD3, b0,b1);
            }
        }
    }

    // ---- stats reduce ----
    seR0 += __shfl_xor_sync(0xffffffffu, seR0, 1);
    seR0 += __shfl_xor_sync(0xffffffffu, seR0, 2);
    seR1 += __shfl_xor_sync(0xffffffffu, seR1, 1);
    seR1 += __shfl_xor_sync(0xffffffffu, seR1, 2);
    dpR0 += __shfl_xor_sync(0xffffffffu, dpR0, 1);
    dpR0 += __shfl_xor_sync(0xffffffffu, dpR0, 2);
    dpR1 += __shfl_xor_sync(0xffffffffu, dpR1, 1);
    dpR1 += __shfl_xor_sync(0xffffffffu, dpR1, 2);
    __syncthreads();   // prior MMA reads of sV complete before any reuse; also orders stats writes
    if (t == 0) {
        sSe[jh*64 + r0] = seR0; sSe[jh*64 + r1] = seR1;
        sDp[jh*64 + r0] = dpR0; sDp[jh*64 + r1] = dpR1;
    }
    // qp_kp_1 partials
    {
        int ii = tid & 63, part = tid >> 6;   // 8 parts x 32 m
        float s = 0.f;
#pragma unroll 8
        for (int mm = 0; mm < 32; ++mm) {
            int m = part*32 + mm;
            s += sQP[m*SP + ii] * sKps[m];
        }
        sQpk[part*64 + ii] = s;
    }
    __syncthreads();
    if (tid < 64) {
        float qpk1 = 0.f;
#pragma unroll
        for (int p = 0; p < 8; ++p) qpk1 += sQpk[p*64 + tid];
        float se = sSe[tid] + sSe[64+tid] + sSe[128+tid] + sSe[192+tid];
        float dp = sDp[tid] + sDp[64+tid] + sDp[128+tid] + sDp[192+tid];
        float lse = __logf(se);                      // no max needed: QK small
        float pls = sQls[tid] - HALF_LOG_M;          // k_log_scale = -half_log_m (s_k = 0)
        float lr  = __logf(fmaxf(qpk1 - dp, 1e-24f)) + pls;
        float mxv = fmaxf(lse, lr);
        float ln  = mxv + log1pf(__expf(-fabsf(lse - lr)));
        sLn[tid] = ln;
        sPs[tid] = __expf(pls - ln);
    }
    __syncthreads();
    float iE0 = __expf(-sLn[r0]), iE1 = __expf(-sLn[r1]);
    float ps0 = sPs[r0], ps1 = sPs[r1];

    // ---- C2 = q' . kv ----
    {
        const float4* kvsrc = (const float4*)(g_kv + (size_t)bh*16384);
        for (int i = tid; i < 4096; i += 512) {
            float4 v4 = kvsrc[i];
            v4.x = tf32_rna(v4.x); v4.y = tf32_rna(v4.y);
            v4.z = tf32_rna(v4.z); v4.w = tf32_rna(v4.w);
            int m = i >> 4, d4 = (i & 15)*4;
            *(float4*)(sKV + m*SP + d4) = v4;
        }
    }
    __syncthreads();
    float C2[2][4];
#pragma unroll
    for (int dt = 0; dt < 2; ++dt)
#pragma unroll
        for (int c = 0; c < 4; ++c) C2[dt][c] = 0.f;
#pragma unroll 4
    for (int kc = 0; kc < 32; ++kc) {
        int k0 = kc*8;
        float a0 = sQP[(k0+t)*SP + i0+g],   a1 = sQP[(k0+t)*SP + i0+g+8];
        float a2 = sQP[(k0+t+4)*SP + i0+g], a3 = sQP[(k0+t+4)*SP + i0+g+8];
#pragma unroll
        for (int dt = 0; dt < 2; ++dt) {
            int d = jh*16 + dt*8 + g;
            float b0 = sKV[(k0+t)*SP + d], b1 = sKV[(k0+t+4)*SP + d];
            mma_tf32(C2[dt], a0,a1,a2,a3, b0,b1);
        }
    }

    // ---- epilogue: out = accE*exp(-ln) + (C2 - accD)*ps ----
    float* ob = out + ((size_t)(b*Tq + t0)*Hq + h)*Eq;
#pragma unroll
    for (int dt = 0; dt < 2; ++dt) {
        int d = jh*16 + dt*8 + 2*t;
        float2 o0, o1;
        o0.x = accE[dt][0]*iE0 + (C2[dt][0] - accD[dt][0])*ps0;
        o0.y = accE[dt][1]*iE0 + (C2[dt][1] - accD[dt][1])*ps0;
        o1.x = accE[dt][2]*iE1 + (C2[dt][2] - accD[dt][2])*ps1;
        o1.y = accE[dt][3]*iE1 + (C2[dt][3] - accD[dt][3])*ps1;
        *(float2*)(ob + (size_t)r0*ROWSTRIDE + d) = o0;
        *(float2*)(ob + (size_t)r1*ROWSTRIDE + d) = o1;
    }
}

// ---------------- launch ----------------
extern "C" void kernel_launch(void* const* d_in, const int* in_sizes, int n_in,
                              void* d_out, int out_size) {
    const float* query = (const float*)d_in[0];
    const float* key   = (const float*)d_in[1];
    const float* value = (const float*)d_in[2];
    const float* proj  = (const float*)d_in[3];
    float* out = (float*)d_out;

    const int SM_SIDE = (16384 + 4096 + 64 + 32) * 4;   // 82304
    const int SM_MAIN = SM_MAIN_FLOATS * 4;              // 227072

    cudaFuncSetAttribute(kside_kernel, cudaFuncAttributeMaxDynamicSharedMemorySize, SM_SIDE);
    cudaFuncSetAttribute(qside_kernel, cudaFuncAttributeMaxDynamicSharedMemorySize, SM_SIDE);
    cudaFuncSetAttribute(main_kernel,  cudaFuncAttributeMaxDynamicSharedMemorySize, SM_MAIN);

    init_kernel<<<64, 256>>>(proj);
    kside_kernel<<<BH*NB, 256, SM_SIDE>>>(key);
    k2_kernel<<<BH*NB, 256>>>(value);
    reduce_kernel<<<(BH*Mq*Eq + 255)/256, 256>>>();
    qside_kernel<<<BH*NB, 256, SM_SIDE>>>(query);
    main_kernel<<<BH*NB, 512, SM_MAIN>>>(value, out);
}

// round 5
// speedup vs baseline: 1.3672x; 1.0136x over previous
#include <cuda_runtime.h>
#include <math.h>
#include <stdint.h>

#define Bq 2
#define Tq 2048
#define Hq 12
#define Eq 64
#define Mq 256
#define NB 32            // T / 64
#define BH 24            // B*H
#define ROWSTRIDE (Hq*Eq)  // 768 floats between consecutive t
#define SP 72            // padded smem stride (conflict-free MMA fragment loads)

#define DN 0.35355339059327379f         // sqrt(1/sqrt(E))
#define TEMP 0.125f                     // 1/sqrt(E)
#define HALF_LOG_M 2.7725887222397811f  // 0.5*log(256)
#define NEG_INF __int_as_float(0xff800000)

// ---------------- device scratch ----------------
__device__ float g_projHi[Eq*Mq];                // [e][m], dn folded, tf32 hi
__device__ float g_projLo[Eq*Mq];                // [e][m], residual lo
__device__ float g_qT  [BH*Tq*Eq];               // per block: [e][i], temp folded
__device__ float g_kT  [BH*Tq*Eq];               // per block: [e][j], raw k
__device__ float g_kp  [BH*NB*Mq*64];            // per block: [m][j]; k_prime (s_k=0, tf32)
__device__ float g_qpT [BH*NB*Mq*64];            // per block: [m][i]; q_prime (tf32)
__device__ float g_qls [BH*Tq];                  // q_log_scale
__device__ float g_kv  [BH*Mq*Eq];               // [m][d]
__device__ float g_kps [BH*Mq];
__device__ float g_kvpart [BH*32*Mq*Eq];
__device__ float g_kpspart[BH*32*Mq];

// ---------------- helpers ----------------
__device__ __forceinline__ float tf32_rna(float x) {
    uint32_t r;
    asm("cvt.rna.tf32.f32 %0, %1;" : "=r"(r) : "f"(x));
    return __uint_as_float(r);
}

// D(16x8) += A(16x8) * B(8x8); tf32 inputs, f32 accum.
__device__ __forceinline__ void mma_tf32(float c[4],
        float a0, float a1, float a2, float a3, float b0, float b1)
{
    asm volatile(
        "mma.sync.aligned.m16n8k8.row.col.f32.tf32.tf32.f32 "
        "{%0,%1,%2,%3}, {%4,%5,%6,%7}, {%8,%9}, {%0,%1,%2,%3};\n"
        : "+f"(c[0]), "+f"(c[1]), "+f"(c[2]), "+f"(c[3])
        : "r"(__float_as_uint(a0)), "r"(__float_as_uint(a1)),
          "r"(__float_as_uint(a2)), "r"(__float_as_uint(a3)),
          "r"(__float_as_uint(b0)), "r"(__float_as_uint(b1)));
}

// ---------------- kernel 0: init — split proj into tf32 hi/lo ----------------
__global__ void init_kernel(const float* __restrict__ proj) {
    int idx = blockIdx.x*256 + threadIdx.x;
    if (idx < Eq*Mq) {
        int e = idx >> 8;
        int m = idx & 255;
        float x = proj[m*Eq + e] * DN;
        float hi = tf32_rna(x);
        g_projHi[idx] = hi;
        g_projLo[idx] = x - hi;
    }
}

// ---------------- kernel 1: sides — k' / q' feature GEMMs via split-tf32 MMA ----------------
// grid (768, 2): y=0 -> k side, y=1 -> q side. 256 threads, 2 CTAs/SM.
__global__ __launch_bounds__(256,2) void sides_kernel(const float* __restrict__ key,
                                                      const float* __restrict__ query) {
    extern __shared__ float sm[];
    float* sTh   = sm;            // 4608  tile hi [e][row]
    float* sTl   = sm + 4608;     // 4608  tile lo
    float* sPh   = sm + 9216;     // 4608  proj chunk hi [e][m64]
    float* sPl   = sm + 13824;    // 4608  proj chunk lo
    float* sDiag = sm + 18432;    // 64
    float* sMax  = sm + 18496;    // 128

    int tid = threadIdx.x;
    int lane = tid & 31, wid = tid >> 5;
    int g = lane >> 2, t = lane & 3;
    int rt = wid & 3;             // row tile of 16
    int ch2 = wid >> 1 & 0;       // placeholder (unused)
    int mh = wid >> 2;            // m col-half (0/1) of each 64-chunk -> 32 cols
    int r0 = rt*16 + g, r1 = r0 + 8;
    int bidx = blockIdx.x, blk = bidx & 31, bh = bidx >> 5;
    int b = bh / Hq, h = bh % Hq;
    int t0 = blk * 64;
    int qside = blockIdx.y;
    (void)ch2;

    // stage tile transposed hi/lo; write raw transposed global copy
    const float* src = (qside ? query : key) + ((size_t)(b*Tq + t0)*Hq + h)*Eq;
    float* rawT = (qside ? g_qT : g_kT) + (size_t)bidx * 4096;
    float scale = qside ? TEMP : 1.0f;
    for (int i = tid; i < 4096; i += 256) {
        int j = i >> 6, e = i & 63;
        float x = src[(size_t)j*ROWSTRIDE + e];
        float hi = tf32_rna(x);
        sTh[e*SP + j] = hi;
        sTl[e*SP + j] = x - hi;
        rawT[e*64 + j] = x * scale;
    }
    __syncthreads();
    if (tid < 64) {
        float s = 0.f;
#pragma unroll
        for (int e = 0; e < 64; ++e) {
            float v = sTh[e*SP + tid] + sTl[e*SP + tid];
            s += v*v;
        }
        sDiag[tid] = 0.0625f * s;   // 0.5 * temp * sum(x^2)
    }

    float C[4][4][4];
#pragma unroll
    for (int c = 0; c < 4; ++c)
#pragma unroll
        for (int mt = 0; mt < 4; ++mt)
#pragma unroll
            for (int k = 0; k < 4; ++k) C[c][mt][k] = 0.f;

    // 4 chunks of 64 feature columns
#pragma unroll 1
    for (int c = 0; c < 4; ++c) {
        __syncthreads();   // (also covers diag) protect sPh/sPl reuse
        for (int i = tid; i < 4096; i += 256) {
            int e = i >> 6, m = i & 63;
            sPh[e*SP + m] = g_projHi[e*256 + c*64 + m];
            sPl[e*SP + m] = g_projLo[e*256 + c*64 + m];
        }
        __syncthreads();
#pragma unroll
        for (int kc = 0; kc < 8; ++kc) {
            int k0 = kc*8;
            float ah0 = sTh[(k0+t)*SP + r0],   ah1 = sTh[(k0+t)*SP + r1];
            float ah2 = sTh[(k0+t+4)*SP + r0], ah3 = sTh[(k0+t+4)*SP + r1];
            float al0 = sTl[(k0+t)*SP + r0],   al1 = sTl[(k0+t)*SP + r1];
            float al2 = sTl[(k0+t+4)*SP + r0], al3 = sTl[(k0+t+4)*SP + r1];
#pragma unroll
            for (int mt = 0; mt < 4; ++mt) {
                int mc = mh*32 + mt*8 + g;
                float bh0 = sPh[(k0+t)*SP + mc], bh1 = sPh[(k0+t+4)*SP + mc];
                float bl0 = sPl[(k0+t)*SP + mc], bl1 = sPl[(k0+t+4)*SP + mc];
                mma_tf32(C[c][mt], ah0,ah1,ah2,ah3, bh0,bh1);
                mma_tf32(C[c][mt], ah0,ah1,ah2,ah3, bl0,bl1);
                mma_tf32(C[c][mt], al0,al1,al2,al3, bh0,bh1);
            }
        }
    }

    if (!qside) {
        // k' = exp(k_dash - k_diag), store [m][j]
        float dg0 = sDiag[r0], dg1 = sDiag[r1];
        float* kp = g_kp + (size_t)bidx * 16384;
#pragma unroll
        for (int c = 0; c < 4; ++c)
#pragma unroll
            for (int mt = 0; mt < 4; ++mt) {
                int m0 = c*64 + mh*32 + mt*8 + 2*t;
                kp[(size_t)m0*64 + r0]     = tf32_rna(__expf(C[c][mt][0] - dg0));
                kp[(size_t)(m0+1)*64 + r0] = tf32_rna(__expf(C[c][mt][1] - dg0));
                kp[(size_t)m0*64 + r1]     = tf32_rna(__expf(C[c][mt][2] - dg1));
                kp[(size_t)(m0+1)*64 + r1] = tf32_rna(__expf(C[c][mt][3] - dg1));
            }
    } else {
        // row max over all 256 features
        float mx0 = NEG_INF, mx1 = NEG_INF;
#pragma unroll
        for (int c = 0; c < 4; ++c)
#pragma unroll
            for (int mt = 0; mt < 4; ++mt) {
                mx0 = fmaxf(mx0, fmaxf(C[c][mt][0], C[c][mt][1]));
                mx1 = fmaxf(mx1, fmaxf(C[c][mt][2], C[c][mt][3]));
            }
        mx0 = fmaxf(mx0, __shfl_xor_sync(0xffffffffu, mx0, 1));
        mx0 = fmaxf(mx0, __shfl_xor_sync(0xffffffffu, mx0, 2));
        mx1 = fmaxf(mx1, __shfl_xor_sync(0xffffffffu, mx1, 1));
        mx1 = fmaxf(mx1, __shfl_xor_sync(0xffffffffu, mx1, 2));
        if (t == 0) { sMax[mh*64 + r0] = mx0; sMax[mh*64 + r1] = mx1; }
        __syncthreads();
        float rm0 = fmaxf(sMax[r0], sMax[64 + r0]);
        float rm1 = fmaxf(sMax[r1], sMax[64 + r1]);
        float* qp = g_qpT + (size_t)bidx * 16384;
#pragma unroll
        for (int c = 0; c < 4; ++c)
#pragma unroll
            for (int mt = 0; mt < 4; ++mt) {
                int m0 = c*64 + mh*32 + mt*8 + 2*t;
                qp[(size_t)m0*64 + r0]     = tf32_rna(__expf(C[c][mt][0] - rm0));
                qp[(size_t)(m0+1)*64 + r0] = tf32_rna(__expf(C[c][mt][1] - rm0));
                qp[(size_t)m0*64 + r1]     = tf32_rna(__expf(C[c][mt][2] - rm1));
                qp[(size_t)(m0+1)*64 + r1] = tf32_rna(__expf(C[c][mt][3] - rm1));
            }
        if (mh == 0 && t == 0) {
            g_qls[bh*Tq + t0 + r0] = rm0 - sDiag[r0] - HALF_LOG_M;
            g_qls[bh*Tq + t0 + r1] = rm1 - sDiag[r1] - HALF_LOG_M;
        }
    }
}

// ---------------- kernel 2: partial kpsum / kv (read-only k') ----------------
__global__ __launch_bounds__(256,1) void k2_kernel(const float* __restrict__ value) {
    __shared__ __align__(16) float sV[4096];   // [j][d]
    int tid = threadIdx.x;
    int bh = blockIdx.x >> 5, sblk = blockIdx.x & 31;
    int b = bh / Hq, h = bh % Hq;
    float acc[64];
#pragma unroll
    for (int d = 0; d < 64; ++d) acc[d] = 0.f;
    float ksum = 0.f;

    const float* vb = value + ((size_t)(b*Tq + sblk*64)*Hq + h)*Eq;
    for (int i = tid; i < 4096; i += 256)
        sV[i] = vb[(size_t)(i>>6)*ROWSTRIDE + (i&63)];
    __syncthreads();
    const float* kbuf = g_kp + ((size_t)((bh*32 + sblk)*256 + tid))*64;
    for (int j = 0; j < 64; j += 4) {
        float4 kv4 = *(const float4*)(kbuf + j);
        ksum += kv4.x + kv4.y + kv4.z + kv4.w;
        float pj[4] = {kv4.x, kv4.y, kv4.z, kv4.w};
#pragma unroll
        for (int jj = 0; jj < 4; ++jj) {
            const float4* vr = (const float4*)(sV + (j+jj)*64);
            float p = pj[jj];
#pragma unroll
            for (int d4 = 0; d4 < 16; ++d4) {
                float4 vv = vr[d4];
                acc[d4*4+0] += p*vv.x;
                acc[d4*4+1] += p*vv.y;
                acc[d4*4+2] += p*vv.z;
                acc[d4*4+3] += p*vv.w;
            }
        }
    }
    float* kvout = g_kvpart + ((size_t)(bh*32 + sblk)*256 + tid)*64;
#pragma unroll
    for (int d4 = 0; d4 < 16; ++d4)
        ((float4*)kvout)[d4] = make_float4(acc[d4*4], acc[d4*4+1], acc[d4*4+2], acc[d4*4+3]);
    g_kpspart[(bh*32 + sblk)*256 + tid] = ksum;
}

// ---------------- kernel 2b: reduce partials ----------------
__global__ void reduce_kernel() {
    int idx = blockIdx.x*256 + threadIdx.x;
    if (idx < BH*Mq*Eq) {
        int bh = idx >> 14;
        int rem = idx & 16383;
        float s = 0.f;
#pragma unroll
        for (int p = 0; p < 32; ++p) s += g_kvpart[(size_t)(bh*32 + p)*16384 + rem];
        g_kv[idx] = s;
    }
    if (idx < BH*Mq) {
        int bh = idx >> 8; int m = idx & 255;
        float s = 0.f;
#pragma unroll
        for (int p = 0; p < 32; ++p) s += g_kpspart[(bh*32 + p)*256 + m];
        g_kps[idx] = s;
    }
}

// ---------------- kernel 4: main fused, streaming, 512 threads ----------------
// smem float offsets
#define O_QTB 0        // 4608  q*temp hi [e][i]
#define O_QTS 4608     // 4608  q*temp lo
#define O_KTB 9216     // 4608  k hi [e][j]       | alias sE  [j][i]
#define O_KTS 13824    // 4608  k lo              | alias sDP [j][i]
#define O_QP  18432    // 18432 q' [m][i]
#define O_KP  36864    // 18432 k' [m][j]         | alias sV [j][d] (first 4608) / sKV [m][d]
#define O_KPS 55296    // 256
#define O_QLS 55552    // 64
#define O_SSE 55616    // 256  [jh][row]
#define O_SDP 55872    // 256
#define O_QPK 56128    // 512
#define O_LN  56640    // 64
#define O_PS  56704    // 64
#define SM_MAIN_FLOATS 56768

__global__ __launch_bounds__(512,1) void main_kernel(const float* __restrict__ value,
                                                     float* __restrict__ out) {
    extern __shared__ float smm[];
    float* sQTb = smm + O_QTB;
    float* sQTs = smm + O_QTS;
    float* sKTb = smm + O_KTB;
    float* sKTs = smm + O_KTS;
    float* sQP  = smm + O_QP;
    float* sKP  = smm + O_KP;
    float* sKps = smm + O_KPS;
    float* sQls = smm + O_QLS;
    float* sSe  = smm + O_SSE;
    float* sDp  = smm + O_SDP;
    float* sQpk = smm + O_QPK;
    float* sLn  = smm + O_LN;
    float* sPs  = smm + O_PS;
    float* sE   = sKTb;   // [j][i] exp(QK)
    float* sDPm = sKTs;   // [j][i] dots_prime
    float* sV   = sKP;    // [j][d]
    float* sKV  = sKP;    // [m][d]

    int tid = threadIdx.x;
    int lane = tid & 31, wid = tid >> 5;
    int g = lane >> 2, t = lane & 3;
    int iw = wid & 3, jh = wid >> 2;        // 4 x 4 warp grid
    int i0 = iw * 16;
    int bidx = blockIdx.x, blk = bidx & 31, bh = bidx >> 5;
    int b = bh / Hq, h = bh % Hq;
    int t0 = blk * 64;
    int r0 = i0 + g, r1 = i0 + g + 8;

    // ---- phase 0: persistent operand loads ----
    {
        const float* qt = g_qT + (size_t)bidx*4096;
        for (int i = tid; i < 4096; i += 512) {
            int e = i >> 6, c = i & 63;
            float x = qt[i];
            float hi = tf32_rna(x);
            sQTb[e*SP + c] = hi;
            sQTs[e*SP + c] = x - hi;
        }
        const float4* qp = (const float4*)(g_qpT + (size_t)bidx*16384);
        for (int i = tid; i < 4096; i += 512) {
            float4 v4 = qp[i];
            int m = i >> 4, c4 = (i & 15) * 4;
            *(float4*)(sQP + m*SP + c4) = v4;
        }
        if (tid < 256) sKps[tid] = g_kps[bh*Mq + tid];
        if (tid < 64)  sQls[tid] = g_qls[bh*Tq + t0 + tid];
    }

    float accE[2][4], accD[2][4];
#pragma unroll
    for (int dt = 0; dt < 2; ++dt)
#pragma unroll
        for (int c = 0; c < 4; ++c) { accE[dt][c] = 0.f; accD[dt][c] = 0.f; }
    float seR0 = 0.f, seR1 = 0.f, dpR0 = 0.f, dpR1 = 0.f;

    // ---- streaming neighbor loop ----
#pragma unroll 1
    for (int nw = 0; nw < 3; ++nw) {
        int nb = blk - 1 + nw;
        if (nb < 0 || nb >= NB) continue;
        __syncthreads();   // previous iteration's MMA reads done before overwrite
        size_t kb = (size_t)(bh*32 + nb);
        const float* kt = g_kT + kb*4096;
        for (int i = tid; i < 4096; i += 512) {
            int e = i >> 6, c = i & 63;
            float x = kt[i];
            float hi = tf32_rna(x);
            sKTb[e*SP + c] = hi;
            sKTs[e*SP + c] = x - hi;
        }
        const float4* kp = (const float4*)(g_kp + kb*16384);
        for (int i = tid; i < 4096; i += 512) {
            float4 v4 = kp[i];
            int m = i >> 4, c4 = (i & 15)*4;
            *(float4*)(sKP + m*SP + c4) = v4;
        }
        __syncthreads();

        float Cqk[2][4], Cdp[2][4];
#pragma unroll
        for (int jt = 0; jt < 2; ++jt)
#pragma unroll
            for (int c = 0; c < 4; ++c) { Cqk[jt][c] = 0.f; Cdp[jt][c] = 0.f; }

        // QK: K=64, split hi/lo (3 MMAs)
#pragma unroll
        for (int kc = 0; kc < 8; ++kc) {
            int k0 = kc*8;
            float ab0 = sQTb[(k0+t)*SP + i0+g],   ab1 = sQTb[(k0+t)*SP + i0+g+8];
            float ab2 = sQTb[(k0+t+4)*SP + i0+g], ab3 = sQTb[(k0+t+4)*SP + i0+g+8];
            float as0 = sQTs[(k0+t)*SP + i0+g],   as1 = sQTs[(k0+t)*SP + i0+g+8];
            float as2 = sQTs[(k0+t+4)*SP + i0+g], as3 = sQTs[(k0+t+4)*SP + i0+g+8];
#pragma unroll
            for (int jt = 0; jt < 2; ++jt) {
                int j = jh*16 + jt*8 + g;
                float bb0 = sKTb[(k0+t)*SP + j], bb1 = sKTb[(k0+t+4)*SP + j];
                float bs0 = sKTs[(k0+t)*SP + j], bs1 = sKTs[(k0+t+4)*SP + j];
                mma_tf32(Cqk[jt], ab0,ab1,ab2,ab3, bb0,bb1);
                mma_tf32(Cqk[jt], ab0,ab1,ab2,ab3, bs0,bs1);
                mma_tf32(Cqk[jt], as0,as1,as2,as3, bb0,bb1);
            }
        }
        // dots_prime: K=256
#pragma unroll 4
        for (int kc = 0; kc < 32; ++kc) {
            int k0 = kc*8;
            float a0 = sQP[(k0+t)*SP + i0+g],   a1 = sQP[(k0+t)*SP + i0+g+8];
            float a2 = sQP[(k0+t+4)*SP + i0+g], a3 = sQP[(k0+t+4)*SP + i0+g+8];
#pragma unroll
            for (int jt = 0; jt < 2; ++jt) {
                int j = jh*16 + jt*8 + g;
                float b0 = sKP[(k0+t)*SP + j], b1 = sKP[(k0+t+4)*SP + j];
                mma_tf32(Cdp[jt], a0,a1,a2,a3, b0,b1);
            }
        }
        __syncthreads();   // all warps done reading sKTb/sKTs/sKP

        // exp frags + running row sums; write E and dp tiles [j][i]
#pragma unroll
        for (int jt = 0; jt < 2; ++jt) {
            int j = jh*16 + jt*8 + 2*t;
            float e00 = __expf(Cqk[jt][0]);
            float e01 = __expf(Cqk[jt][1]);
            float e10 = __expf(Cqk[jt][2]);
            float e11 = __expf(Cqk[jt][3]);
            seR0 += e00 + e01;  seR1 += e10 + e11;
            dpR0 += Cdp[jt][0] + Cdp[jt][1];
            dpR1 += Cdp[jt][2] + Cdp[jt][3];
            sE[(size_t)j*SP + r0]     = tf32_rna(e00);
            sE[(size_t)(j+1)*SP + r0] = tf32_rna(e01);
            sE[(size_t)j*SP + r1]     = tf32_rna(e10);
            sE[(size_t)(j+1)*SP + r1] = tf32_rna(e11);
            sDPm[(size_t)j*SP + r0]     = tf32_rna(Cdp[jt][0]);
            sDPm[(size_t)(j+1)*SP + r0] = tf32_rna(Cdp[jt][1]);
            sDPm[(size_t)j*SP + r1]     = tf32_rna(Cdp[jt][2]);
            sDPm[(size_t)(j+1)*SP + r1] = tf32_rna(Cdp[jt][3]);
        }
        // v tile
        const float* vb = value + ((size_t)(b*Tq + nb*64)*Hq + h)*Eq;
        for (int i = tid; i < 1024; i += 512) {
            int j = i >> 4, d4 = (i & 15)*4;
            float4 v4 = *(const float4*)(vb + (size_t)j*ROWSTRIDE + d4);
            v4.x = tf32_rna(v4.x); v4.y = tf32_rna(v4.y);
            v4.z = tf32_rna(v4.z); v4.w = tf32_rna(v4.w);
            *(float4*)(sV + j*SP + d4) = v4;
        }
        __syncthreads();

        // accE += E . V ; accD += dp . V   (K = 64 over j)
#pragma unroll
        for (int kc = 0; kc < 8; ++kc) {
            int k0 = kc*8;
            float aE0 = sE[(k0+t)*SP + i0+g],   aE1 = sE[(k0+t)*SP + i0+g+8];
            float aE2 = sE[(k0+t+4)*SP + i0+g], aE3 = sE[(k0+t+4)*SP + i0+g+8];
            float aD0 = sDPm[(k0+t)*SP + i0+g],   aD1 = sDPm[(k0+t)*SP + i0+g+8];
            float aD2 = sDPm[(k0+t+4)*SP + i0+g], aD3 = sDPm[(k0+t+4)*SP + i0+g+8];
#pragma unroll
            for (int dt = 0; dt < 2; ++dt) {
                int d = jh*16 + dt*8 + g;
                float b0 = sV[(k0+t)*SP + d], b1 = sV[(k0+t+4)*SP + d];
                mma_tf32(accE[dt], aE0,aE1,aE2,aE3, b0,b1);
                mma_tf32(accD[dt], aD0,aD1,aD2,aD3, b0,b1);
            }
        }
    }

    // ---- stats reduce ----
    seR0 += __shfl_xor_sync(0xffffffffu, seR0, 1);
    seR0 += __shfl_xor_sync(0xffffffffu, seR0, 2);
    seR1 += __shfl_xor_sync(0xffffffffu, seR1, 1);
    seR1 += __shfl_xor_sync(0xffffffffu, seR1, 2);
    dpR0 += __shfl_xor_sync(0xffffffffu, dpR0, 1);
    dpR0 += __shfl_xor_sync(0xffffffffu, dpR0, 2);
    dpR1 += __shfl_xor_sync(0xffffffffu, dpR1, 1);
    dpR1 += __shfl_xor_sync(0xffffffffu, dpR1, 2);
    __syncthreads();   // prior MMA reads of sV complete before any reuse; also orders stats writes
    if (t == 0) {
        sSe[jh*64 + r0] = seR0; sSe[jh*64 + r1] = seR1;
        sDp[jh*64 + r0] = dpR0; sDp[jh*64 + r1] = dpR1;
    }
    // qp_kp_1 partials
    {
        int ii = tid & 63, part = tid >> 6;   // 8 parts x 32 m
        float s = 0.f;
#pragma unroll 8
        for (int mm = 0; mm < 32; ++mm) {
            int m = part*32 + mm;
            s += sQP[m*SP + ii] * sKps[m];
        }
        sQpk[part*64 + ii] = s;
    }
    __syncthreads();
    if (tid < 64) {
        float qpk1 = 0.f;
#pragma unroll
        for (int p = 0; p < 8; ++p) qpk1 += sQpk[p*64 + tid];
        float se = sSe[tid] + sSe[64+tid] + sSe[128+tid] + sSe[192+tid];
        float dp = sDp[tid] + sDp[64+tid] + sDp[128+tid] + sDp[192+tid];
        float lse = __logf(se);                      // no max needed: QK small
        float pls = sQls[tid] - HALF_LOG_M;          // k_log_scale = -half_log_m (s_k = 0)
        float lr  = __logf(fmaxf(qpk1 - dp, 1e-24f)) + pls;
        float mxv = fmaxf(lse, lr);
        float ln  = mxv + log1pf(__expf(-fabsf(lse - lr)));
        sLn[tid] = ln;
        sPs[tid] = __expf(pls - ln);
    }
    __syncthreads();
    float iE0 = __expf(-sLn[r0]), iE1 = __expf(-sLn[r1]);
    float ps0 = sPs[r0], ps1 = sPs[r1];

    // ---- C2 = q' . kv ----
    {
        const float4* kvsrc = (const float4*)(g_kv + (size_t)bh*16384);
        for (int i = tid; i < 4096; i += 512) {
            float4 v4 = kvsrc[i];
            v4.x = tf32_rna(v4.x); v4.y = tf32_rna(v4.y);
            v4.z = tf32_rna(v4.z); v4.w = tf32_rna(v4.w);
            int m = i >> 4, d4 = (i & 15)*4;
            *(float4*)(sKV + m*SP + d4) = v4;
        }
    }
    __syncthreads();
    float C2[2][4];
#pragma unroll
    for (int dt = 0; dt < 2; ++dt)
#pragma unroll
        for (int c = 0; c < 4; ++c) C2[dt][c] = 0.f;
#pragma unroll 4
    for (int kc = 0; kc < 32; ++kc) {
        int k0 = kc*8;
        float a0 = sQP[(k0+t)*SP + i0+g],   a1 = sQP[(k0+t)*SP + i0+g+8];
        float a2 = sQP[(k0+t+4)*SP + i0+g], a3 = sQP[(k0+t+4)*SP + i0+g+8];
#pragma unroll
        for (int dt = 0; dt < 2; ++dt) {
            int d = jh*16 + dt*8 + g;
            float b0 = sKV[(k0+t)*SP + d], b1 = sKV[(k0+t+4)*SP + d];
            mma_tf32(C2[dt], a0,a1,a2,a3, b0,b1);
        }
    }

    // ---- epilogue: out = accE*exp(-ln) + (C2 - accD)*ps ----
    float* ob = out + ((size_t)(b*Tq + t0)*Hq + h)*Eq;
#pragma unroll
    for (int dt = 0; dt < 2; ++dt) {
        int d = jh*16 + dt*8 + 2*t;
        float2 o0, o1;
        o0.x = accE[dt][0]*iE0 + (C2[dt][0] - accD[dt][0])*ps0;
        o0.y = accE[dt][1]*iE0 + (C2[dt][1] - accD[dt][1])*ps0;
        o1.x = accE[dt][2]*iE1 + (C2[dt][2] - accD[dt][2])*ps1;
        o1.y = accE[dt][3]*iE1 + (C2[dt][3] - accD[dt][3])*ps1;
        *(float2*)(ob + (size_t)r0*ROWSTRIDE + d) = o0;
        *(float2*)(ob + (size_t)r1*ROWSTRIDE + d) = o1;
    }
}

// ---------------- launch ----------------
extern "C" void kernel_launch(void* const* d_in, const int* in_sizes, int n_in,
                              void* d_out, int out_size) {
    const float* query = (const float*)d_in[0];
    const float* key   = (const float*)d_in[1];
    const float* value = (const float*)d_in[2];
    const float* proj  = (const float*)d_in[3];
    float* out = (float*)d_out;

    const int SM_SIDES = 18624 * 4;                      // 74496
    const int SM_MAIN  = SM_MAIN_FLOATS * 4;             // 227072

    cudaFuncSetAttribute(sides_kernel, cudaFuncAttributeMaxDynamicSharedMemorySize, SM_SIDES);
    cudaFuncSetAttribute(main_kernel,  cudaFuncAttributeMaxDynamicSharedMemorySize, SM_MAIN);

    init_kernel<<<64, 256>>>(proj);
    sides_kernel<<<dim3(BH*NB, 2), 256, SM_SIDES>>>(key, query);
    k2_kernel<<<BH*NB, 256>>>(value);
    reduce_kernel<<<(BH*Mq*Eq + 255)/256, 256>>>();
    main_kernel<<<BH*NB, 512, SM_MAIN>>>(value, out);
}

// round 6
// speedup vs baseline: 1.5174x; 1.1098x over previous
#include <cuda_runtime.h>
#include <math.h>
#include <stdint.h>

#define Bq 2
#define Tq 2048
#define Hq 12
#define Eq 64
#define Mq 256
#define NB 32            // T / 64
#define BH 24            // B*H
#define ROWSTRIDE (Hq*Eq)  // 768 floats between consecutive t
#define SP 72            // padded smem stride (conflict-free MMA fragment loads)
#define SPK 68           // stride for [m][j] k' staging in k2

#define DN 0.35355339059327379f         // sqrt(1/sqrt(E))
#define TEMP 0.125f                     // 1/sqrt(E)
#define HALF_LOG_M 2.7725887222397811f  // 0.5*log(256)
#define NEG_INF __int_as_float(0xff800000)

// ---------------- device scratch ----------------
__device__ float g_qT  [BH*Tq*Eq];               // per block: [e][i], temp folded
__device__ float g_kT  [BH*Tq*Eq];               // per block: [e][j], raw k
__device__ float g_kp  [BH*NB*Mq*64];            // per block: [m][j]; k_prime (s_k=0, tf32)
__device__ float g_qpT [BH*NB*Mq*64];            // per block: [m][i]; q_prime (tf32)
__device__ float g_qls [BH*Tq];                  // q_log_scale
__device__ float g_kv  [BH*Mq*Eq];               // [m][d]
__device__ float g_kps [BH*Mq];
__device__ float g_kvpart [BH*32*Mq*Eq];
__device__ float g_kpspart[BH*32*Mq];

// ---------------- helpers ----------------
__device__ __forceinline__ float tf32_rna(float x) {
    uint32_t r;
    asm("cvt.rna.tf32.f32 %0, %1;" : "=r"(r) : "f"(x));
    return __uint_as_float(r);
}

// D(16x8) += A(16x8) * B(8x8); tf32 inputs, f32 accum.
__device__ __forceinline__ void mma_tf32(float c[4],
        float a0, float a1, float a2, float a3, float b0, float b1)
{
    asm volatile(
        "mma.sync.aligned.m16n8k8.row.col.f32.tf32.tf32.f32 "
        "{%0,%1,%2,%3}, {%4,%5,%6,%7}, {%8,%9}, {%0,%1,%2,%3};\n"
        : "+f"(c[0]), "+f"(c[1]), "+f"(c[2]), "+f"(c[3])
        : "r"(__float_as_uint(a0)), "r"(__float_as_uint(a1)),
          "r"(__float_as_uint(a2)), "r"(__float_as_uint(a3)),
          "r"(__float_as_uint(b0)), "r"(__float_as_uint(b1)));
}

// ---------------- kernel 1: sides — k' / q' feature GEMMs via split-tf32 MMA ----------------
// grid (768, 2): y=0 -> k side, y=1 -> q side. 256 threads, 2 CTAs/SM.
__global__ __launch_bounds__(256,2) void sides_kernel(const float* __restrict__ key,
                                                      const float* __restrict__ query,
                                                      const float* __restrict__ proj) {
    extern __shared__ float sm[];
    float* sTh   = sm;            // 4608  tile hi [e][row]
    float* sTl   = sm + 4608;     // 4608  tile lo
    float* sPh   = sm + 9216;     // 4608  proj chunk hi [e][m64]
    float* sPl   = sm + 13824;    // 4608  proj chunk lo
    float* sDiag = sm + 18432;    // 64
    float* sMax  = sm + 18496;    // 128

    int tid = threadIdx.x;
    int lane = tid & 31, wid = tid >> 5;
    int g = lane >> 2, t = lane & 3;
    int rt = wid & 3;             // row tile of 16
    int mh = wid >> 2;            // m col-half (0/1) of each 64-chunk -> 32 cols
    int r0 = rt*16 + g, r1 = r0 + 8;
    int bidx = blockIdx.x, blk = bidx & 31, bh = bidx >> 5;
    int b = bh / Hq, h = bh % Hq;
    int t0 = blk * 64;
    int qside = blockIdx.y;

    // stage tile transposed hi/lo; write raw transposed global copy
    const float* src = (qside ? query : key) + ((size_t)(b*Tq + t0)*Hq + h)*Eq;
    float* rawT = (qside ? g_qT : g_kT) + (size_t)bidx * 4096;
    float scale = qside ? TEMP : 1.0f;
    for (int i = tid; i < 4096; i += 256) {
        int j = i >> 6, e = i & 63;
        float x = src[(size_t)j*ROWSTRIDE + e];
        float hi = tf32_rna(x);
        sTh[e*SP + j] = hi;
        sTl[e*SP + j] = x - hi;
        rawT[e*64 + j] = x * scale;
    }
    __syncthreads();
    if (tid < 64) {
        float s = 0.f;
#pragma unroll
        for (int e = 0; e < 64; ++e) {
            float v = sTh[e*SP + tid] + sTl[e*SP + tid];
            s += v*v;
        }
        sDiag[tid] = 0.0625f * s;   // 0.5 * temp * sum(x^2)
    }

    float C[4][4][4];
#pragma unroll
    for (int c = 0; c < 4; ++c)
#pragma unroll
        for (int mt = 0; mt < 4; ++mt)
#pragma unroll
            for (int k = 0; k < 4; ++k) C[c][mt][k] = 0.f;

    // 4 chunks of 64 feature columns; proj split done inline (proj is [m][e])
#pragma unroll 1
    for (int c = 0; c < 4; ++c) {
        __syncthreads();   // (also covers diag) protect sPh/sPl reuse
        for (int i = tid; i < 4096; i += 256) {
            int mm = i >> 6, e = i & 63;   // coalesced over e
            float x = proj[(size_t)(c*64 + mm)*64 + e] * DN;
            float hi = tf32_rna(x);
            sPh[e*SP + mm] = hi;
            sPl[e*SP + mm] = x - hi;
        }
        __syncthreads();
#pragma unroll
        for (int kc = 0; kc < 8; ++kc) {
            int k0 = kc*8;
            float ah0 = sTh[(k0+t)*SP + r0],   ah1 = sTh[(k0+t)*SP + r1];
            float ah2 = sTh[(k0+t+4)*SP + r0], ah3 = sTh[(k0+t+4)*SP + r1];
            float al0 = sTl[(k0+t)*SP + r0],   al1 = sTl[(k0+t)*SP + r1];
            float al2 = sTl[(k0+t+4)*SP + r0], al3 = sTl[(k0+t+4)*SP + r1];
#pragma unroll
            for (int mt = 0; mt < 4; ++mt) {
                int mc = mh*32 + mt*8 + g;
                float bh0 = sPh[(k0+t)*SP + mc], bh1 = sPh[(k0+t+4)*SP + mc];
                float bl0 = sPl[(k0+t)*SP + mc], bl1 = sPl[(k0+t+4)*SP + mc];
                mma_tf32(C[c][mt], ah0,ah1,ah2,ah3, bh0,bh1);
                mma_tf32(C[c][mt], ah0,ah1,ah2,ah3, bl0,bl1);
                mma_tf32(C[c][mt], al0,al1,al2,al3, bh0,bh1);
            }
        }
    }

    if (!qside) {
        // k' = exp(k_dash - k_diag), store [m][j]
        float dg0 = sDiag[r0], dg1 = sDiag[r1];
        float* kp = g_kp + (size_t)bidx * 16384;
#pragma unroll
        for (int c = 0; c < 4; ++c)
#pragma unroll
            for (int mt = 0; mt < 4; ++mt) {
                int m0 = c*64 + mh*32 + mt*8 + 2*t;
                kp[(size_t)m0*64 + r0]     = tf32_rna(__expf(C[c][mt][0] - dg0));
                kp[(size_t)(m0+1)*64 + r0] = tf32_rna(__expf(C[c][mt][1] - dg0));
                kp[(size_t)m0*64 + r1]     = tf32_rna(__expf(C[c][mt][2] - dg1));
                kp[(size_t)(m0+1)*64 + r1] = tf32_rna(__expf(C[c][mt][3] - dg1));
            }
    } else {
        // row max over all 256 features
        float mx0 = NEG_INF, mx1 = NEG_INF;
#pragma unroll
        for (int c = 0; c < 4; ++c)
#pragma unroll
            for (int mt = 0; mt < 4; ++mt) {
                mx0 = fmaxf(mx0, fmaxf(C[c][mt][0], C[c][mt][1]));
                mx1 = fmaxf(mx1, fmaxf(C[c][mt][2], C[c][mt][3]));
            }
        mx0 = fmaxf(mx0, __shfl_xor_sync(0xffffffffu, mx0, 1));
        mx0 = fmaxf(mx0, __shfl_xor_sync(0xffffffffu, mx0, 2));
        mx1 = fmaxf(mx1, __shfl_xor_sync(0xffffffffu, mx1, 1));
        mx1 = fmaxf(mx1, __shfl_xor_sync(0xffffffffu, mx1, 2));
        if (t == 0) { sMax[mh*64 + r0] = mx0; sMax[mh*64 + r1] = mx1; }
        __syncthreads();
        float rm0 = fmaxf(sMax[r0], sMax[64 + r0]);
        float rm1 = fmaxf(sMax[r1], sMax[64 + r1]);
        float* qp = g_qpT + (size_t)bidx * 16384;
#pragma unroll
        for (int c = 0; c < 4; ++c)
#pragma unroll
            for (int mt = 0; mt < 4; ++mt) {
                int m0 = c*64 + mh*32 + mt*8 + 2*t;
                qp[(size_t)m0*64 + r0]     = tf32_rna(__expf(C[c][mt][0] - rm0));
                qp[(size_t)(m0+1)*64 + r0] = tf32_rna(__expf(C[c][mt][1] - rm0));
                qp[(size_t)m0*64 + r1]     = tf32_rna(__expf(C[c][mt][2] - rm1));
                qp[(size_t)(m0+1)*64 + r1] = tf32_rna(__expf(C[c][mt][3] - rm1));
            }
        if (mh == 0 && t == 0) {
            g_qls[bh*Tq + t0 + r0] = rm0 - sDiag[r0] - HALF_LOG_M;
            g_qls[bh*Tq + t0 + r1] = rm1 - sDiag[r1] - HALF_LOG_M;
        }
    }
}

// ---------------- kernel 2: kv / kps partials via tf32 MMA ----------------
// one CTA per (bh, sblk); kv_part[m][d] = sum_j k'[m][j] * v[j][d]
__global__ __launch_bounds__(256,2) void k2_kernel(const float* __restrict__ value) {
    extern __shared__ float sm[];
    float* sKp = sm;              // [m][j] stride 68 : 17408 floats
    float* sVh = sm + 17408;      // [j][d] stride 72 hi : 4608
    float* sVl = sm + 22016;      // [j][d] lo : 4608  -> total 26624 floats (106 KB)
    int tid = threadIdx.x;
    int lane = tid & 31, wid = tid >> 5;
    int g = lane >> 2, t = lane & 3;
    int bh = blockIdx.x >> 5, sblk = blockIdx.x & 31;
    int b = bh / Hq, h = bh % Hq;

    // stage k' [m][j] (already tf32)
    const float4* kp = (const float4*)(g_kp + (size_t)blockIdx.x * 16384);
    for (int i = tid; i < 4096; i += 256) {
        int m = i >> 4, j4 = (i & 15)*4;
        *(float4*)(sKp + m*SPK + j4) = kp[i];
    }
    // stage v [j][d] split hi/lo
    const float* vb = value + ((size_t)(b*Tq + sblk*64)*Hq + h)*Eq;
    for (int i = tid; i < 1024; i += 256) {
        int j = i >> 4, d4 = (i & 15)*4;
        float4 v4 = *(const float4*)(vb + (size_t)j*ROWSTRIDE + d4);
        float4 hi, lo;
        hi.x = tf32_rna(v4.x); lo.x = v4.x - hi.x;
        hi.y = tf32_rna(v4.y); lo.y = v4.y - hi.y;
        hi.z = tf32_rna(v4.z); lo.z = v4.z - hi.z;
        hi.w = tf32_rna(v4.w); lo.w = v4.w - hi.w;
        *(float4*)(sVh + j*SP + d4) = hi;
        *(float4*)(sVl + j*SP + d4) = lo;
    }
    __syncthreads();

    // ksum: thread owns row m = tid
    {
        float s = 0.f;
#pragma unroll
        for (int j4 = 0; j4 < 64; j4 += 4) {
            float4 k4 = *(const float4*)(sKp + tid*SPK + j4);
            s += k4.x + k4.y + k4.z + k4.w;
        }
        g_kpspart[(size_t)blockIdx.x*256 + tid] = s;
    }

    // MMA: each warp owns 32 m-rows x 64 d
    float C[2][8][4];
#pragma unroll
    for (int it = 0; it < 2; ++it)
#pragma unroll
        for (int nt = 0; nt < 8; ++nt)
#pragma unroll
            for (int k = 0; k < 4; ++k) C[it][nt][k] = 0.f;

#pragma unroll
    for (int kc = 0; kc < 8; ++kc) {
        int k0 = kc*8;
        float a[2][4];
#pragma unroll
        for (int it = 0; it < 2; ++it) {
            int r = wid*32 + it*16 + g;
            a[it][0] = sKp[(size_t)r*SPK + k0 + t];
            a[it][1] = sKp[(size_t)(r+8)*SPK + k0 + t];
            a[it][2] = sKp[(size_t)r*SPK + k0 + t + 4];
            a[it][3] = sKp[(size_t)(r+8)*SPK + k0 + t + 4];
        }
#pragma unroll
        for (int nt = 0; nt < 8; ++nt) {
            int d = nt*8 + g;
            float bh0 = sVh[(k0+t)*SP + d], bh1 = sVh[(k0+t+4)*SP + d];
            float bl0 = sVl[(k0+t)*SP + d], bl1 = sVl[(k0+t+4)*SP + d];
#pragma unroll
            for (int it = 0; it < 2; ++it) {
                mma_tf32(C[it][nt], a[it][0],a[it][1],a[it][2],a[it][3], bh0,bh1);
                mma_tf32(C[it][nt], a[it][0],a[it][1],a[it][2],a[it][3], bl0,bl1);
            }
        }
    }

    // write partials [m][d]
    float* kvp = g_kvpart + (size_t)blockIdx.x * 16384;
#pragma unroll
    for (int it = 0; it < 2; ++it) {
        int m0 = wid*32 + it*16 + g;
#pragma unroll
        for (int nt = 0; nt < 8; ++nt) {
            int d = nt*8 + 2*t;
            *(float2*)(kvp + (size_t)m0*64 + d)     = make_float2(C[it][nt][0], C[it][nt][1]);
            *(float2*)(kvp + (size_t)(m0+8)*64 + d) = make_float2(C[it][nt][2], C[it][nt][3]);
        }
    }
}

// ---------------- kernel 2b: reduce partials ----------------
__global__ void reduce_kernel() {
    int idx = blockIdx.x*256 + threadIdx.x;
    if (idx < BH*Mq*Eq) {
        int bh = idx >> 14;
        int rem = idx & 16383;
        float s = 0.f;
#pragma unroll
        for (int p = 0; p < 32; ++p) s += g_kvpart[(size_t)(bh*32 + p)*16384 + rem];
        g_kv[idx] = s;
    }
    if (idx < BH*Mq) {
        int bh = idx >> 8; int m = idx & 255;
        float s = 0.f;
#pragma unroll
        for (int p = 0; p < 32; ++p) s += g_kpspart[(bh*32 + p)*256 + m];
        g_kps[idx] = s;
    }
}

// ---------------- kernel 4: main fused, streaming, 512 threads ----------------
// smem float offsets
#define O_QTB 0        // 4608  q*temp hi [e][i]
#define O_QTS 4608     // 4608  q*temp lo
#define O_KTB 9216     // 4608  k hi [e][j]       | alias sE  [j][i]
#define O_KTS 13824    // 4608  k lo              | alias sDP [j][i]
#define O_QP  18432    // 18432 q' [m][i]
#define O_KP  36864    // 18432 k' [m][j]         | alias sV [j][d] (first 4608) / sKV [m][d]
#define O_KPS 55296    // 256
#define O_QLS 55552    // 64
#define O_SSE 55616    // 256  [jh][row]
#define O_SDP 55872    // 256
#define O_QPK 56128    // 512
#define O_LN  56640    // 64
#define O_PS  56704    // 64
#define SM_MAIN_FLOATS 56768

__global__ __launch_bounds__(512,1) void main_kernel(const float* __restrict__ value,
                                                     float* __restrict__ out) {
    extern __shared__ float smm[];
    float* sQTb = smm + O_QTB;
    float* sQTs = smm + O_QTS;
    float* sKTb = smm + O_KTB;
    float* sKTs = smm + O_KTS;
    float* sQP  = smm + O_QP;
    float* sKP  = smm + O_KP;
    float* sKps = smm + O_KPS;
    float* sQls = smm + O_QLS;
    float* sSe  = smm + O_SSE;
    float* sDp  = smm + O_SDP;
    float* sQpk = smm + O_QPK;
    float* sLn  = smm + O_LN;
    float* sPs  = smm + O_PS;
    float* sE   = sKTb;   // [j][i] exp(QK)
    float* sDPm = sKTs;   // [j][i] dots_prime
    float* sV   = sKP;    // [j][d]
    float* sKV  = sKP;    // [m][d]

    int tid = threadIdx.x;
    int lane = tid & 31, wid = tid >> 5;
    int g = lane >> 2, t = lane & 3;
    int iw = wid & 3, jh = wid >> 2;        // 4 x 4 warp grid
    int i0 = iw * 16;
    int bidx = blockIdx.x, blk = bidx & 31, bh = bidx >> 5;
    int b = bh / Hq, h = bh % Hq;
    int t0 = blk * 64;
    int r0 = i0 + g, r1 = i0 + g + 8;

    // ---- phase 0: persistent operand loads ----
    {
        const float* qt = g_qT + (size_t)bidx*4096;
        for (int i = tid; i < 4096; i += 512) {
            int e = i >> 6, c = i & 63;
            float x = qt[i];
            float hi = tf32_rna(x);
            sQTb[e*SP + c] = hi;
            sQTs[e*SP + c] = x - hi;
        }
        const float4* qp = (const float4*)(g_qpT + (size_t)bidx*16384);
        for (int i = tid; i < 4096; i += 512) {
            float4 v4 = qp[i];
            int m = i >> 4, c4 = (i & 15) * 4;
            *(float4*)(sQP + m*SP + c4) = v4;
        }
        if (tid < 256) sKps[tid] = g_kps[bh*Mq + tid];
        if (tid < 64)  sQls[tid] = g_qls[bh*Tq + t0 + tid];
    }

    float accE[2][4], accD[2][4];
#pragma unroll
    for (int dt = 0; dt < 2; ++dt)
#pragma unroll
        for (int c = 0; c < 4; ++c) { accE[dt][c] = 0.f; accD[dt][c] = 0.f; }
    float seR0 = 0.f, seR1 = 0.f, dpR0 = 0.f, dpR1 = 0.f;

    // ---- streaming neighbor loop ----
#pragma unroll 1
    for (int nw = 0; nw < 3; ++nw) {
        int nb = blk - 1 + nw;
        if (nb < 0 || nb >= NB) continue;
        __syncthreads();   // previous iteration's MMA reads done before overwrite
        size_t kb = (size_t)(bh*32 + nb);
        const float* kt = g_kT + kb*4096;
        for (int i = tid; i < 4096; i += 512) {
            int e = i >> 6, c = i & 63;
            float x = kt[i];
            float hi = tf32_rna(x);
            sKTb[e*SP + c] = hi;
            sKTs[e*SP + c] = x - hi;
        }
        const float4* kp = (const float4*)(g_kp + kb*16384);
        for (int i = tid; i < 4096; i += 512) {
            float4 v4 = kp[i];
            int m = i >> 4, c4 = (i & 15)*4;
            *(float4*)(sKP + m*SP + c4) = v4;
        }
        __syncthreads();

        float Cqk[2][4], Cdp[2][4];
#pragma unroll
        for (int jt = 0; jt < 2; ++jt)
#pragma unroll
            for (int c = 0; c < 4; ++c) { Cqk[jt][c] = 0.f; Cdp[jt][c] = 0.f; }

        // QK: K=64, split hi/lo (3 MMAs)
#pragma unroll
        for (int kc = 0; kc < 8; ++kc) {
            int k0 = kc*8;
            float ab0 = sQTb[(k0+t)*SP + i0+g],   ab1 = sQTb[(k0+t)*SP + i0+g+8];
            float ab2 = sQTb[(k0+t+4)*SP + i0+g], ab3 = sQTb[(k0+t+4)*SP + i0+g+8];
            float as0 = sQTs[(k0+t)*SP + i0+g],   as1 = sQTs[(k0+t)*SP + i0+g+8];
            float as2 = sQTs[(k0+t+4)*SP + i0+g], as3 = sQTs[(k0+t+4)*SP + i0+g+8];
#pragma unroll
            for (int jt = 0; jt < 2; ++jt) {
                int j = jh*16 + jt*8 + g;
                float bb0 = sKTb[(k0+t)*SP + j], bb1 = sKTb[(k0+t+4)*SP + j];
                float bs0 = sKTs[(k0+t)*SP + j], bs1 = sKTs[(k0+t+4)*SP + j];
                mma_tf32(Cqk[jt], ab0,ab1,ab2,ab3, bb0,bb1);
                mma_tf32(Cqk[jt], ab0,ab1,ab2,ab3, bs0,bs1);
                mma_tf32(Cqk[jt], as0,as1,as2,as3, bb0,bb1);
            }
        }
        // dots_prime: K=256
#pragma unroll 4
        for (int kc = 0; kc < 32; ++kc) {
            int k0 = kc*8;
            float a0 = sQP[(k0+t)*SP + i0+g],   a1 = sQP[(k0+t)*SP + i0+g+8];
            float a2 = sQP[(k0+t+4)*SP + i0+g], a3 = sQP[(k0+t+4)*SP + i0+g+8];
#pragma unroll
            for (int jt = 0; jt < 2; ++jt) {
                int j = jh*16 + jt*8 + g;
                float b0 = sKP[(k0+t)*SP + j], b1 = sKP[(k0+t+4)*SP + j];
                mma_tf32(Cdp[jt], a0,a1,a2,a3, b0,b1);
            }
        }
        __syncthreads();   // all warps done reading sKTb/sKTs/sKP

        // exp frags + running row sums; write E and dp tiles [j][i]
#pragma unroll
        for (int jt = 0; jt < 2; ++jt) {
            int j = jh*16 + jt*8 + 2*t;
            float e00 = __expf(Cqk[jt][0]);
            float e01 = __expf(Cqk[jt][1]);
            float e10 = __expf(Cqk[jt][2]);
            float e11 = __expf(Cqk[jt][3]);
            seR0 += e00 + e01;  seR1 += e10 + e11;
            dpR0 += Cdp[jt][0] + Cdp[jt][1];
            dpR1 += Cdp[jt][2] + Cdp[jt][3];
            sE[(size_t)j*SP + r0]     = tf32_rna(e00);
            sE[(size_t)(j+1)*SP + r0] = tf32_rna(e01);
            sE[(size_t)j*SP + r1]     = tf32_rna(e10);
            sE[(size_t)(j+1)*SP + r1] = tf32_rna(e11);
            sDPm[(size_t)j*SP + r0]     = tf32_rna(Cdp[jt][0]);
            sDPm[(size_t)(j+1)*SP + r0] = tf32_rna(Cdp[jt][1]);
            sDPm[(size_t)j*SP + r1]     = tf32_rna(Cdp[jt][2]);
            sDPm[(size_t)(j+1)*SP + r1] = tf32_rna(Cdp[jt][3]);
        }
        // v tile
        const float* vb = value + ((size_t)(b*Tq + nb*64)*Hq + h)*Eq;
        for (int i = tid; i < 1024; i += 512) {
            int j = i >> 4, d4 = (i & 15)*4;
            float4 v4 = *(const float4*)(vb + (size_t)j*ROWSTRIDE + d4);
            v4.x = tf32_rna(v4.x); v4.y = tf32_rna(v4.y);
            v4.z = tf32_rna(v4.z); v4.w = tf32_rna(v4.w);
            *(float4*)(sV + j*SP + d4) = v4;
        }
        __syncthreads();

        // accE += E . V ; accD += dp . V   (K = 64 over j)
#pragma unroll
        for (int kc = 0; kc < 8; ++kc) {
            int k0 = kc*8;
            float aE0 = sE[(k0+t)*SP + i0+g],   aE1 = sE[(k0+t)*SP + i0+g+8];
            float aE2 = sE[(k0+t+4)*SP + i0+g], aE3 = sE[(k0+t+4)*SP + i0+g+8];
            float aD0 = sDPm[(k0+t)*SP + i0+g],   aD1 = sDPm[(k0+t)*SP + i0+g+8];
            float aD2 = sDPm[(k0+t+4)*SP + i0+g], aD3 = sDPm[(k0+t+4)*SP + i0+g+8];
#pragma unroll
            for (int dt = 0; dt < 2; ++dt) {
                int d = jh*16 + dt*8 + g;
                float b0 = sV[(k0+t)*SP + d], b1 = sV[(k0+t+4)*SP + d];
                mma_tf32(accE[dt], aE0,aE1,aE2,aE3, b0,b1);
                mma_tf32(accD[dt], aD0,aD1,aD2,aD3, b0,b1);
            }
        }
    }

    // ---- stats reduce ----
    seR0 += __shfl_xor_sync(0xffffffffu, seR0, 1);
    seR0 += __shfl_xor_sync(0xffffffffu, seR0, 2);
    seR1 += __shfl_xor_sync(0xffffffffu, seR1, 1);
    seR1 += __shfl_xor_sync(0xffffffffu, seR1, 2);
    dpR0 += __shfl_xor_sync(0xffffffffu, dpR0, 1);
    dpR0 += __shfl_xor_sync(0xffffffffu, dpR0, 2);
    dpR1 += __shfl_xor_sync(0xffffffffu, dpR1, 1);
    dpR1 += __shfl_xor_sync(0xffffffffu, dpR1, 2);
    __syncthreads();   // prior MMA reads of sV complete before any reuse; also orders stats writes
    if (t == 0) {
        sSe[jh*64 + r0] = seR0; sSe[jh*64 + r1] = seR1;
        sDp[jh*64 + r0] = dpR0; sDp[jh*64 + r1] = dpR1;
    }
    // qp_kp_1 partials
    {
        int ii = tid & 63, part = tid >> 6;   // 8 parts x 32 m
        float s = 0.f;
#pragma unroll 8
        for (int mm = 0; mm < 32; ++mm) {
            int m = part*32 + mm;
            s += sQP[m*SP + ii] * sKps[m];
        }
        sQpk[part*64 + ii] = s;
    }
    __syncthreads();
    if (tid < 64) {
        float qpk1 = 0.f;
#pragma unroll
        for (int p = 0; p < 8; ++p) qpk1 += sQpk[p*64 + tid];
        float se = sSe[tid] + sSe[64+tid] + sSe[128+tid] + sSe[192+tid];
        float dp = sDp[tid] + sDp[64+tid] + sDp[128+tid] + sDp[192+tid];
        float lse = __logf(se);                      // no max needed: QK small
        float pls = sQls[tid] - HALF_LOG_M;          // k_log_scale = -half_log_m (s_k = 0)
        float lr  = __logf(fmaxf(qpk1 - dp, 1e-24f)) + pls;
        float mxv = fmaxf(lse, lr);
        float ln  = mxv + log1pf(__expf(-fabsf(lse - lr)));
        sLn[tid] = ln;
        sPs[tid] = __expf(pls - ln);
    }
    __syncthreads();
    float iE0 = __expf(-sLn[r0]), iE1 = __expf(-sLn[r1]);
    float ps0 = sPs[r0], ps1 = sPs[r1];

    // ---- C2 = q' . kv ----
    {
        const float4* kvsrc = (const float4*)(g_kv + (size_t)bh*16384);
        for (int i = tid; i < 4096; i += 512) {
            float4 v4 = kvsrc[i];
            v4.x = tf32_rna(v4.x); v4.y = tf32_rna(v4.y);
            v4.z = tf32_rna(v4.z); v4.w = tf32_rna(v4.w);
            int m = i >> 4, d4 = (i & 15)*4;
            *(float4*)(sKV + m*SP + d4) = v4;
        }
    }
    __syncthreads();
    float C2[2][4];
#pragma unroll
    for (int dt = 0; dt < 2; ++dt)
#pragma unroll
        for (int c = 0; c < 4; ++c) C2[dt][c] = 0.f;
#pragma unroll 4
    for (int kc = 0; kc < 32; ++kc) {
        int k0 = kc*8;
        float a0 = sQP[(k0+t)*SP + i0+g],   a1 = sQP[(k0+t)*SP + i0+g+8];
        float a2 = sQP[(k0+t+4)*SP + i0+g], a3 = sQP[(k0+t+4)*SP + i0+g+8];
#pragma unroll
        for (int dt = 0; dt < 2; ++dt) {
            int d = jh*16 + dt*8 + g;
            float b0 = sKV[(k0+t)*SP + d], b1 = sKV[(k0+t+4)*SP + d];
            mma_tf32(C2[dt], a0,a1,a2,a3, b0,b1);
        }
    }

    // ---- epilogue: out = accE*exp(-ln) + (C2 - accD)*ps ----
    float* ob = out + ((size_t)(b*Tq + t0)*Hq + h)*Eq;
#pragma unroll
    for (int dt = 0; dt < 2; ++dt) {
        int d = jh*16 + dt*8 + 2*t;
        float2 o0, o1;
        o0.x = accE[dt][0]*iE0 + (C2[dt][0] - accD[dt][0])*ps0;
        o0.y = accE[dt][1]*iE0 + (C2[dt][1] - accD[dt][1])*ps0;
        o1.x = accE[dt][2]*iE1 + (C2[dt][2] - accD[dt][2])*ps1;
        o1.y = accE[dt][3]*iE1 + (C2[dt][3] - accD[dt][3])*ps1;
        *(float2*)(ob + (size_t)r0*ROWSTRIDE + d) = o0;
        *(float2*)(ob + (size_t)r1*ROWSTRIDE + d) = o1;
    }
}

// ---------------- launch ----------------
extern "C" void kernel_launch(void* const* d_in, const int* in_sizes, int n_in,
                              void* d_out, int out_size) {
    const float* query = (const float*)d_in[0];
    const float* key   = (const float*)d_in[1];
    const float* value = (const float*)d_in[2];
    const float* proj  = (const float*)d_in[3];
    float* out = (float*)d_out;

    const int SM_SIDES = 18624 * 4;                      // 74496
    const int SM_K2    = 26624 * 4;                      // 106496
    const int SM_MAIN  = SM_MAIN_FLOATS * 4;             // 227072

    cudaFuncSetAttribute(sides_kernel, cudaFuncAttributeMaxDynamicSharedMemorySize, SM_SIDES);
    cudaFuncSetAttribute(k2_kernel,    cudaFuncAttributeMaxDynamicSharedMemorySize, SM_K2);
    cudaFuncSetAttribute(main_kernel,  cudaFuncAttributeMaxDynamicSharedMemorySize, SM_MAIN);

    sides_kernel<<<dim3(BH*NB, 2), 256, SM_SIDES>>>(key, query, proj);
    k2_kernel<<<BH*NB, 256, SM_K2>>>(value);
    reduce_kernel<<<(BH*Mq*Eq + 255)/256, 256>>>();
    main_kernel<<<BH*NB, 512, SM_MAIN>>>(value, out);
}

// round 7
// speedup vs baseline: 1.8492x; 1.2187x over previous
#include <cuda_runtime.h>
#include <cuda_bf16.h>
#include <math.h>
#include <stdint.h>

#define Bq 2
#define Tq 2048
#define Hq 12
#define Eq 64
#define Mq 256
#define NB 32            // T / 64
#define BH 24            // B*H
#define ROWSTRIDE (Hq*Eq)  // 768 floats between consecutive t
#define SPC 68           // f32 padded stride (scalar tf32 fragment loads)
#define SPK 68           // stride for [m][j] k' staging in k2
#define SP  72           // f32 stride used by k2 V staging

#define TEMP 0.125f                     // 1/sqrt(E)
#define DN 0.35355339059327379f         // sqrt(temp)
#define HALF_LOG_M 2.7725887222397811f  // 0.5*log(256)
#define NEG_INF __int_as_float(0xff800000)

// ---------------- device scratch ----------------
__device__ uint32_t g_qbf[BH*NB*4096];           // per block: raw q bf16 planes [row][e]: hi 2048 u32, lo 2048
__device__ uint32_t g_kbf[BH*NB*4096];           // per block: raw k bf16 planes
__device__ float g_kp  [BH*NB*Mq*64];            // per block: [m][j]; k_prime (s_k=0, tf32)
__device__ float g_qpT [BH*NB*Mq*64];            // per block: [m][i]; q_prime (tf32)
__device__ float g_qls [BH*Tq];                  // q_log_scale
__device__ float g_kv  [BH*Mq*Eq];               // [m][d]
__device__ float g_kps [BH*Mq];
__device__ float g_kvpart [BH*32*Mq*Eq];
__device__ float g_kpspart[BH*32*Mq];

// ---------------- helpers ----------------
__device__ __forceinline__ float tf32_rna(float x) {
    uint32_t r;
    asm("cvt.rna.tf32.f32 %0, %1;" : "=r"(r) : "f"(x));
    return __uint_as_float(r);
}

__device__ __forceinline__ void mma_tf32(float c[4],
        float a0, float a1, float a2, float a3, float b0, float b1)
{
    asm volatile(
        "mma.sync.aligned.m16n8k8.row.col.f32.tf32.tf32.f32 "
        "{%0,%1,%2,%3}, {%4,%5,%6,%7}, {%8,%9}, {%0,%1,%2,%3};\n"
        : "+f"(c[0]), "+f"(c[1]), "+f"(c[2]), "+f"(c[3])
        : "r"(__float_as_uint(a0)), "r"(__float_as_uint(a1)),
          "r"(__float_as_uint(a2)), "r"(__float_as_uint(a3)),
          "r"(__float_as_uint(b0)), "r"(__float_as_uint(b1)));
}

__device__ __forceinline__ void mma_bf16(float c[4],
        uint32_t a0, uint32_t a1, uint32_t a2, uint32_t a3, uint32_t b0, uint32_t b1)
{
    asm volatile(
        "mma.sync.aligned.m16n8k16.row.col.f32.bf16.bf16.f32 "
        "{%0,%1,%2,%3}, {%4,%5,%6,%7}, {%8,%9}, {%0,%1,%2,%3};\n"
        : "+f"(c[0]), "+f"(c[1]), "+f"(c[2]), "+f"(c[3])
        : "r"(a0), "r"(a1), "r"(a2), "r"(a3), "r"(b0), "r"(b1));
}

// split two floats into packed bf16 hi/lo pairs
__device__ __forceinline__ void split2_bf16(float x, float y, uint32_t &hi, uint32_t &lo) {
    __nv_bfloat16 hx = __float2bfloat16(x);
    __nv_bfloat16 hy = __float2bfloat16(y);
    __nv_bfloat16 lx = __float2bfloat16(x - __bfloat162float(hx));
    __nv_bfloat16 ly = __float2bfloat16(y - __bfloat162float(hy));
    hi = ((uint32_t)__bfloat16_as_ushort(hy) << 16) | (uint32_t)__bfloat16_as_ushort(hx);
    lo = ((uint32_t)__bfloat16_as_ushort(ly) << 16) | (uint32_t)__bfloat16_as_ushort(lx);
}

__device__ __forceinline__ float bf16lo_f(uint32_t u) {
    __nv_bfloat16 b = __ushort_as_bfloat16((unsigned short)(u & 0xffffu));
    return __bfloat162float(b);
}
__device__ __forceinline__ float bf16hi_f(uint32_t u) {
    __nv_bfloat16 b = __ushort_as_bfloat16((unsigned short)(u >> 16));
    return __bfloat162float(b);
}

// ---------------- kernel 1: sides — bf16 feature GEMMs ----------------
// grid (768, 2): y=0 -> k side, y=1 -> q side. 256 threads, 2 CTAs/SM.
// smem: uT planes 4608 f, uP planes 4608 f, diag 64, max 128 -> 9408 f = 37632 B
__global__ __launch_bounds__(256,2) void sides_kernel(const float* __restrict__ key,
                                                      const float* __restrict__ query,
                                                      const float* __restrict__ proj) {
    extern __shared__ float sm[];
    uint32_t* uT = (uint32_t*)sm;            // tile planes: hi [0..2303], lo [2304..4607] (u32)
    uint32_t* uP = (uint32_t*)(sm + 4608);   // proj chunk planes
    float* sDiag = sm + 9216;                // 64
    float* sMax  = sm + 9280;                // 128

    int tid = threadIdx.x;
    int lane = tid & 31, wid = tid >> 5;
    int g = lane >> 2, t = lane & 3;
    int rt = wid & 3;             // row tile of 16
    int mh = wid >> 2;            // feature half (0/1) within 64-chunk
    int r0 = rt*16 + g, r1 = r0 + 8;
    int bidx = blockIdx.x, blk = bidx & 31, bh = bidx >> 5;
    int b = bh / Hq, h = bh % Hq;
    int t0 = blk * 64;
    int qside = blockIdx.y;

    // stage raw tile as bf16 planes [row][e] (stride 72 halfs = 36 u32); also write global planes
    const float* src = (qside ? query : key) + ((size_t)(b*Tq + t0)*Hq + h)*Eq;
    uint32_t* gdst = (qside ? g_qbf : g_kbf) + (size_t)bidx * 4096;
    for (int i = tid; i < 2048; i += 256) {
        int row = i >> 5, eh = i & 31;
        float2 v = *(const float2*)(src + (size_t)row*ROWSTRIDE + eh*2);
        uint32_t hi, lo;
        split2_bf16(v.x, v.y, hi, lo);
        uT[row*36 + eh] = hi;
        uT[2304 + row*36 + eh] = lo;
        gdst[row*32 + eh] = hi;
        gdst[2048 + row*32 + eh] = lo;
    }
    __syncthreads();
    if (tid < 64) {
        float s = 0.f;
#pragma unroll
        for (int eh = 0; eh < 32; ++eh) {
            uint32_t hu = uT[tid*36 + eh], lu = uT[2304 + tid*36 + eh];
            float x0 = bf16lo_f(hu) + bf16lo_f(lu);
            float x1 = bf16hi_f(hu) + bf16hi_f(lu);
            s += x0*x0 + x1*x1;
        }
        sDiag[tid] = 0.0625f * s;   // 0.5 * temp * sum(x^2)
    }

    float C[4][4][4];
#pragma unroll
    for (int c = 0; c < 4; ++c)
#pragma unroll
        for (int mt = 0; mt < 4; ++mt)
#pragma unroll
            for (int k = 0; k < 4; ++k) C[c][mt][k] = 0.f;

    // 4 chunks of 64 feature columns; proj [m][e] split inline (DN folded)
#pragma unroll 1
    for (int c = 0; c < 4; ++c) {
        __syncthreads();
        for (int i = tid; i < 2048; i += 256) {
            int mm = i >> 5, eh = i & 31;
            float2 v = *(const float2*)(proj + (size_t)(c*64 + mm)*64 + eh*2);
            uint32_t hi, lo;
            split2_bf16(v.x * DN, v.y * DN, hi, lo);
            uP[mm*36 + eh] = hi;
            uP[2304 + mm*36 + eh] = lo;
        }
        __syncthreads();
#pragma unroll
        for (int kc = 0; kc < 4; ++kc) {
            int k8 = kc*8;
            uint32_t ah0 = uT[r0*36 + k8 + t],     ah1 = uT[r1*36 + k8 + t];
            uint32_t ah2 = uT[r0*36 + k8 + t + 4], ah3 = uT[r1*36 + k8 + t + 4];
            uint32_t al0 = uT[2304 + r0*36 + k8 + t],     al1 = uT[2304 + r1*36 + k8 + t];
            uint32_t al2 = uT[2304 + r0*36 + k8 + t + 4], al3 = uT[2304 + r1*36 + k8 + t + 4];
#pragma unroll
            for (int mt = 0; mt < 4; ++mt) {
                int mc = mh*32 + mt*8 + g;
                uint32_t bh0 = uP[mc*36 + k8 + t],        bh1 = uP[mc*36 + k8 + t + 4];
                uint32_t bl0 = uP[2304 + mc*36 + k8 + t], bl1 = uP[2304 + mc*36 + k8 + t + 4];
                mma_bf16(C[c][mt], ah0,ah1,ah2,ah3, bh0,bh1);
                mma_bf16(C[c][mt], ah0,ah1,ah2,ah3, bl0,bl1);
                mma_bf16(C[c][mt], al0,al1,al2,al3, bh0,bh1);
            }
        }
    }

    if (!qside) {
        float dg0 = sDiag[r0], dg1 = sDiag[r1];
        float* kp = g_kp + (size_t)bidx * 16384;
#pragma unroll
        for (int c = 0; c < 4; ++c)
#pragma unroll
            for (int mt = 0; mt < 4; ++mt) {
                int m0 = c*64 + mh*32 + mt*8 + 2*t;
                kp[(size_t)m0*64 + r0]     = tf32_rna(__expf(C[c][mt][0] - dg0));
                kp[(size_t)(m0+1)*64 + r0] = tf32_rna(__expf(C[c][mt][1] - dg0));
                kp[(size_t)m0*64 + r1]     = tf32_rna(__expf(C[c][mt][2] - dg1));
                kp[(size_t)(m0+1)*64 + r1] = tf32_rna(__expf(C[c][mt][3] - dg1));
            }
    } else {
        float mx0 = NEG_INF, mx1 = NEG_INF;
#pragma unroll
        for (int c = 0; c < 4; ++c)
#pragma unroll
            for (int mt = 0; mt < 4; ++mt) {
                mx0 = fmaxf(mx0, fmaxf(C[c][mt][0], C[c][mt][1]));
                mx1 = fmaxf(mx1, fmaxf(C[c][mt][2], C[c][mt][3]));
            }
        mx0 = fmaxf(mx0, __shfl_xor_sync(0xffffffffu, mx0, 1));
        mx0 = fmaxf(mx0, __shfl_xor_sync(0xffffffffu, mx0, 2));
        mx1 = fmaxf(mx1, __shfl_xor_sync(0xffffffffu, mx1, 1));
        mx1 = fmaxf(mx1, __shfl_xor_sync(0xffffffffu, mx1, 2));
        if (t == 0) { sMax[mh*64 + r0] = mx0; sMax[mh*64 + r1] = mx1; }
        __syncthreads();
        float rm0 = fmaxf(sMax[r0], sMax[64 + r0]);
        float rm1 = fmaxf(sMax[r1], sMax[64 + r1]);
        float* qp = g_qpT + (size_t)bidx * 16384;
#pragma unroll
        for (int c = 0; c < 4; ++c)
#pragma unroll
            for (int mt = 0; mt < 4; ++mt) {
                int m0 = c*64 + mh*32 + mt*8 + 2*t;
                qp[(size_t)m0*64 + r0]     = tf32_rna(__expf(C[c][mt][0] - rm0));
                qp[(size_t)(m0+1)*64 + r0] = tf32_rna(__expf(C[c][mt][1] - rm0));
                qp[(size_t)m0*64 + r1]     = tf32_rna(__expf(C[c][mt][2] - rm1));
                qp[(size_t)(m0+1)*64 + r1] = tf32_rna(__expf(C[c][mt][3] - rm1));
            }
        if (mh == 0 && t == 0) {
            g_qls[bh*Tq + t0 + r0] = rm0 - sDiag[r0] - HALF_LOG_M;
            g_qls[bh*Tq + t0 + r1] = rm1 - sDiag[r1] - HALF_LOG_M;
        }
    }
}

// ---------------- kernel 2: kv / kps partials via tf32 MMA (unchanged) ----------------
__global__ __launch_bounds__(256,2) void k2_kernel(const float* __restrict__ value) {
    extern __shared__ float sm[];
    float* sKp = sm;              // [m][j] stride 68 : 17408
    float* sVh = sm + 17408;      // [j][d] stride 72 hi : 4608
    float* sVl = sm + 22016;      // lo : 4608
    int tid = threadIdx.x;
    int lane = tid & 31, wid = tid >> 5;
    int g = lane >> 2, t = lane & 3;
    int bh = blockIdx.x >> 5, sblk = blockIdx.x & 31;
    int b = bh / Hq, h = bh % Hq;

    const float4* kp = (const float4*)(g_kp + (size_t)blockIdx.x * 16384);
    for (int i = tid; i < 4096; i += 256) {
        int m = i >> 4, j4 = (i & 15)*4;
        *(float4*)(sKp + m*SPK + j4) = kp[i];
    }
    const float* vb = value + ((size_t)(b*Tq + sblk*64)*Hq + h)*Eq;
    for (int i = tid; i < 1024; i += 256) {
        int j = i >> 4, d4 = (i & 15)*4;
        float4 v4 = *(const float4*)(vb + (size_t)j*ROWSTRIDE + d4);
        float4 hi, lo;
        hi.x = tf32_rna(v4.x); lo.x = v4.x - hi.x;
        hi.y = tf32_rna(v4.y); lo.y = v4.y - hi.y;
        hi.z = tf32_rna(v4.z); lo.z = v4.z - hi.z;
        hi.w = tf32_rna(v4.w); lo.w = v4.w - hi.w;
        *(float4*)(sVh + j*SP + d4) = hi;
        *(float4*)(sVl + j*SP + d4) = lo;
    }
    __syncthreads();

    {
        float s = 0.f;
#pragma unroll
        for (int j4 = 0; j4 < 64; j4 += 4) {
            float4 k4 = *(const float4*)(sKp + tid*SPK + j4);
            s += k4.x + k4.y + k4.z + k4.w;
        }
        g_kpspart[(size_t)blockIdx.x*256 + tid] = s;
    }

    float C[2][8][4];
#pragma unroll
    for (int it = 0; it < 2; ++it)
#pragma unroll
        for (int nt = 0; nt < 8; ++nt)
#pragma unroll
            for (int k = 0; k < 4; ++k) C[it][nt][k] = 0.f;

#pragma unroll
    for (int kc = 0; kc < 8; ++kc) {
        int k0 = kc*8;
        float a[2][4];
#pragma unroll
        for (int it = 0; it < 2; ++it) {
            int r = wid*32 + it*16 + g;
            a[it][0] = sKp[(size_t)r*SPK + k0 + t];
            a[it][1] = sKp[(size_t)(r+8)*SPK + k0 + t];
            a[it][2] = sKp[(size_t)r*SPK + k0 + t + 4];
            a[it][3] = sKp[(size_t)(r+8)*SPK + k0 + t + 4];
        }
#pragma unroll
        for (int nt = 0; nt < 8; ++nt) {
            int d = nt*8 + g;
            float bh0 = sVh[(k0+t)*SP + d], bh1 = sVh[(k0+t+4)*SP + d];
            float bl0 = sVl[(k0+t)*SP + d], bl1 = sVl[(k0+t+4)*SP + d];
#pragma unroll
            for (int it = 0; it < 2; ++it) {
                mma_tf32(C[it][nt], a[it][0],a[it][1],a[it][2],a[it][3], bh0,bh1);
                mma_tf32(C[it][nt], a[it][0],a[it][1],a[it][2],a[it][3], bl0,bl1);
            }
        }
    }

    float* kvp = g_kvpart + (size_t)blockIdx.x * 16384;
#pragma unroll
    for (int it = 0; it < 2; ++it) {
        int m0 = wid*32 + it*16 + g;
#pragma unroll
        for (int nt = 0; nt < 8; ++nt) {
            int d = nt*8 + 2*t;
            *(float2*)(kvp + (size_t)m0*64 + d)     = make_float2(C[it][nt][0], C[it][nt][1]);
            *(float2*)(kvp + (size_t)(m0+8)*64 + d) = make_float2(C[it][nt][2], C[it][nt][3]);
        }
    }
}

// ---------------- kernel 2b: reduce partials ----------------
__global__ void reduce_kernel() {
    int idx = blockIdx.x*256 + threadIdx.x;
    if (idx < BH*Mq*Eq) {
        int bh = idx >> 14;
        int rem = idx & 16383;
        float s = 0.f;
#pragma unroll
        for (int p = 0; p < 32; ++p) s += g_kvpart[(size_t)(bh*32 + p)*16384 + rem];
        g_kv[idx] = s;
    }
    if (idx < BH*Mq) {
        int bh = idx >> 8; int m = idx & 255;
        float s = 0.f;
#pragma unroll
        for (int p = 0; p < 32; ++p) s += g_kpspart[(bh*32 + p)*256 + m];
        g_kps[idx] = s;
    }
}

// ---------------- kernel 4: main — low-smem streaming, 2 CTAs/SM ----------------
// float offsets
#define O_QT  0        // 4608 : q bf16 planes [i][e] (hi 2304 u32, lo 2304 u32)
#define O_KT  4608     // 4608 : k bf16 planes        | alias sE [j][i] s68
#define O_QPC 9216     // 4352 : q' m-chunk [m64][i] s68 | alias sDP [j][i]
#define O_KPC 13568    // 4352 : k' m-chunk [m64][j] s68 | alias sV [j][d] / sKVc [m64][d]
#define O_KPS 17920    // 256
#define O_QLS 18176    // 64
#define O_SSE 18240    // 256
#define O_SDP 18496    // 256
#define O_QPK 18752    // 512
#define O_LN  19264    // 64
#define O_PS  19328    // 64
#define SM_MAIN_FLOATS 19392

__global__ __launch_bounds__(512,2) void main_kernel(const float* __restrict__ value,
                                                     float* __restrict__ out) {
    extern __shared__ float smm[];
    uint32_t* uQT = (uint32_t*)(smm + O_QT);   // hi [0..2303], lo [2304..4607]
    uint32_t* uKT = (uint32_t*)(smm + O_KT);
    float* sE   = smm + O_KT;    // alias
    float* sQPC = smm + O_QPC;
    float* sDP  = smm + O_QPC;   // alias
    float* sKPC = smm + O_KPC;
    float* sV   = smm + O_KPC;   // alias
    float* sKVc = smm + O_KPC;   // alias
    float* sKps = smm + O_KPS;
    float* sQls = smm + O_QLS;
    float* sSe  = smm + O_SSE;
    float* sDp  = smm + O_SDP;
    float* sQpk = smm + O_QPK;
    float* sLn  = smm + O_LN;
    float* sPs  = smm + O_PS;

    int tid = threadIdx.x;
    int lane = tid & 31, wid = tid >> 5;
    int g = lane >> 2, t = lane & 3;
    int iw = wid & 3, jh = wid >> 2;        // 4(i) x 4(j) warp grid
    int i0 = iw * 16;
    int bidx = blockIdx.x, blk = bidx & 31, bh = bidx >> 5;
    int b = bh / Hq, h = bh % Hq;
    int t0 = blk * 64;
    int r0 = i0 + g, r1 = r0 + 8;

    // ---- phase 0 ----
    {
        const uint32_t* gq = g_qbf + (size_t)bidx*4096;
        for (int i = tid; i < 2048; i += 512) {
            int row = i >> 5, eh = i & 31;
            uQT[row*36 + eh]        = gq[i];
            uQT[2304 + row*36 + eh] = gq[2048 + i];
        }
        if (tid < 256) sKps[tid] = g_kps[bh*Mq + tid];
        if (tid < 64)  sQls[tid] = g_qls[bh*Tq + t0 + tid];
    }

    float accE[2][4], accD[2][4];
#pragma unroll
    for (int dt = 0; dt < 2; ++dt)
#pragma unroll
        for (int c = 0; c < 4; ++c) { accE[dt][c] = 0.f; accD[dt][c] = 0.f; }
    float seR0 = 0.f, seR1 = 0.f, dpR0 = 0.f, dpR1 = 0.f;

    // ---- neighbor loop ----
#pragma unroll 1
    for (int nw = 0; nw < 3; ++nw) {
        int nb = blk - 1 + nw;
        if (nb < 0 || nb >= NB) continue;
        size_t kb = (size_t)(bh*32 + nb);
        __syncthreads();   // S0: prior readers of KT/QPC/KPC done
        {
            const uint32_t* gk = g_kbf + kb*4096;
            for (int i = tid; i < 2048; i += 512) {
                int row = i >> 5, eh = i & 31;
                uKT[row*36 + eh]        = gk[i];
                uKT[2304 + row*36 + eh] = gk[2048 + i];
            }
            const float4* qp = (const float4*)(g_qpT + bidx*(size_t)16384);
            const float4* kp = (const float4*)(g_kp + kb*16384);
            for (int i = tid; i < 1024; i += 512) {
                int m = i >> 4, c4 = (i & 15)*4;
                *(float4*)(sQPC + m*SPC + c4) = qp[i];
                *(float4*)(sKPC + m*SPC + c4) = kp[i];
            }
        }
        __syncthreads();   // S1

        float Cqk[2][4], Cdp[2][4];
#pragma unroll
        for (int jt = 0; jt < 2; ++jt)
#pragma unroll
            for (int c = 0; c < 4; ++c) { Cqk[jt][c] = 0.f; Cdp[jt][c] = 0.f; }

        // QK: bf16 3-term, k=64 -> 4 chunks of k16
#pragma unroll
        for (int kc = 0; kc < 4; ++kc) {
            int k8 = kc*8;
            uint32_t ah0 = uQT[r0*36 + k8 + t],     ah1 = uQT[r1*36 + k8 + t];
            uint32_t ah2 = uQT[r0*36 + k8 + t + 4], ah3 = uQT[r1*36 + k8 + t + 4];
            uint32_t al0 = uQT[2304 + r0*36 + k8 + t],     al1 = uQT[2304 + r1*36 + k8 + t];
            uint32_t al2 = uQT[2304 + r0*36 + k8 + t + 4], al3 = uQT[2304 + r1*36 + k8 + t + 4];
#pragma unroll
            for (int jt = 0; jt < 2; ++jt) {
                int j = jh*16 + jt*8 + g;
                uint32_t bh0 = uKT[j*36 + k8 + t],        bh1 = uKT[j*36 + k8 + t + 4];
                uint32_t bl0 = uKT[2304 + j*36 + k8 + t], bl1 = uKT[2304 + j*36 + k8 + t + 4];
                mma_bf16(Cqk[jt], ah0,ah1,ah2,ah3, bh0,bh1);
                mma_bf16(Cqk[jt], ah0,ah1,ah2,ah3, bl0,bl1);
                mma_bf16(Cqk[jt], al0,al1,al2,al3, bh0,bh1);
            }
        }
        // dp chunk 0 + streamed chunks 1..3
#pragma unroll 1
        for (int mc = 0; mc < 4; ++mc) {
            if (mc > 0) {
                __syncthreads();
                const float4* qp = (const float4*)(g_qpT + bidx*(size_t)16384 + mc*4096);
                const float4* kp = (const float4*)(g_kp + kb*16384 + mc*4096);
                for (int i = tid; i < 1024; i += 512) {
                    int m = i >> 4, c4 = (i & 15)*4;
                    *(float4*)(sQPC + m*SPC + c4) = qp[i];
                    *(float4*)(sKPC + m*SPC + c4) = kp[i];
                }
                __syncthreads();
            }
#pragma unroll
            for (int kc = 0; kc < 8; ++kc) {
                int k0 = kc*8;
                float a0 = sQPC[(k0+t)*SPC + i0+g],   a1 = sQPC[(k0+t)*SPC + i0+g+8];
                float a2 = sQPC[(k0+t+4)*SPC + i0+g], a3 = sQPC[(k0+t+4)*SPC + i0+g+8];
#pragma unroll
                for (int jt = 0; jt < 2; ++jt) {
                    int j = jh*16 + jt*8 + g;
                    float b0 = sKPC[(k0+t)*SPC + j], b1 = sKPC[(k0+t+4)*SPC + j];
                    mma_tf32(Cdp[jt], a0,a1,a2,a3, b0,b1);
                }
            }
        }
        __syncthreads();   // dp reads done; KT dead (QK done) -> write E/DP, load V

#pragma unroll
        for (int jt = 0; jt < 2; ++jt) {
            int j = jh*16 + jt*8 + 2*t;
            float e00 = __expf(TEMP*Cqk[jt][0]);
            float e01 = __expf(TEMP*Cqk[jt][1]);
            float e10 = __expf(TEMP*Cqk[jt][2]);
            float e11 = __expf(TEMP*Cqk[jt][3]);
            seR0 += e00 + e01;  seR1 += e10 + e11;
            dpR0 += Cdp[jt][0] + Cdp[jt][1];
            dpR1 += Cdp[jt][2] + Cdp[jt][3];
            sE[j*SPC + r0]     = tf32_rna(e00);
            sE[(j+1)*SPC + r0] = tf32_rna(e01);
            sE[j*SPC + r1]     = tf32_rna(e10);
            sE[(j+1)*SPC + r1] = tf32_rna(e11);
            sDP[j*SPC + r0]     = tf32_rna(Cdp[jt][0]);
            sDP[(j+1)*SPC + r0] = tf32_rna(Cdp[jt][1]);
            sDP[j*SPC + r1]     = tf32_rna(Cdp[jt][2]);
            sDP[(j+1)*SPC + r1] = tf32_rna(Cdp[jt][3]);
        }
        {
            const float* vb = value + ((size_t)(b*Tq + nb*64)*Hq + h)*Eq;
            for (int i = tid; i < 1024; i += 512) {
                int j = i >> 4, d4 = (i & 15)*4;
                float4 v4 = *(const float4*)(vb + (size_t)j*ROWSTRIDE + d4);
                v4.x = tf32_rna(v4.x); v4.y = tf32_rna(v4.y);
                v4.z = tf32_rna(v4.z); v4.w = tf32_rna(v4.w);
                *(float4*)(sV + j*SPC + d4) = v4;
            }
        }
        __syncthreads();

        // accE += E.V ; accD += DP.V
#pragma unroll
        for (int kc = 0; kc < 8; ++kc) {
            int k0 = kc*8;
            float aE0 = sE[(k0+t)*SPC + i0+g],   aE1 = sE[(k0+t)*SPC + i0+g+8];
            float aE2 = sE[(k0+t+4)*SPC + i0+g], aE3 = sE[(k0+t+4)*SPC + i0+g+8];
            float aD0 = sDP[(k0+t)*SPC + i0+g],   aD1 = sDP[(k0+t)*SPC + i0+g+8];
            float aD2 = sDP[(k0+t+4)*SPC + i0+g], aD3 = sDP[(k0+t+4)*SPC + i0+g+8];
#pragma unroll
            for (int dt = 0; dt < 2; ++dt) {
                int d = jh*16 + dt*8 + g;
                float b0 = sV[(k0+t)*SPC + d], b1 = sV[(k0+t+4)*SPC + d];
                mma_tf32(accE[dt], aE0,aE1,aE2,aE3, b0,b1);
                mma_tf32(accD[dt], aD0,aD1,aD2,aD3, b0,b1);
            }
        }
    }

    // ---- row stats to smem ----
    seR0 += __shfl_xor_sync(0xffffffffu, seR0, 1);
    seR0 += __shfl_xor_sync(0xffffffffu, seR0, 2);
    seR1 += __shfl_xor_sync(0xffffffffu, seR1, 1);
    seR1 += __shfl_xor_sync(0xffffffffu, seR1, 2);
    dpR0 += __shfl_xor_sync(0xffffffffu, dpR0, 1);
    dpR0 += __shfl_xor_sync(0xffffffffu, dpR0, 2);
    dpR1 += __shfl_xor_sync(0xffffffffu, dpR1, 1);
    dpR1 += __shfl_xor_sync(0xffffffffu, dpR1, 2);
    if (t == 0) {
        sSe[jh*64 + r0] = seR0; sSe[jh*64 + r1] = seR1;
        sDp[jh*64 + r0] = dpR0; sDp[jh*64 + r1] = dpR1;
    }

    // ---- C2 = q'.kv + qp_kp_1, streamed chunks ----
    float C2[2][4];
#pragma unroll
    for (int dt = 0; dt < 2; ++dt)
#pragma unroll
        for (int c = 0; c < 4; ++c) C2[dt][c] = 0.f;
    float qpkAcc = 0.f;
    int part = tid >> 6, ii = tid & 63;

#pragma unroll 1
    for (int mc = 0; mc < 4; ++mc) {
        __syncthreads();   // prior readers of QPC/KPC done
        {
            const float4* qp = (const float4*)(g_qpT + bidx*(size_t)16384 + mc*4096);
            const float*  kvsrc = g_kv + (size_t)bh*16384 + mc*4096;
            for (int i = tid; i < 1024; i += 512) {
                int m = i >> 4, c4 = (i & 15)*4;
                *(float4*)(sQPC + m*SPC + c4) = qp[i];
                float4 v4 = *(const float4*)(kvsrc + i*4);
                v4.x = tf32_rna(v4.x); v4.y = tf32_rna(v4.y);
                v4.z = tf32_rna(v4.z); v4.w = tf32_rna(v4.w);
                *(float4*)(sKVc + m*SPC + c4) = v4;
            }
        }
        __syncthreads();
        // qp_kp_1 partial (8 parts x 8 m each)
#pragma unroll
        for (int mm = 0; mm < 8; ++mm) {
            int ml = part*8 + mm;
            qpkAcc += sQPC[ml*SPC + ii] * sKps[mc*64 + ml];
        }
#pragma unroll
        for (int kc = 0; kc < 8; ++kc) {
            int k0 = kc*8;
            float a0 = sQPC[(k0+t)*SPC + i0+g],   a1 = sQPC[(k0+t)*SPC + i0+g+8];
            float a2 = sQPC[(k0+t+4)*SPC + i0+g], a3 = sQPC[(k0+t+4)*SPC + i0+g+8];
#pragma unroll
            for (int dt = 0; dt < 2; ++dt) {
                int d = jh*16 + dt*8 + g;
                float b0 = sKVc[(k0+t)*SPC + d], b1 = sKVc[(k0+t+4)*SPC + d];
                mma_tf32(C2[dt], a0,a1,a2,a3, b0,b1);
            }
        }
    }

    __syncthreads();
    sQpk[part*64 + ii] = qpkAcc;
    __syncthreads();
    if (tid < 64) {
        float qpk1 = 0.f;
#pragma unroll
        for (int p = 0; p < 8; ++p) qpk1 += sQpk[p*64 + tid];
        float se = sSe[tid] + sSe[64+tid] + sSe[128+tid] + sSe[192+tid];
        float dp = sDp[tid] + sDp[64+tid] + sDp[128+tid] + sDp[192+tid];
        float lse = __logf(se);
        float pls = sQls[tid] - HALF_LOG_M;          // k_log_scale = -half_log_m (s_k = 0)
        float lr  = __logf(fmaxf(qpk1 - dp, 1e-24f)) + pls;
        float mxv = fmaxf(lse, lr);
        float ln  = mxv + log1pf(__expf(-fabsf(lse - lr)));
        sLn[tid] = ln;
        sPs[tid] = __expf(pls - ln);
    }
    __syncthreads();
    float iE0 = __expf(-sLn[r0]), iE1 = __expf(-sLn[r1]);
    float ps0 = sPs[r0], ps1 = sPs[r1];

    // ---- epilogue ----
    float* ob = out + ((size_t)(b*Tq + t0)*Hq + h)*Eq;
#pragma unroll
    for (int dt = 0; dt < 2; ++dt) {
        int d = jh*16 + dt*8 + 2*t;
        float2 o0, o1;
        o0.x = accE[dt][0]*iE0 + (C2[dt][0] - accD[dt][0])*ps0;
        o0.y = accE[dt][1]*iE0 + (C2[dt][1] - accD[dt][1])*ps0;
        o1.x = accE[dt][2]*iE1 + (C2[dt][2] - accD[dt][2])*ps1;
        o1.y = accE[dt][3]*iE1 + (C2[dt][3] - accD[dt][3])*ps1;
        *(float2*)(ob + (size_t)r0*ROWSTRIDE + d) = o0;
        *(float2*)(ob + (size_t)r1*ROWSTRIDE + d) = o1;
    }
}

// ---------------- launch ----------------
extern "C" void kernel_launch(void* const* d_in, const int* in_sizes, int n_in,
                              void* d_out, int out_size) {
    const float* query = (const float*)d_in[0];
    const float* key   = (const float*)d_in[1];
    const float* value = (const float*)d_in[2];
    const float* proj  = (const float*)d_in[3];
    float* out = (float*)d_out;

    const int SM_SIDES = 9408 * 4;                  // 37632
    const int SM_K2    = 26624 * 4;                 // 106496
    const int SM_MAIN  = SM_MAIN_FLOATS * 4;        // 77568

    cudaFuncSetAttribute(sides_kernel, cudaFuncAttributeMaxDynamicSharedMemorySize, SM_SIDES);
    cudaFuncSetAttribute(k2_kernel,    cudaFuncAttributeMaxDynamicSharedMemorySize, SM_K2);
    cudaFuncSetAttribute(main_kernel,  cudaFuncAttributeMaxDynamicSharedMemorySize, SM_MAIN);

    sides_kernel<<<dim3(BH*NB, 2), 256, SM_SIDES>>>(key, query, proj);
    k2_kernel<<<BH*NB, 256, SM_K2>>>(value);
    reduce_kernel<<<(BH*Mq*Eq + 255)/256, 256>>>();
    main_kernel<<<BH*NB, 512, SM_MAIN>>>(value, out);
}

// round 10
// speedup vs baseline: 2.5280x; 1.3671x over previous
#include <cuda_runtime.h>
#include <cuda_bf16.h>
#include <cuda_fp16.h>
#include <math.h>
#include <stdint.h>

#define Bq 2
#define Tq 2048
#define Hq 12
#define Eq 64
#define Mq 256
#define NB 32
#define BH 24
#define ROWSTRIDE (Hq*Eq)
#define SPK 68
#define SP  72

#define TEMP 0.125f
#define DN 0.35355339059327379f
#define HALF_LOG_M 2.7725887222397811f
#define NEG_INF __int_as_float(0xff800000)
#define KS 0.00390625f                 // 2^-8 prime-side scale
#define LOG_KS 5.5451774444795624753f  // -log(KS) = 8*ln2

// ---------------- device scratch ----------------
__device__ uint32_t g_qbf[BH*NB*4096];           // raw q bf16 planes [row][e]: hi 2048 u32, lo 2048
__device__ uint32_t g_kbf[BH*NB*4096];           // raw k bf16 planes
__device__ float    g_kp [BH*NB*Mq*64];          // [m][j] f32 k' (unscaled, for k2)
__device__ __align__(16) uint32_t g_qpb[BH*NB*8192]; // q' fp16 packed [i][m/2]
__device__ __align__(16) uint32_t g_kpb[BH*NB*8192]; // k'*KS fp16 packed [j][m/2]
__device__ float g_qls [BH*Tq];
__device__ float g_kv  [BH*Mq*Eq];               // [m][d] f32 (unscaled)
__device__ __align__(16) unsigned short g_kvf16[BH*Eq*Mq]; // kv*KS fp16 [d][m]
__device__ float g_kps [BH*Mq];                  // scaled: sum_j f16(k'*KS)
__device__ float g_kvpart [BH*32*Mq*Eq];
__device__ float g_kpspart[BH*32*Mq];

// ---------------- helpers ----------------
__device__ __forceinline__ float tf32_rna(float x) {
    uint32_t r;
    asm("cvt.rna.tf32.f32 %0, %1;" : "=r"(r) : "f"(x));
    return __uint_as_float(r);
}

__device__ __forceinline__ void mma_tf32(float c[4],
        float a0, float a1, float a2, float a3, float b0, float b1)
{
    asm volatile(
        "mma.sync.aligned.m16n8k8.row.col.f32.tf32.tf32.f32 "
        "{%0,%1,%2,%3}, {%4,%5,%6,%7}, {%8,%9}, {%0,%1,%2,%3};\n"
        : "+f"(c[0]), "+f"(c[1]), "+f"(c[2]), "+f"(c[3])
        : "r"(__float_as_uint(a0)), "r"(__float_as_uint(a1)),
          "r"(__float_as_uint(a2)), "r"(__float_as_uint(a3)),
          "r"(__float_as_uint(b0)), "r"(__float_as_uint(b1)));
}

__device__ __forceinline__ void mma_bf16(float c[4],
        uint32_t a0, uint32_t a1, uint32_t a2, uint32_t a3, uint32_t b0, uint32_t b1)
{
    asm volatile(
        "mma.sync.aligned.m16n8k16.row.col.f32.bf16.bf16.f32 "
        "{%0,%1,%2,%3}, {%4,%5,%6,%7}, {%8,%9}, {%0,%1,%2,%3};\n"
        : "+f"(c[0]), "+f"(c[1]), "+f"(c[2]), "+f"(c[3])
        : "r"(a0), "r"(a1), "r"(a2), "r"(a3), "r"(b0), "r"(b1));
}

__device__ __forceinline__ void mma_f16(float c[4],
        uint32_t a0, uint32_t a1, uint32_t a2, uint32_t a3, uint32_t b0, uint32_t b1)
{
    asm volatile(
        "mma.sync.aligned.m16n8k16.row.col.f32.f16.f16.f32 "
        "{%0,%1,%2,%3}, {%4,%5,%6,%7}, {%8,%9}, {%0,%1,%2,%3};\n"
        : "+f"(c[0]), "+f"(c[1]), "+f"(c[2]), "+f"(c[3])
        : "r"(a0), "r"(a1), "r"(a2), "r"(a3), "r"(b0), "r"(b1));
}

__device__ __forceinline__ void split2_bf16(float x, float y, uint32_t &hi, uint32_t &lo) {
    __nv_bfloat16 hx = __float2bfloat16(x);
    __nv_bfloat16 hy = __float2bfloat16(y);
    __nv_bfloat16 lx = __float2bfloat16(x - __bfloat162float(hx));
    __nv_bfloat16 ly = __float2bfloat16(y - __bfloat162float(hy));
    hi = ((uint32_t)__bfloat16_as_ushort(hy) << 16) | (uint32_t)__bfloat16_as_ushort(hx);
    lo = ((uint32_t)__bfloat16_as_ushort(ly) << 16) | (uint32_t)__bfloat16_as_ushort(lx);
}

__device__ __forceinline__ uint32_t pack_f16(float x, float y) {
    __half2 h = __floats2half2_rn(x, y);
    return *reinterpret_cast<uint32_t*>(&h);
}
__device__ __forceinline__ float f16lo(uint32_t u) {
    return __half2float(__ushort_as_half((unsigned short)(u & 0xffffu)));
}
__device__ __forceinline__ float f16hi(uint32_t u) {
    return __half2float(__ushort_as_half((unsigned short)(u >> 16)));
}
__device__ __forceinline__ float bf16lo_f(uint32_t u) {
    return __bfloat162float(__ushort_as_bfloat16((unsigned short)(u & 0xffffu)));
}
__device__ __forceinline__ float bf16hi_f(uint32_t u) {
    return __bfloat162float(__ushort_as_bfloat16((unsigned short)(u >> 16)));
}

// ---------------- kernel 1: sides ----------------
// smem: uT 4608 f, uP 4608 f, diag 64, max 128, part 1024 -> 10432 f
__global__ __launch_bounds__(256,2) void sides_kernel(const float* __restrict__ key,
                                                      const float* __restrict__ query,
                                                      const float* __restrict__ proj) {
    extern __shared__ float sm[];
    uint32_t* uT = (uint32_t*)sm;
    uint32_t* uP = (uint32_t*)(sm + 4608);
    float* sDiag = sm + 9216;
    float* sMax  = sm + 9280;
    float* sPart = sm + 9408;   // [4 rt][256]

    int tid = threadIdx.x;
    int lane = tid & 31, wid = tid >> 5;
    int g = lane >> 2, t = lane & 3;
    int rt = wid & 3;
    int mh = wid >> 2;
    int r0 = rt*16 + g, r1 = r0 + 8;
    int bidx = blockIdx.x, blk = bidx & 31, bh = bidx >> 5;
    int b = bh / Hq, h = bh % Hq;
    int t0 = blk * 64;
    int qside = blockIdx.y;

    const float* src = (qside ? query : key) + ((size_t)(b*Tq + t0)*Hq + h)*Eq;
    uint32_t* gdst = (qside ? g_qbf : g_kbf) + (size_t)bidx * 4096;
    for (int i = tid; i < 2048; i += 256) {
        int row = i >> 5, eh = i & 31;
        float2 v = *(const float2*)(src + (size_t)row*ROWSTRIDE + eh*2);
        uint32_t hi, lo;
        split2_bf16(v.x, v.y, hi, lo);
        uT[row*36 + eh] = hi;
        uT[2304 + row*36 + eh] = lo;
        gdst[row*32 + eh] = hi;
        gdst[2048 + row*32 + eh] = lo;
    }
    __syncthreads();
    if (tid < 64) {
        float s = 0.f;
#pragma unroll
        for (int eh = 0; eh < 32; ++eh) {
            uint32_t hu = uT[tid*36 + eh], lu = uT[2304 + tid*36 + eh];
            float x0 = bf16lo_f(hu) + bf16lo_f(lu);
            float x1 = bf16hi_f(hu) + bf16hi_f(lu);
            s += x0*x0 + x1*x1;
        }
        sDiag[tid] = 0.0625f * s;
    }

    float C[4][4][4];
#pragma unroll
    for (int c = 0; c < 4; ++c)
#pragma unroll
        for (int mt = 0; mt < 4; ++mt)
#pragma unroll
            for (int k = 0; k < 4; ++k) C[c][mt][k] = 0.f;

#pragma unroll 1
    for (int c = 0; c < 4; ++c) {
        __syncthreads();
        for (int i = tid; i < 2048; i += 256) {
            int mm = i >> 5, eh = i & 31;
            float2 v = *(const float2*)(proj + (size_t)(c*64 + mm)*64 + eh*2);
            uint32_t hi, lo;
            split2_bf16(v.x * DN, v.y * DN, hi, lo);
            uP[mm*36 + eh] = hi;
            uP[2304 + mm*36 + eh] = lo;
        }
        __syncthreads();
#pragma unroll
        for (int kc = 0; kc < 4; ++kc) {
            int k8 = kc*8;
            uint32_t ah0 = uT[r0*36 + k8 + t],     ah1 = uT[r1*36 + k8 + t];
            uint32_t ah2 = uT[r0*36 + k8 + t + 4], ah3 = uT[r1*36 + k8 + t + 4];
            uint32_t al0 = uT[2304 + r0*36 + k8 + t],     al1 = uT[2304 + r1*36 + k8 + t];
            uint32_t al2 = uT[2304 + r0*36 + k8 + t + 4], al3 = uT[2304 + r1*36 + k8 + t + 4];
#pragma unroll
            for (int mt = 0; mt < 4; ++mt) {
                int mc = mh*32 + mt*8 + g;
                uint32_t bh0 = uP[mc*36 + k8 + t],        bh1 = uP[mc*36 + k8 + t + 4];
                uint32_t bl0 = uP[2304 + mc*36 + k8 + t], bl1 = uP[2304 + mc*36 + k8 + t + 4];
                mma_bf16(C[c][mt], ah0,ah1,ah2,ah3, bh0,bh1);
                mma_bf16(C[c][mt], ah0,ah1,ah2,ah3, bl0,bl1);
                mma_bf16(C[c][mt], al0,al1,al2,al3, bh0,bh1);
            }
        }
    }

    if (!qside) {
        float dg0 = sDiag[r0], dg1 = sDiag[r1];
        float* kp = g_kp + (size_t)bidx * 16384;
        uint32_t* kpb = g_kpb + (size_t)bidx * 8192;
#pragma unroll
        for (int c = 0; c < 4; ++c)
#pragma unroll
            for (int mt = 0; mt < 4; ++mt) {
                int m0 = c*64 + mh*32 + mt*8 + 2*t;
                int mp = m0 >> 1;
                float e0 = __expf(C[c][mt][0] - dg0);
                float e1 = __expf(C[c][mt][1] - dg0);
                float e2 = __expf(C[c][mt][2] - dg1);
                float e3 = __expf(C[c][mt][3] - dg1);
                kp[(size_t)m0*64 + r0]     = tf32_rna(e0);
                kp[(size_t)(m0+1)*64 + r0] = tf32_rna(e1);
                kp[(size_t)m0*64 + r1]     = tf32_rna(e2);
                kp[(size_t)(m0+1)*64 + r1] = tf32_rna(e3);
                uint32_t p0 = pack_f16(e0*KS, e1*KS);
                uint32_t p1 = pack_f16(e2*KS, e3*KS);
                kpb[r0*128 + mp] = p0;
                kpb[r1*128 + mp] = p1;
                // kps partials from the EXACT fp16 values used by dp
                float pm0 = f16lo(p0) + f16lo(p1);
                float pm1 = f16hi(p0) + f16hi(p1);
                pm0 += __shfl_xor_sync(0xffffffffu, pm0, 4);
                pm0 += __shfl_xor_sync(0xffffffffu, pm0, 8);
                pm0 += __shfl_xor_sync(0xffffffffu, pm0, 16);
                pm1 += __shfl_xor_sync(0xffffffffu, pm1, 4);
                pm1 += __shfl_xor_sync(0xffffffffu, pm1, 8);
                pm1 += __shfl_xor_sync(0xffffffffu, pm1, 16);
                if (g == 0) {
                    sPart[rt*256 + m0]     = pm0;
                    sPart[rt*256 + m0 + 1] = pm1;
                }
            }
        __syncthreads();
        if (tid < 256)
            g_kpspart[(size_t)bidx*256 + tid] =
                sPart[tid] + sPart[256+tid] + sPart[512+tid] + sPart[768+tid];
    } else {
        float mx0 = NEG_INF, mx1 = NEG_INF;
#pragma unroll
        for (int c = 0; c < 4; ++c)
#pragma unroll
            for (int mt = 0; mt < 4; ++mt) {
                mx0 = fmaxf(mx0, fmaxf(C[c][mt][0], C[c][mt][1]));
                mx1 = fmaxf(mx1, fmaxf(C[c][mt][2], C[c][mt][3]));
            }
        mx0 = fmaxf(mx0, __shfl_xor_sync(0xffffffffu, mx0, 1));
        mx0 = fmaxf(mx0, __shfl_xor_sync(0xffffffffu, mx0, 2));
        mx1 = fmaxf(mx1, __shfl_xor_sync(0xffffffffu, mx1, 1));
        mx1 = fmaxf(mx1, __shfl_xor_sync(0xffffffffu, mx1, 2));
        if (t == 0) { sMax[mh*64 + r0] = mx0; sMax[mh*64 + r1] = mx1; }
        __syncthreads();
        float rm0 = fmaxf(sMax[r0], sMax[64 + r0]);
        float rm1 = fmaxf(sMax[r1], sMax[64 + r1]);
        uint32_t* qpb = g_qpb + (size_t)bidx * 8192;
#pragma unroll
        for (int c = 0; c < 4; ++c)
#pragma unroll
            for (int mt = 0; mt < 4; ++mt) {
                int m0 = c*64 + mh*32 + mt*8 + 2*t;
                int mp = m0 >> 1;
                qpb[r0*128 + mp] = pack_f16(__expf(C[c][mt][0] - rm0), __expf(C[c][mt][1] - rm0));
                qpb[r1*128 + mp] = pack_f16(__expf(C[c][mt][2] - rm1), __expf(C[c][mt][3] - rm1));
            }
        if (mh == 0 && t == 0) {
            g_qls[bh*Tq + t0 + r0] = rm0 - sDiag[r0] - HALF_LOG_M;
            g_qls[bh*Tq + t0 + r1] = rm1 - sDiag[r1] - HALF_LOG_M;
        }
    }
}

// ---------------- kernel 2: kv partials (tf32; ksum removed) ----------------
__global__ __launch_bounds__(256,2) void k2_kernel(const float* __restrict__ value) {
    extern __shared__ float sm[];
    float* sKp = sm;
    float* sVh = sm + 17408;
    float* sVl = sm + 22016;
    int tid = threadIdx.x;
    int lane = tid & 31, wid = tid >> 5;
    int g = lane >> 2, t = lane & 3;
    int bh = blockIdx.x >> 5, sblk = blockIdx.x & 31;
    int b = bh / Hq, h = bh % Hq;

    const float4* kp = (const float4*)(g_kp + (size_t)blockIdx.x * 16384);
    for (int i = tid; i < 4096; i += 256) {
        int m = i >> 4, j4 = (i & 15)*4;
        *(float4*)(sKp + m*SPK + j4) = kp[i];
    }
    const float* vb = value + ((size_t)(b*Tq + sblk*64)*Hq + h)*Eq;
    for (int i = tid; i < 1024; i += 256) {
        int j = i >> 4, d4 = (i & 15)*4;
        float4 v4 = *(const float4*)(vb + (size_t)j*ROWSTRIDE + d4);
        float4 hi, lo;
        hi.x = tf32_rna(v4.x); lo.x = v4.x - hi.x;
        hi.y = tf32_rna(v4.y); lo.y = v4.y - hi.y;
        hi.z = tf32_rna(v4.z); lo.z = v4.z - hi.z;
        hi.w = tf32_rna(v4.w); lo.w = v4.w - hi.w;
        *(float4*)(sVh + j*SP + d4) = hi;
        *(float4*)(sVl + j*SP + d4) = lo;
    }
    __syncthreads();

    float C[2][8][4];
#pragma unroll
    for (int it = 0; it < 2; ++it)
#pragma unroll
        for (int nt = 0; nt < 8; ++nt)
#pragma unroll
            for (int k = 0; k < 4; ++k) C[it][nt][k] = 0.f;

#pragma unroll
    for (int kc = 0; kc < 8; ++kc) {
        int k0 = kc*8;
        float a[2][4];
#pragma unroll
        for (int it = 0; it < 2; ++it) {
            int r = wid*32 + it*16 + g;
            a[it][0] = sKp[(size_t)r*SPK + k0 + t];
            a[it][1] = sKp[(size_t)(r+8)*SPK + k0 + t];
            a[it][2] = sKp[(size_t)r*SPK + k0 + t + 4];
            a[it][3] = sKp[(size_t)(r+8)*SPK + k0 + t + 4];
        }
#pragma unroll
        for (int nt = 0; nt < 8; ++nt) {
            int d = nt*8 + g;
            float bh0 = sVh[(k0+t)*SP + d], bh1 = sVh[(k0+t+4)*SP + d];
            float bl0 = sVl[(k0+t)*SP + d], bl1 = sVl[(k0+t+4)*SP + d];
#pragma unroll
            for (int it = 0; it < 2; ++it) {
                mma_tf32(C[it][nt], a[it][0],a[it][1],a[it][2],a[it][3], bh0,bh1);
                mma_tf32(C[it][nt], a[it][0],a[it][1],a[it][2],a[it][3], bl0,bl1);
            }
        }
    }

    float* kvp = g_kvpart + (size_t)blockIdx.x * 16384;
#pragma unroll
    for (int it = 0; it < 2; ++it) {
        int m0 = wid*32 + it*16 + g;
#pragma unroll
        for (int nt = 0; nt < 8; ++nt) {
            int d = nt*8 + 2*t;
            *(float2*)(kvp + (size_t)m0*64 + d)     = make_float2(C[it][nt][0], C[it][nt][1]);
            *(float2*)(kvp + (size_t)(m0+8)*64 + d) = make_float2(C[it][nt][2], C[it][nt][3]);
        }
    }
}

// ---------------- kernel 2b: reduce partials (+ fp16 kv transpose, scaled) ----------------
__global__ void reduce_kernel() {
    int idx = blockIdx.x*256 + threadIdx.x;
    if (idx < BH*Mq*Eq) {
        int bh = idx >> 14;
        int rem = idx & 16383;
        float s = 0.f;
#pragma unroll
        for (int p = 0; p < 32; ++p) s += g_kvpart[(size_t)(bh*32 + p)*16384 + rem];
        g_kv[idx] = s;
        int m = rem >> 6, d = rem & 63;
        g_kvf16[bh*16384 + d*256 + m] = __half_as_ushort(__float2half_rn(s * KS));
    }
    if (idx < BH*Mq) {
        int bh = idx >> 8; int m = idx & 255;
        float s = 0.f;
#pragma unroll
        for (int p = 0; p < 32; ++p) s += g_kpspart[(bh*32 + p)*256 + m];
        g_kps[idx] = s;   // scaled by KS (from sides fp16 partials)
    }
}

// ---------------- kernel 4: main — packed fp16 data path ----------------
#define O_QT  0
#define O_KT  4608
#define O_QPP 9216
#define O_KPP 17664
#define O_KPS 26112
#define O_QLS 26368
#define O_SSE 26432
#define O_SDP 26688
#define O_QPK 26944
#define O_LN  27456
#define O_PS  27520
#define SM_MAIN_FLOATS 27584

__global__ __launch_bounds__(512,2) void main_kernel(const float* __restrict__ value,
                                                     float* __restrict__ out) {
    extern __shared__ float smm[];
    uint32_t* uQT  = (uint32_t*)(smm + O_QT);
    uint32_t* uKT  = (uint32_t*)(smm + O_KT);
    uint32_t* sQPp = (uint32_t*)(smm + O_QPP);
    uint32_t* sKPp = (uint32_t*)(smm + O_KPP);
    uint32_t* sE16 = sKPp;
    uint32_t* sD16 = sKPp + 2304;
    uint32_t* sVt  = sKPp + 4608;
    unsigned short* sVt16 = (unsigned short*)sVt;
    uint32_t* sKVp = sKPp;
    float* sKps = smm + O_KPS;
    float* sQls = smm + O_QLS;
    float* sSe  = smm + O_SSE;
    float* sDp  = smm + O_SDP;
    float* sQpk = smm + O_QPK;
    float* sLn  = smm + O_LN;
    float* sPs  = smm + O_PS;

    int tid = threadIdx.x;
    int lane = tid & 31, wid = tid >> 5;
    int g = lane >> 2, t = lane & 3;
    int iw = wid & 3, jh = wid >> 2;
    int i0 = iw * 16;
    int bidx = blockIdx.x, blk = bidx & 31, bh = bidx >> 5;
    int b = bh / Hq, h = bh % Hq;
    int t0 = blk * 64;
    int r0 = i0 + g, r1 = r0 + 8;

    // ---- phase 0 ----
    {
        const uint32_t* gq = g_qbf + (size_t)bidx*4096;
        for (int i = tid; i < 2048; i += 512) {
            int row = i >> 5, eh = i & 31;
            uQT[row*36 + eh]        = gq[i];
            uQT[2304 + row*36 + eh] = gq[2048 + i];
        }
        const uint4* qp4 = (const uint4*)(g_qpb + (size_t)bidx*8192);
        for (int i = tid; i < 2048; i += 512) {
            int row = i >> 5, mp0 = (i & 31)*4;
            *(uint4*)(sQPp + row*132 + mp0) = qp4[i];
        }
        if (tid < 256) sKps[tid] = g_kps[bh*Mq + tid];
        if (tid < 64)  sQls[tid] = g_qls[bh*Tq + t0 + tid];
    }

    float accE[2][4], accD[2][4];
#pragma unroll
    for (int dt = 0; dt < 2; ++dt)
#pragma unroll
        for (int c = 0; c < 4; ++c) { accE[dt][c] = 0.f; accD[dt][c] = 0.f; }
    float seR0 = 0.f, seR1 = 0.f, dpR0 = 0.f, dpR1 = 0.f;

    // ---- neighbor loop ----
#pragma unroll 1
    for (int nw = 0; nw < 3; ++nw) {
        int nb = blk - 1 + nw;
        if (nb < 0 || nb >= NB) continue;
        size_t kb = (size_t)(bh*32 + nb);
        __syncthreads();   // S0
        {
            const uint32_t* gk = g_kbf + kb*4096;
            for (int i = tid; i < 2048; i += 512) {
                int row = i >> 5, eh = i & 31;
                uKT[row*36 + eh]        = gk[i];
                uKT[2304 + row*36 + eh] = gk[2048 + i];
            }
            const uint4* kp4 = (const uint4*)(g_kpb + kb*8192);
            for (int i = tid; i < 2048; i += 512) {
                int row = i >> 5, mp0 = (i & 31)*4;
                *(uint4*)(sKPp + row*132 + mp0) = kp4[i];
            }
        }
        __syncthreads();   // S1

        float Cqk[2][4], Cdp[2][4];
#pragma unroll
        for (int jt = 0; jt < 2; ++jt)
#pragma unroll
            for (int c = 0; c < 4; ++c) { Cqk[jt][c] = 0.f; Cdp[jt][c] = 0.f; }

        // QK: bf16 3-term split (unchanged)
#pragma unroll
        for (int kc = 0; kc < 4; ++kc) {
            int k8 = kc*8;
            uint32_t ah0 = uQT[r0*36 + k8 + t],     ah1 = uQT[r1*36 + k8 + t];
            uint32_t ah2 = uQT[r0*36 + k8 + t + 4], ah3 = uQT[r1*36 + k8 + t + 4];
            uint32_t al0 = uQT[2304 + r0*36 + k8 + t],     al1 = uQT[2304 + r1*36 + k8 + t];
            uint32_t al2 = uQT[2304 + r0*36 + k8 + t + 4], al3 = uQT[2304 + r1*36 + k8 + t + 4];
#pragma unroll
            for (int jt = 0; jt < 2; ++jt) {
                int j = jh*16 + jt*8 + g;
                uint32_t bh0 = uKT[j*36 + k8 + t],        bh1 = uKT[j*36 + k8 + t + 4];
                uint32_t bl0 = uKT[2304 + j*36 + k8 + t], bl1 = uKT[2304 + j*36 + k8 + t + 4];
                mma_bf16(Cqk[jt], ah0,ah1,ah2,ah3, bh0,bh1);
                mma_bf16(Cqk[jt], ah0,ah1,ah2,ah3, bl0,bl1);
                mma_bf16(Cqk[jt], al0,al1,al2,al3, bh0,bh1);
            }
        }
        // dp (scaled by KS): packed fp16, K=256 -> 16 chunks of k16
#pragma unroll
        for (int kc = 0; kc < 16; ++kc) {
            int k8 = kc*8;
            uint32_t a0 = sQPp[r0*132 + k8 + t],     a1 = sQPp[r1*132 + k8 + t];
            uint32_t a2 = sQPp[r0*132 + k8 + t + 4], a3 = sQPp[r1*132 + k8 + t + 4];
#pragma unroll
            for (int jt = 0; jt < 2; ++jt) {
                int j = jh*16 + jt*8 + g;
                uint32_t b0 = sKPp[j*132 + k8 + t], b1 = sKPp[j*132 + k8 + t + 4];
                mma_f16(Cdp[jt], a0,a1,a2,a3, b0,b1);
            }
        }
        __syncthreads();   // S2

        // E/DP pack (fp16) + row sums; stage V transposed fp16
#pragma unroll
        for (int jt = 0; jt < 2; ++jt) {
            int j0 = jh*16 + jt*8;
            float e00 = __expf(TEMP*Cqk[jt][0]);
            float e01 = __expf(TEMP*Cqk[jt][1]);
            float e10 = __expf(TEMP*Cqk[jt][2]);
            float e11 = __expf(TEMP*Cqk[jt][3]);
            seR0 += e00 + e01;  seR1 += e10 + e11;
            dpR0 += Cdp[jt][0] + Cdp[jt][1];
            dpR1 += Cdp[jt][2] + Cdp[jt][3];
            int jp = (j0 >> 1) + t;
            sE16[r0*36 + jp] = pack_f16(e00, e01);
            sE16[r1*36 + jp] = pack_f16(e10, e11);
            sD16[r0*36 + jp] = pack_f16(Cdp[jt][0], Cdp[jt][1]);
            sD16[r1*36 + jp] = pack_f16(Cdp[jt][2], Cdp[jt][3]);
        }
        {
            const float* vb = value + ((size_t)(b*Tq + nb*64)*Hq + h)*Eq;
            for (int i2 = tid; i2 < 1024; i2 += 512) {
                int j = i2 >> 4, d0 = (i2 & 15)*4;
                float4 v4 = *(const float4*)(vb + (size_t)j*ROWSTRIDE + d0);
                sVt16[(d0+0)*72 + j] = __half_as_ushort(__float2half_rn(v4.x));
                sVt16[(d0+1)*72 + j] = __half_as_ushort(__float2half_rn(v4.y));
                sVt16[(d0+2)*72 + j] = __half_as_ushort(__float2half_rn(v4.z));
                sVt16[(d0+3)*72 + j] = __half_as_ushort(__float2half_rn(v4.w));
            }
        }
        __syncthreads();   // S3

        // accE += E.V ; accD += DP.V   (fp16)
#pragma unroll
        for (int kc = 0; kc < 4; ++kc) {
            int k8 = kc*8;
            uint32_t aE0 = sE16[r0*36 + k8 + t],     aE1 = sE16[r1*36 + k8 + t];
            uint32_t aE2 = sE16[r0*36 + k8 + t + 4], aE3 = sE16[r1*36 + k8 + t + 4];
            uint32_t aD0 = sD16[r0*36 + k8 + t],     aD1 = sD16[r1*36 + k8 + t];
            uint32_t aD2 = sD16[r0*36 + k8 + t + 4], aD3 = sD16[r1*36 + k8 + t + 4];
#pragma unroll
            for (int dt = 0; dt < 2; ++dt) {
                int d = jh*16 + dt*8 + g;
                uint32_t b0 = sVt[d*36 + k8 + t], b1 = sVt[d*36 + k8 + t + 4];
                mma_f16(accE[dt], aE0,aE1,aE2,aE3, b0,b1);
                mma_f16(accD[dt], aD0,aD1,aD2,aD3, b0,b1);
            }
        }
    }

    // ---- row stats ----
    seR0 += __shfl_xor_sync(0xffffffffu, seR0, 1);
    seR0 += __shfl_xor_sync(0xffffffffu, seR0, 2);
    seR1 += __shfl_xor_sync(0xffffffffu, seR1, 1);
    seR1 += __shfl_xor_sync(0xffffffffu, seR1, 2);
    dpR0 += __shfl_xor_sync(0xffffffffu, dpR0, 1);
    dpR0 += __shfl_xor_sync(0xffffffffu, dpR0, 2);
    dpR1 += __shfl_xor_sync(0xffffffffu, dpR1, 1);
    dpR1 += __shfl_xor_sync(0xffffffffu, dpR1, 2);
    if (t == 0) {
        sSe[jh*64 + r0] = seR0; sSe[jh*64 + r1] = seR1;
        sDp[jh*64 + r0] = dpR0; sDp[jh*64 + r1] = dpR1;
    }
    __syncthreads();
    // stage kv fp16 (scaled) [d][132]
    {
        const uint4* kv4 = (const uint4*)(g_kvf16 + (size_t)bh*16384);
        for (int i = tid; i < 2048; i += 512) {
            int row = i >> 5, mp0 = (i & 31)*4;
            *(uint4*)(sKVp + row*132 + mp0) = kv4[i];
        }
    }
    __syncthreads();

    // qp_kp_1 partials (fp16 q' x scaled kps — consistent with dp)
    {
        int part = tid >> 6, ii = tid & 63;
        float s = 0.f;
#pragma unroll
        for (int k = 0; k < 16; ++k) {
            uint32_t u = sQPp[ii*132 + part*16 + k];
            int m2 = (part*16 + k)*2;
            s += f16lo(u) * sKps[m2] + f16hi(u) * sKps[m2+1];
        }
        sQpk[part*64 + ii] = s;
    }

    // C2 = q'.kv (fp16, scaled)
    float C2[2][4];
#pragma unroll
    for (int dt = 0; dt < 2; ++dt)
#pragma unroll
        for (int c = 0; c < 4; ++c) C2[dt][c] = 0.f;
#pragma unroll
    for (int kc = 0; kc < 16; ++kc) {
        int k8 = kc*8;
        uint32_t a0 = sQPp[r0*132 + k8 + t],     a1 = sQPp[r1*132 + k8 + t];
        uint32_t a2 = sQPp[r0*132 + k8 + t + 4], a3 = sQPp[r1*132 + k8 + t + 4];
#pragma unroll
        for (int dt = 0; dt < 2; ++dt) {
            int d = jh*16 + dt*8 + g;
            uint32_t b0 = sKVp[d*132 + k8 + t], b1 = sKVp[d*132 + k8 + t + 4];
            mma_f16(C2[dt], a0,a1,a2,a3, b0,b1);
        }
    }

    __syncthreads();
    if (tid < 64) {
        float qpk1 = 0.f;
#pragma unroll
        for (int p = 0; p < 8; ++p) qpk1 += sQpk[p*64 + tid];
        float se = sSe[tid] + sSe[64+tid] + sSe[128+tid] + sSe[192+tid];
        float dp = sDp[tid] + sDp[64+tid] + sDp[128+tid] + sDp[192+tid];
        float lse = __logf(se);
        float pls = sQls[tid] - HALF_LOG_M;
        // qpk1, dp are scaled by KS: log(actual) = log(scaled) + LOG_KS
        float lr  = __logf(fmaxf(qpk1 - dp, 1e-30f)) + LOG_KS + pls;
        float mxv = fmaxf(lse, lr);
        float ln  = mxv + log1pf(__expf(-fabsf(lse - lr)));
        sLn[tid] = ln;
        sPs[tid] = __expf(pls - ln);
    }
    __syncthreads();
    float iE0 = __expf(-sLn[r0]), iE1 = __expf(-sLn[r1]);
    float ps0 = sPs[r0] * 256.f, ps1 = sPs[r1] * 256.f;  // /KS for scaled C2,accD

    // ---- epilogue ----
    float* ob = out + ((size_t)(b*Tq + t0)*Hq + h)*Eq;
#pragma unroll
    for (int dt = 0; dt < 2; ++dt) {
        int d = jh*16 + dt*8 + 2*t;
        float2 o0, o1;
        o0.x = accE[dt][0]*iE0 + (C2[dt][0] - accD[dt][0])*ps0;
        o0.y = accE[dt][1]*iE0 + (C2[dt][1] - accD[dt][1])*ps0;
        o1.x = accE[dt][2]*iE1 + (C2[dt][2] - accD[dt][2])*ps1;
        o1.y = accE[dt][3]*iE1 + (C2[dt][3] - accD[dt][3])*ps1;
        *(float2*)(ob + (size_t)r0*ROWSTRIDE + d) = o0;
        *(float2*)(ob + (size_t)r1*ROWSTRIDE + d) = o1;
    }
}

// ---------------- launch ----------------
extern "C" void kernel_launch(void* const* d_in, const int* in_sizes, int n_in,
                              void* d_out, int out_size) {
    const float* query = (const float*)d_in[0];
    const float* key   = (const float*)d_in[1];
    const float* value = (const float*)d_in[2];
    const float* proj  = (const float*)d_in[3];
    float* out = (float*)d_out;

    const int SM_SIDES = 10432 * 4;            // 41728
    const int SM_K2    = 26624 * 4;            // 106496
    const int SM_MAIN  = SM_MAIN_FLOATS * 4;   // 110336

    cudaFuncSetAttribute(sides_kernel, cudaFuncAttributeMaxDynamicSharedMemorySize, SM_SIDES);
    cudaFuncSetAttribute(k2_kernel,    cudaFuncAttributeMaxDynamicSharedMemorySize, SM_K2);
    cudaFuncSetAttribute(main_kernel,  cudaFuncAttributeMaxDynamicSharedMemorySize, SM_MAIN);

    sides_kernel<<<dim3(BH*NB, 2), 256, SM_SIDES>>>(key, query, proj);
    k2_kernel<<<BH*NB, 256, SM_K2>>>(value);
    reduce_kernel<<<(BH*Mq*Eq + 255)/256, 256>>>();
    main_kernel<<<BH*NB, 512, SM_MAIN>>>(value, out);
}

// round 11
// speedup vs baseline: 2.9140x; 1.1527x over previous
#include <cuda_runtime.h>
#include <cuda_bf16.h>
#include <cuda_fp16.h>
#include <math.h>
#include <stdint.h>

#define Bq 2
#define Tq 2048
#define Hq 12
#define Eq 64
#define Mq 256
#define NB 32
#define BH 24
#define ROWSTRIDE (Hq*Eq)

#define TEMP 0.125f
#define DN 0.35355339059327379f
#define HALF_LOG_M 2.7725887222397811f
#define NEG_INF __int_as_float(0xff800000)
#define KS 0.00390625f                 // 2^-8 prime-side scale
#define LOG_KS 5.5451774444795624753f  // -log(KS) = 8*ln2

// ---------------- device scratch ----------------
__device__ uint32_t g_qbf[BH*NB*4096];           // raw q bf16 planes [row][e]: hi 2048 u32, lo 2048
__device__ uint32_t g_kbf[BH*NB*4096];           // raw k bf16 planes
__device__ __align__(16) uint32_t g_qpb[BH*NB*8192]; // q' fp16 packed [i][m/2]
__device__ __align__(16) uint32_t g_kpb[BH*NB*8192]; // k'*KS fp16 packed [j][m/2]
__device__ float g_qls [BH*Tq];
__device__ __align__(16) unsigned short g_kvf16[BH*Eq*Mq]; // kv*KS fp16 [d][m]
__device__ float g_kps [BH*Mq];                  // scaled: sum_j f16(k'*KS)
__device__ float g_kvpart [BH*32*Mq*Eq];         // KS-scaled kv partials [m][d]
__device__ float g_kpspart[BH*32*Mq];

// ---------------- helpers ----------------
__device__ __forceinline__ void mma_bf16(float c[4],
        uint32_t a0, uint32_t a1, uint32_t a2, uint32_t a3, uint32_t b0, uint32_t b1)
{
    asm volatile(
        "mma.sync.aligned.m16n8k16.row.col.f32.bf16.bf16.f32 "
        "{%0,%1,%2,%3}, {%4,%5,%6,%7}, {%8,%9}, {%0,%1,%2,%3};\n"
        : "+f"(c[0]), "+f"(c[1]), "+f"(c[2]), "+f"(c[3])
        : "r"(a0), "r"(a1), "r"(a2), "r"(a3), "r"(b0), "r"(b1));
}

__device__ __forceinline__ void mma_f16(float c[4],
        uint32_t a0, uint32_t a1, uint32_t a2, uint32_t a3, uint32_t b0, uint32_t b1)
{
    asm volatile(
        "mma.sync.aligned.m16n8k16.row.col.f32.f16.f16.f32 "
        "{%0,%1,%2,%3}, {%4,%5,%6,%7}, {%8,%9}, {%0,%1,%2,%3};\n"
        : "+f"(c[0]), "+f"(c[1]), "+f"(c[2]), "+f"(c[3])
        : "r"(a0), "r"(a1), "r"(a2), "r"(a3), "r"(b0), "r"(b1));
}

__device__ __forceinline__ void split2_bf16(float x, float y, uint32_t &hi, uint32_t &lo) {
    __nv_bfloat16 hx = __float2bfloat16(x);
    __nv_bfloat16 hy = __float2bfloat16(y);
    __nv_bfloat16 lx = __float2bfloat16(x - __bfloat162float(hx));
    __nv_bfloat16 ly = __float2bfloat16(y - __bfloat162float(hy));
    hi = ((uint32_t)__bfloat16_as_ushort(hy) << 16) | (uint32_t)__bfloat16_as_ushort(hx);
    lo = ((uint32_t)__bfloat16_as_ushort(ly) << 16) | (uint32_t)__bfloat16_as_ushort(lx);
}

__device__ __forceinline__ uint32_t pack_f16(float x, float y) {
    __half2 h = __floats2half2_rn(x, y);
    return *reinterpret_cast<uint32_t*>(&h);
}
__device__ __forceinline__ float f16lo(uint32_t u) {
    return __half2float(__ushort_as_half((unsigned short)(u & 0xffffu)));
}
__device__ __forceinline__ float f16hi(uint32_t u) {
    return __half2float(__ushort_as_half((unsigned short)(u >> 16)));
}
__device__ __forceinline__ float bf16lo_f(uint32_t u) {
    return __bfloat162float(__ushort_as_bfloat16((unsigned short)(u & 0xffffu)));
}
__device__ __forceinline__ float bf16hi_f(uint32_t u) {
    return __bfloat162float(__ushort_as_bfloat16((unsigned short)(u >> 16)));
}

// ---------------- kernel 1: sides (k-side fused with kv partials) ----------------
// smem floats: uT 4608 | uP 4608 | diag 64 | max 128 | part 1024 | sKp16 9216 | sVt 2304 = 21952
#define SD_DIAG 9216
#define SD_MAX  9280
#define SD_PART 9408
#define SD_KP16 10432
#define SD_VT   19648
#define SM_SIDES_FLOATS 21952

__global__ __launch_bounds__(256,2) void sides_kernel(const float* __restrict__ key,
                                                      const float* __restrict__ query,
                                                      const float* __restrict__ proj,
                                                      const float* __restrict__ value) {
    extern __shared__ float sm[];
    uint32_t* uT = (uint32_t*)sm;
    uint32_t* uP = (uint32_t*)(sm + 4608);
    float* sDiag = sm + SD_DIAG;
    float* sMax  = sm + SD_MAX;
    float* sPart = sm + SD_PART;   // [4 rt][256]
    unsigned short* sKp16 = (unsigned short*)(sm + SD_KP16);  // [m][j] stride 72 halfs
    uint32_t*       sKp32 = (uint32_t*)(sm + SD_KP16);        // [m][j/2] stride 36 u32
    unsigned short* sVt16 = (unsigned short*)(sm + SD_VT);    // [d][j] stride 72 halfs
    uint32_t*       sVt32 = (uint32_t*)(sm + SD_VT);

    int tid = threadIdx.x;
    int lane = tid & 31, wid = tid >> 5;
    int g = lane >> 2, t = lane & 3;
    int rt = wid & 3;
    int mh = wid >> 2;
    int r0 = rt*16 + g, r1 = r0 + 8;
    int bidx = blockIdx.x, blk = bidx & 31, bh = bidx >> 5;
    int b = bh / Hq, h = bh % Hq;
    int t0 = blk * 64;
    int qside = blockIdx.y;

    const float* src = (qside ? query : key) + ((size_t)(b*Tq + t0)*Hq + h)*Eq;
    uint32_t* gdst = (qside ? g_qbf : g_kbf) + (size_t)bidx * 4096;
    for (int i = tid; i < 2048; i += 256) {
        int row = i >> 5, eh = i & 31;
        float2 v = *(const float2*)(src + (size_t)row*ROWSTRIDE + eh*2);
        uint32_t hi, lo;
        split2_bf16(v.x, v.y, hi, lo);
        uT[row*36 + eh] = hi;
        uT[2304 + row*36 + eh] = lo;
        gdst[row*32 + eh] = hi;
        gdst[2048 + row*32 + eh] = lo;
    }
    __syncthreads();
    if (tid < 64) {
        float s = 0.f;
#pragma unroll
        for (int eh = 0; eh < 32; ++eh) {
            uint32_t hu = uT[tid*36 + eh], lu = uT[2304 + tid*36 + eh];
            float x0 = bf16lo_f(hu) + bf16lo_f(lu);
            float x1 = bf16hi_f(hu) + bf16hi_f(lu);
            s += x0*x0 + x1*x1;
        }
        sDiag[tid] = 0.0625f * s;
    }

    float C[4][4][4];
#pragma unroll
    for (int c = 0; c < 4; ++c)
#pragma unroll
        for (int mt = 0; mt < 4; ++mt)
#pragma unroll
            for (int k = 0; k < 4; ++k) C[c][mt][k] = 0.f;

#pragma unroll 1
    for (int c = 0; c < 4; ++c) {
        __syncthreads();
        for (int i = tid; i < 2048; i += 256) {
            int mm = i >> 5, eh = i & 31;
            float2 v = *(const float2*)(proj + (size_t)(c*64 + mm)*64 + eh*2);
            uint32_t hi, lo;
            split2_bf16(v.x * DN, v.y * DN, hi, lo);
            uP[mm*36 + eh] = hi;
            uP[2304 + mm*36 + eh] = lo;
        }
        __syncthreads();
#pragma unroll
        for (int kc = 0; kc < 4; ++kc) {
            int k8 = kc*8;
            uint32_t ah0 = uT[r0*36 + k8 + t],     ah1 = uT[r1*36 + k8 + t];
            uint32_t ah2 = uT[r0*36 + k8 + t + 4], ah3 = uT[r1*36 + k8 + t + 4];
            uint32_t al0 = uT[2304 + r0*36 + k8 + t],     al1 = uT[2304 + r1*36 + k8 + t];
            uint32_t al2 = uT[2304 + r0*36 + k8 + t + 4], al3 = uT[2304 + r1*36 + k8 + t + 4];
#pragma unroll
            for (int mt = 0; mt < 4; ++mt) {
                int mc = mh*32 + mt*8 + g;
                uint32_t bh0 = uP[mc*36 + k8 + t],        bh1 = uP[mc*36 + k8 + t + 4];
                uint32_t bl0 = uP[2304 + mc*36 + k8 + t], bl1 = uP[2304 + mc*36 + k8 + t + 4];
                mma_bf16(C[c][mt], ah0,ah1,ah2,ah3, bh0,bh1);
                mma_bf16(C[c][mt], ah0,ah1,ah2,ah3, bl0,bl1);
                mma_bf16(C[c][mt], al0,al1,al2,al3, bh0,bh1);
            }
        }
    }

    if (!qside) {
        float dg0 = sDiag[r0], dg1 = sDiag[r1];
        uint32_t* kpb = g_kpb + (size_t)bidx * 8192;
#pragma unroll
        for (int c = 0; c < 4; ++c)
#pragma unroll
            for (int mt = 0; mt < 4; ++mt) {
                int m0 = c*64 + mh*32 + mt*8 + 2*t;
                int mp = m0 >> 1;
                float e0 = __expf(C[c][mt][0] - dg0);
                float e1 = __expf(C[c][mt][1] - dg0);
                float e2 = __expf(C[c][mt][2] - dg1);
                float e3 = __expf(C[c][mt][3] - dg1);
                uint32_t p0 = pack_f16(e0*KS, e1*KS);
                uint32_t p1 = pack_f16(e2*KS, e3*KS);
                kpb[r0*128 + mp] = p0;
                kpb[r1*128 + mp] = p1;
                // smem transpose: k' fp16 [m][j]
                sKp16[m0*72 + r0]     = (unsigned short)(p0 & 0xffffu);
                sKp16[(m0+1)*72 + r0] = (unsigned short)(p0 >> 16);
                sKp16[m0*72 + r1]     = (unsigned short)(p1 & 0xffffu);
                sKp16[(m0+1)*72 + r1] = (unsigned short)(p1 >> 16);
                // kps partials from the EXACT fp16 values used by dp
                float pm0 = f16lo(p0) + f16lo(p1);
                float pm1 = f16hi(p0) + f16hi(p1);
                pm0 += __shfl_xor_sync(0xffffffffu, pm0, 4);
                pm0 += __shfl_xor_sync(0xffffffffu, pm0, 8);
                pm0 += __shfl_xor_sync(0xffffffffu, pm0, 16);
                pm1 += __shfl_xor_sync(0xffffffffu, pm1, 4);
                pm1 += __shfl_xor_sync(0xffffffffu, pm1, 8);
                pm1 += __shfl_xor_sync(0xffffffffu, pm1, 16);
                if (g == 0) {
                    sPart[rt*256 + m0]     = pm0;
                    sPart[rt*256 + m0 + 1] = pm1;
                }
            }
        // stage v transposed fp16 [d][j]
        {
            const float* vb = value + ((size_t)(b*Tq + t0)*Hq + h)*Eq;
            for (int i2 = tid; i2 < 1024; i2 += 256) {
                int j = i2 >> 4, d0 = (i2 & 15)*4;
                float4 v4 = *(const float4*)(vb + (size_t)j*ROWSTRIDE + d0);
                sVt16[(d0+0)*72 + j] = __half_as_ushort(__float2half_rn(v4.x));
                sVt16[(d0+1)*72 + j] = __half_as_ushort(__float2half_rn(v4.y));
                sVt16[(d0+2)*72 + j] = __half_as_ushort(__float2half_rn(v4.z));
                sVt16[(d0+3)*72 + j] = __half_as_ushort(__float2half_rn(v4.w));
            }
        }
        __syncthreads();
        if (tid < 256)
            g_kpspart[(size_t)bidx*256 + tid] =
                sPart[tid] + sPart[256+tid] + sPart[512+tid] + sPart[768+tid];

        // kv partials: KC[m][d] = sum_j k'[m][j]*v[j][d]  (fp16 MMA, f32 accum)
        float KC[2][8][4];
#pragma unroll
        for (int it = 0; it < 2; ++it)
#pragma unroll
            for (int nt = 0; nt < 8; ++nt)
#pragma unroll
                for (int k = 0; k < 4; ++k) KC[it][nt][k] = 0.f;

#pragma unroll
        for (int kc = 0; kc < 4; ++kc) {
            int k8 = kc*8;
            uint32_t a[2][4];
#pragma unroll
            for (int it = 0; it < 2; ++it) {
                int rb = wid*32 + it*16;
                a[it][0] = sKp32[(rb+g)*36 + k8 + t];
                a[it][1] = sKp32[(rb+g+8)*36 + k8 + t];
                a[it][2] = sKp32[(rb+g)*36 + k8 + t + 4];
                a[it][3] = sKp32[(rb+g+8)*36 + k8 + t + 4];
            }
#pragma unroll
            for (int nt = 0; nt < 8; ++nt) {
                int d = nt*8 + g;
                uint32_t b0 = sVt32[d*36 + k8 + t], b1 = sVt32[d*36 + k8 + t + 4];
#pragma unroll
                for (int it = 0; it < 2; ++it)
                    mma_f16(KC[it][nt], a[it][0],a[it][1],a[it][2],a[it][3], b0,b1);
            }
        }
        float* kvp = g_kvpart + (size_t)bidx * 16384;
#pragma unroll
        for (int it = 0; it < 2; ++it) {
            int m0 = wid*32 + it*16 + g;
#pragma unroll
            for (int nt = 0; nt < 8; ++nt) {
                int d = nt*8 + 2*t;
                *(float2*)(kvp + (size_t)m0*64 + d)     = make_float2(KC[it][nt][0], KC[it][nt][1]);
                *(float2*)(kvp + (size_t)(m0+8)*64 + d) = make_float2(KC[it][nt][2], KC[it][nt][3]);
            }
        }
    } else {
        float mx0 = NEG_INF, mx1 = NEG_INF;
#pragma unroll
        for (int c = 0; c < 4; ++c)
#pragma unroll
            for (int mt = 0; mt < 4; ++mt) {
                mx0 = fmaxf(mx0, fmaxf(C[c][mt][0], C[c][mt][1]));
                mx1 = fmaxf(mx1, fmaxf(C[c][mt][2], C[c][mt][3]));
            }
        mx0 = fmaxf(mx0, __shfl_xor_sync(0xffffffffu, mx0, 1));
        mx0 = fmaxf(mx0, __shfl_xor_sync(0xffffffffu, mx0, 2));
        mx1 = fmaxf(mx1, __shfl_xor_sync(0xffffffffu, mx1, 1));
        mx1 = fmaxf(mx1, __shfl_xor_sync(0xffffffffu, mx1, 2));
        if (t == 0) { sMax[mh*64 + r0] = mx0; sMax[mh*64 + r1] = mx1; }
        __syncthreads();
        float rm0 = fmaxf(sMax[r0], sMax[64 + r0]);
        float rm1 = fmaxf(sMax[r1], sMax[64 + r1]);
        uint32_t* qpb = g_qpb + (size_t)bidx * 8192;
#pragma unroll
        for (int c = 0; c < 4; ++c)
#pragma unroll
            for (int mt = 0; mt < 4; ++mt) {
                int m0 = c*64 + mh*32 + mt*8 + 2*t;
                int mp = m0 >> 1;
                qpb[r0*128 + mp] = pack_f16(__expf(C[c][mt][0] - rm0), __expf(C[c][mt][1] - rm0));
                qpb[r1*128 + mp] = pack_f16(__expf(C[c][mt][2] - rm1), __expf(C[c][mt][3] - rm1));
            }
        if (mh == 0 && t == 0) {
            g_qls[bh*Tq + t0 + r0] = rm0 - sDiag[r0] - HALF_LOG_M;
            g_qls[bh*Tq + t0 + r1] = rm1 - sDiag[r1] - HALF_LOG_M;
        }
    }
}

// ---------------- kernel 2b: reduce partials (fp16 kv transpose, scaled) ----------------
__global__ void reduce_kernel() {
    int idx = blockIdx.x*256 + threadIdx.x;
    if (idx < BH*Mq*Eq) {
        int bh = idx >> 14;
        int rem = idx & 16383;
        float s = 0.f;
#pragma unroll
        for (int p = 0; p < 32; ++p) s += g_kvpart[(size_t)(bh*32 + p)*16384 + rem];
        int m = rem >> 6, d = rem & 63;
        g_kvf16[bh*16384 + d*256 + m] = __half_as_ushort(__float2half_rn(s));  // already KS-scaled
    }
    if (idx < BH*Mq) {
        int bh = idx >> 8; int m = idx & 255;
        float s = 0.f;
#pragma unroll
        for (int p = 0; p < 32; ++p) s += g_kpspart[(bh*32 + p)*256 + m];
        g_kps[idx] = s;   // KS-scaled
    }
}

// ---------------- kernel 4: main — packed fp16 data path (unchanged from R10) ----------------
#define O_QT  0
#define O_KT  4608
#define O_QPP 9216
#define O_KPP 17664
#define O_KPS 26112
#define O_QLS 26368
#define O_SSE 26432
#define O_SDP 26688
#define O_QPK 26944
#define O_LN  27456
#define O_PS  27520
#define SM_MAIN_FLOATS 27584

__global__ __launch_bounds__(512,2) void main_kernel(const float* __restrict__ value,
                                                     float* __restrict__ out) {
    extern __shared__ float smm[];
    uint32_t* uQT  = (uint32_t*)(smm + O_QT);
    uint32_t* uKT  = (uint32_t*)(smm + O_KT);
    uint32_t* sQPp = (uint32_t*)(smm + O_QPP);
    uint32_t* sKPp = (uint32_t*)(smm + O_KPP);
    uint32_t* sE16 = sKPp;
    uint32_t* sD16 = sKPp + 2304;
    uint32_t* sVt  = sKPp + 4608;
    unsigned short* sVt16 = (unsigned short*)sVt;
    uint32_t* sKVp = sKPp;
    float* sKps = smm + O_KPS;
    float* sQls = smm + O_QLS;
    float* sSe  = smm + O_SSE;
    float* sDp  = smm + O_SDP;
    float* sQpk = smm + O_QPK;
    float* sLn  = smm + O_LN;
    float* sPs  = smm + O_PS;

    int tid = threadIdx.x;
    int lane = tid & 31, wid = tid >> 5;
    int g = lane >> 2, t = lane & 3;
    int iw = wid & 3, jh = wid >> 2;
    int i0 = iw * 16;
    int bidx = blockIdx.x, blk = bidx & 31, bh = bidx >> 5;
    int b = bh / Hq, h = bh % Hq;
    int t0 = blk * 64;
    int r0 = i0 + g, r1 = r0 + 8;

    // ---- phase 0 ----
    {
        const uint32_t* gq = g_qbf + (size_t)bidx*4096;
        for (int i = tid; i < 2048; i += 512) {
            int row = i >> 5, eh = i & 31;
            uQT[row*36 + eh]        = gq[i];
            uQT[2304 + row*36 + eh] = gq[2048 + i];
        }
        const uint4* qp4 = (const uint4*)(g_qpb + (size_t)bidx*8192);
        for (int i = tid; i < 2048; i += 512) {
            int row = i >> 5, mp0 = (i & 31)*4;
            *(uint4*)(sQPp + row*132 + mp0) = qp4[i];
        }
        if (tid < 256) sKps[tid] = g_kps[bh*Mq + tid];
        if (tid < 64)  sQls[tid] = g_qls[bh*Tq + t0 + tid];
    }

    float accE[2][4], accD[2][4];
#pragma unroll
    for (int dt = 0; dt < 2; ++dt)
#pragma unroll
        for (int c = 0; c < 4; ++c) { accE[dt][c] = 0.f; accD[dt][c] = 0.f; }
    float seR0 = 0.f, seR1 = 0.f, dpR0 = 0.f, dpR1 = 0.f;

    // ---- neighbor loop ----
#pragma unroll 1
    for (int nw = 0; nw < 3; ++nw) {
        int nb = blk - 1 + nw;
        if (nb < 0 || nb >= NB) continue;
        size_t kb = (size_t)(bh*32 + nb);
        __syncthreads();   // S0
        {
            const uint32_t* gk = g_kbf + kb*4096;
            for (int i = tid; i < 2048; i += 512) {
                int row = i >> 5, eh = i & 31;
                uKT[row*36 + eh]        = gk[i];
                uKT[2304 + row*36 + eh] = gk[2048 + i];
            }
            const uint4* kp4 = (const uint4*)(g_kpb + kb*8192);
            for (int i = tid; i < 2048; i += 512) {
                int row = i >> 5, mp0 = (i & 31)*4;
                *(uint4*)(sKPp + row*132 + mp0) = kp4[i];
            }
        }
        __syncthreads();   // S1

        float Cqk[2][4], Cdp[2][4];
#pragma unroll
        for (int jt = 0; jt < 2; ++jt)
#pragma unroll
            for (int c = 0; c < 4; ++c) { Cqk[jt][c] = 0.f; Cdp[jt][c] = 0.f; }

        // QK: bf16 3-term split
#pragma unroll
        for (int kc = 0; kc < 4; ++kc) {
            int k8 = kc*8;
            uint32_t ah0 = uQT[r0*36 + k8 + t],     ah1 = uQT[r1*36 + k8 + t];
            uint32_t ah2 = uQT[r0*36 + k8 + t + 4], ah3 = uQT[r1*36 + k8 + t + 4];
            uint32_t al0 = uQT[2304 + r0*36 + k8 + t],     al1 = uQT[2304 + r1*36 + k8 + t];
            uint32_t al2 = uQT[2304 + r0*36 + k8 + t + 4], al3 = uQT[2304 + r1*36 + k8 + t + 4];
#pragma unroll
            for (int jt = 0; jt < 2; ++jt) {
                int j = jh*16 + jt*8 + g;
                uint32_t bh0 = uKT[j*36 + k8 + t],        bh1 = uKT[j*36 + k8 + t + 4];
                uint32_t bl0 = uKT[2304 + j*36 + k8 + t], bl1 = uKT[2304 + j*36 + k8 + t + 4];
                mma_bf16(Cqk[jt], ah0,ah1,ah2,ah3, bh0,bh1);
                mma_bf16(Cqk[jt], ah0,ah1,ah2,ah3, bl0,bl1);
                mma_bf16(Cqk[jt], al0,al1,al2,al3, bh0,bh1);
            }
        }
        // dp (KS-scaled): packed fp16, K=256
#pragma unroll
        for (int kc = 0; kc < 16; ++kc) {
            int k8 = kc*8;
            uint32_t a0 = sQPp[r0*132 + k8 + t],     a1 = sQPp[r1*132 + k8 + t];
            uint32_t a2 = sQPp[r0*132 + k8 + t + 4], a3 = sQPp[r1*132 + k8 + t + 4];
#pragma unroll
            for (int jt = 0; jt < 2; ++jt) {
                int j = jh*16 + jt*8 + g;
                uint32_t b0 = sKPp[j*132 + k8 + t], b1 = sKPp[j*132 + k8 + t + 4];
                mma_f16(Cdp[jt], a0,a1,a2,a3, b0,b1);
            }
        }
        __syncthreads();   // S2

        // E/DP pack (fp16) + row sums; stage V transposed fp16
#pragma unroll
        for (int jt = 0; jt < 2; ++jt) {
            int j0 = jh*16 + jt*8;
            float e00 = __expf(TEMP*Cqk[jt][0]);
            float e01 = __expf(TEMP*Cqk[jt][1]);
            float e10 = __expf(TEMP*Cqk[jt][2]);
            float e11 = __expf(TEMP*Cqk[jt][3]);
            seR0 += e00 + e01;  seR1 += e10 + e11;
            dpR0 += Cdp[jt][0] + Cdp[jt][1];
            dpR1 += Cdp[jt][2] + Cdp[jt][3];
            int jp = (j0 >> 1) + t;
            sE16[r0*36 + jp] = pack_f16(e00, e01);
            sE16[r1*36 + jp] = pack_f16(e10, e11);
            sD16[r0*36 + jp] = pack_f16(Cdp[jt][0], Cdp[jt][1]);
            sD16[r1*36 + jp] = pack_f16(Cdp[jt][2], Cdp[jt][3]);
        }
        {
            const float* vb = value + ((size_t)(b*Tq + nb*64)*Hq + h)*Eq;
            for (int i2 = tid; i2 < 1024; i2 += 512) {
                int j = i2 >> 4, d0 = (i2 & 15)*4;
                float4 v4 = *(const float4*)(vb + (size_t)j*ROWSTRIDE + d0);
                sVt16[(d0+0)*72 + j] = __half_as_ushort(__float2half_rn(v4.x));
                sVt16[(d0+1)*72 + j] = __half_as_ushort(__float2half_rn(v4.y));
                sVt16[(d0+2)*72 + j] = __half_as_ushort(__float2half_rn(v4.z));
                sVt16[(d0+3)*72 + j] = __half_as_ushort(__float2half_rn(v4.w));
            }
        }
        __syncthreads();   // S3

        // accE += E.V ; accD += DP.V   (fp16)
#pragma unroll
        for (int kc = 0; kc < 4; ++kc) {
            int k8 = kc*8;
            uint32_t aE0 = sE16[r0*36 + k8 + t],     aE1 = sE16[r1*36 + k8 + t];
            uint32_t aE2 = sE16[r0*36 + k8 + t + 4], aE3 = sE16[r1*36 + k8 + t + 4];
            uint32_t aD0 = sD16[r0*36 + k8 + t],     aD1 = sD16[r1*36 + k8 + t];
            uint32_t aD2 = sD16[r0*36 + k8 + t + 4], aD3 = sD16[r1*36 + k8 + t + 4];
#pragma unroll
            for (int dt = 0; dt < 2; ++dt) {
                int d = jh*16 + dt*8 + g;
                uint32_t b0 = sVt[d*36 + k8 + t], b1 = sVt[d*36 + k8 + t + 4];
                mma_f16(accE[dt], aE0,aE1,aE2,aE3, b0,b1);
                mma_f16(accD[dt], aD0,aD1,aD2,aD3, b0,b1);
            }
        }
    }

    // ---- row stats ----
    seR0 += __shfl_xor_sync(0xffffffffu, seR0, 1);
    seR0 += __shfl_xor_sync(0xffffffffu, seR0, 2);
    seR1 += __shfl_xor_sync(0xffffffffu, seR1, 1);
    seR1 += __shfl_xor_sync(0xffffffffu, seR1, 2);
    dpR0 += __shfl_xor_sync(0xffffffffu, dpR0, 1);
    dpR0 += __shfl_xor_sync(0xffffffffu, dpR0, 2);
    dpR1 += __shfl_xor_sync(0xffffffffu, dpR1, 1);
    dpR1 += __shfl_xor_sync(0xffffffffu, dpR1, 2);
    if (t == 0) {
        sSe[jh*64 + r0] = seR0; sSe[jh*64 + r1] = seR1;
        sDp[jh*64 + r0] = dpR0; sDp[jh*64 + r1] = dpR1;
    }
    __syncthreads();
    // stage kv fp16 (scaled) [d][132]
    {
        const uint4* kv4 = (const uint4*)(g_kvf16 + (size_t)bh*16384);
        for (int i = tid; i < 2048; i += 512) {
            int row = i >> 5, mp0 = (i & 31)*4;
            *(uint4*)(sKVp + row*132 + mp0) = kv4[i];
        }
    }
    __syncthreads();

    // qp_kp_1 partials (fp16 q' x scaled kps — consistent with dp)
    {
        int part = tid >> 6, ii = tid & 63;
        float s = 0.f;
#pragma unroll
        for (int k = 0; k < 16; ++k) {
            uint32_t u = sQPp[ii*132 + part*16 + k];
            int m2 = (part*16 + k)*2;
            s += f16lo(u) * sKps[m2] + f16hi(u) * sKps[m2+1];
        }
        sQpk[part*64 + ii] = s;
    }

    // C2 = q'.kv (fp16, scaled)
    float C2[2][4];
#pragma unroll
    for (int dt = 0; dt < 2; ++dt)
#pragma unroll
        for (int c = 0; c < 4; ++c) C2[dt][c] = 0.f;
#pragma unroll
    for (int kc = 0; kc < 16; ++kc) {
        int k8 = kc*8;
        uint32_t a0 = sQPp[r0*132 + k8 + t],     a1 = sQPp[r1*132 + k8 + t];
        uint32_t a2 = sQPp[r0*132 + k8 + t + 4], a3 = sQPp[r1*132 + k8 + t + 4];
#pragma unroll
        for (int dt = 0; dt < 2; ++dt) {
            int d = jh*16 + dt*8 + g;
            uint32_t b0 = sKVp[d*132 + k8 + t], b1 = sKVp[d*132 + k8 + t + 4];
            mma_f16(C2[dt], a0,a1,a2,a3, b0,b1);
        }
    }

    __syncthreads();
    if (tid < 64) {
        float qpk1 = 0.f;
#pragma unroll
        for (int p = 0; p < 8; ++p) qpk1 += sQpk[p*64 + tid];
        float se = sSe[tid] + sSe[64+tid] + sSe[128+tid] + sSe[192+tid];
        float dp = sDp[tid] + sDp[64+tid] + sDp[128+tid] + sDp[192+tid];
        float lse = __logf(se);
        float pls = sQls[tid] - HALF_LOG_M;
        float lr  = __logf(fmaxf(qpk1 - dp, 1e-30f)) + LOG_KS + pls;
        float mxv = fmaxf(lse, lr);
        float ln  = mxv + log1pf(__expf(-fabsf(lse - lr)));
        sLn[tid] = ln;
        sPs[tid] = __expf(pls - ln);
    }
    __syncthreads();
    float iE0 = __expf(-sLn[r0]), iE1 = __expf(-sLn[r1]);
    float ps0 = sPs[r0] * 256.f, ps1 = sPs[r1] * 256.f;

    // ---- epilogue ----
    float* ob = out + ((size_t)(b*Tq + t0)*Hq + h)*Eq;
#pragma unroll
    for (int dt = 0; dt < 2; ++dt) {
        int d = jh*16 + dt*8 + 2*t;
        float2 o0, o1;
        o0.x = accE[dt][0]*iE0 + (C2[dt][0] - accD[dt][0])*ps0;
        o0.y = accE[dt][1]*iE0 + (C2[dt][1] - accD[dt][1])*ps0;
        o1.x = accE[dt][2]*iE1 + (C2[dt][2] - accD[dt][2])*ps1;
        o1.y = accE[dt][3]*iE1 + (C2[dt][3] - accD[dt][3])*ps1;
        *(float2*)(ob + (size_t)r0*ROWSTRIDE + d) = o0;
        *(float2*)(ob + (size_t)r1*ROWSTRIDE + d) = o1;
    }
}

// ---------------- launch ----------------
extern "C" void kernel_launch(void* const* d_in, const int* in_sizes, int n_in,
                              void* d_out, int out_size) {
    const float* query = (const float*)d_in[0];
    const float* key   = (const float*)d_in[1];
    const float* value = (const float*)d_in[2];
    const float* proj  = (const float*)d_in[3];
    float* out = (float*)d_out;

    const int SM_SIDES = SM_SIDES_FLOATS * 4;  // 87808
    const int SM_MAIN  = SM_MAIN_FLOATS * 4;   // 110336

    cudaFuncSetAttribute(sides_kernel, cudaFuncAttributeMaxDynamicSharedMemorySize, SM_SIDES);
    cudaFuncSetAttribute(main_kernel,  cudaFuncAttributeMaxDynamicSharedMemorySize, SM_MAIN);

    sides_kernel<<<dim3(BH*NB, 2), 256, SM_SIDES>>>(key, query, proj, value);
    reduce_kernel<<<(BH*Mq*Eq + 255)/256, 256>>>();
    main_kernel<<<BH*NB, 512, SM_MAIN>>>(value, out);
}

// round 13
// speedup vs baseline: 3.4702x; 1.1909x over previous
#include <cuda_runtime.h>
#include <cuda_bf16.h>
#include <cuda_fp16.h>
#include <math.h>
#include <stdint.h>

#define Bq 2
#define Tq 2048
#define Hq 12
#define Eq 64
#define Mq 256
#define NB 32
#define BH 24
#define ROWSTRIDE (Hq*Eq)

#define TEMP 0.125f
#define DN 0.35355339059327379f
#define HALF_LOG_M 2.7725887222397811f
#define NEG_INF __int_as_float(0xff800000)
#define KS 0.00390625f                 // 2^-8 prime-side (k) scale
#define LOG_KS 5.5451774444795624753f  // -log(KS) = 8*ln2
#define SQ 8.0f                        // fixed q-side shift (replaces s_q rowmax)

// ---------------- device scratch ----------------
__device__ uint32_t g_pbf[16384];                // proj*DN bf16 planes, per chunk: 2048 hi + 2048 lo
__device__ uint32_t g_qbf[BH*NB*4096];           // raw q bf16 planes [row][e]: hi 2048 u32, lo 2048
__device__ uint32_t g_kbf[BH*NB*4096];           // raw k bf16 planes
__device__ __align__(16) uint32_t g_qpb[BH*NB*8192]; // q'=exp(qd-SQ) fp16 packed [i][m/2]
__device__ __align__(16) uint32_t g_kpb[BH*NB*8192]; // k'*KS fp16 packed [j][m/2]
__device__ float g_qls [BH*Tq];
__device__ __align__(16) unsigned short g_kvf16[BH*Eq*Mq]; // kv*KS fp16 [d][m]
__device__ float g_kps [BH*Mq];                  // scaled: sum_j f16(k'*KS)
__device__ float g_kvpart [BH*32*Mq*Eq];         // KS-scaled kv partials [m][d]
__device__ float g_kpspart[BH*32*Mq];

// ---------------- helpers ----------------
__device__ __forceinline__ void mma_bf16(float c[4],
        uint32_t a0, uint32_t a1, uint32_t a2, uint32_t a3, uint32_t b0, uint32_t b1)
{
    asm volatile(
        "mma.sync.aligned.m16n8k16.row.col.f32.bf16.bf16.f32 "
        "{%0,%1,%2,%3}, {%4,%5,%6,%7}, {%8,%9}, {%0,%1,%2,%3};\n"
        : "+f"(c[0]), "+f"(c[1]), "+f"(c[2]), "+f"(c[3])
        : "r"(a0), "r"(a1), "r"(a2), "r"(a3), "r"(b0), "r"(b1));
}

__device__ __forceinline__ void mma_f16(float c[4],
        uint32_t a0, uint32_t a1, uint32_t a2, uint32_t a3, uint32_t b0, uint32_t b1)
{
    asm volatile(
        "mma.sync.aligned.m16n8k16.row.col.f32.f16.f16.f32 "
        "{%0,%1,%2,%3}, {%4,%5,%6,%7}, {%8,%9}, {%0,%1,%2,%3};\n"
        : "+f"(c[0]), "+f"(c[1]), "+f"(c[2]), "+f"(c[3])
        : "r"(a0), "r"(a1), "r"(a2), "r"(a3), "r"(b0), "r"(b1));
}

__device__ __forceinline__ void split2_bf16(float x, float y, uint32_t &hi, uint32_t &lo) {
    __nv_bfloat16 hx = __float2bfloat16(x);
    __nv_bfloat16 hy = __float2bfloat16(y);
    __nv_bfloat16 lx = __float2bfloat16(x - __bfloat162float(hx));
    __nv_bfloat16 ly = __float2bfloat16(y - __bfloat162float(hy));
    hi = ((uint32_t)__bfloat16_as_ushort(hy) << 16) | (uint32_t)__bfloat16_as_ushort(hx);
    lo = ((uint32_t)__bfloat16_as_ushort(ly) << 16) | (uint32_t)__bfloat16_as_ushort(lx);
}

__device__ __forceinline__ uint32_t pack_f16(float x, float y) {
    __half2 h = __floats2half2_rn(x, y);
    return *reinterpret_cast<uint32_t*>(&h);
}
__device__ __forceinline__ float f16lo(uint32_t u) {
    return __half2float(__ushort_as_half((unsigned short)(u & 0xffffu)));
}
__device__ __forceinline__ float f16hi(uint32_t u) {
    return __half2float(__ushort_as_half((unsigned short)(u >> 16)));
}
__device__ __forceinline__ float bf16lo_f(uint32_t u) {
    return __bfloat162float(__ushort_as_bfloat16((unsigned short)(u & 0xffffu)));
}
__device__ __forceinline__ float bf16hi_f(uint32_t u) {
    return __bfloat162float(__ushort_as_bfloat16((unsigned short)(u >> 16)));
}

// ---------------- kernel 0: proj planes precompute ----------------
__global__ void pinit_kernel(const float* __restrict__ proj) {
    int idx = blockIdx.x*256 + threadIdx.x;   // 8192 float2 pairs
    if (idx < 8192) {
        int c = idx >> 11, rem = idx & 2047;
        int mm = rem >> 5, eh = rem & 31;
        float2 v = *(const float2*)(proj + (size_t)(c*64 + mm)*64 + eh*2);
        uint32_t hi, lo;
        split2_bf16(v.x * DN, v.y * DN, hi, lo);
        g_pbf[c*4096 + mm*32 + eh]        = hi;
        g_pbf[c*4096 + 2048 + mm*32 + eh] = lo;
    }
}

// ---------------- kernel 1: sides — fused k+q feature GEMMs + kv partials ----------------
// smem floats: uTk 4608 | uTq 4608 | uP 4608 | diag 128 | part 1024 | sKp16 9216 | sVt 2304 = 26496
#define SD_UTQ  4608
#define SD_UP   9216
#define SD_DIAG 13824
#define SD_PART 13952
#define SD_KP16 14976
#define SD_VT   24192
#define SM_SIDES_FLOATS 26496

__global__ __launch_bounds__(256,2) void sides_kernel(const float* __restrict__ key,
                                                      const float* __restrict__ query,
                                                      const float* __restrict__ value) {
    extern __shared__ float sm[];
    uint32_t* uTk = (uint32_t*)sm;
    uint32_t* uTq = (uint32_t*)(sm + SD_UTQ);
    uint32_t* uP  = (uint32_t*)(sm + SD_UP);
    float* sDiag = sm + SD_DIAG;   // [0:64) k, [64:128) q
    float* sPart = sm + SD_PART;   // [4 rt][256]
    unsigned short* sKp16 = (unsigned short*)(sm + SD_KP16);  // [m][j] stride 72 halfs
    uint32_t*       sKp32 = (uint32_t*)(sm + SD_KP16);
    unsigned short* sVt16 = (unsigned short*)(sm + SD_VT);    // [d][j] stride 72 halfs
    uint32_t*       sVt32 = (uint32_t*)(sm + SD_VT);

    int tid = threadIdx.x;
    int lane = tid & 31, wid = tid >> 5;
    int g = lane >> 2, t = lane & 3;
    int rt = wid & 3;
    int mh = wid >> 2;
    int r0 = rt*16 + g, r1 = r0 + 8;
    int bidx = blockIdx.x, blk = bidx & 31, bh = bidx >> 5;
    int b = bh / Hq, h = bh % Hq;
    int t0 = blk * 64;

    // stage k and q tiles as bf16 planes; write raw global planes
    const float* ksrc = key   + ((size_t)(b*Tq + t0)*Hq + h)*Eq;
    const float* qsrc = query + ((size_t)(b*Tq + t0)*Hq + h)*Eq;
    uint32_t* gk = g_kbf + (size_t)bidx * 4096;
    uint32_t* gq = g_qbf + (size_t)bidx * 4096;
    for (int i = tid; i < 2048; i += 256) {
        int row = i >> 5, eh = i & 31;
        uint32_t hi, lo;
        float2 vk = *(const float2*)(ksrc + (size_t)row*ROWSTRIDE + eh*2);
        split2_bf16(vk.x, vk.y, hi, lo);
        uTk[row*36 + eh] = hi;
        uTk[2304 + row*36 + eh] = lo;
        gk[row*32 + eh] = hi;
        gk[2048 + row*32 + eh] = lo;
        float2 vq = *(const float2*)(qsrc + (size_t)row*ROWSTRIDE + eh*2);
        split2_bf16(vq.x, vq.y, hi, lo);
        uTq[row*36 + eh] = hi;
        uTq[2304 + row*36 + eh] = lo;
        gq[row*32 + eh] = hi;
        gq[2048 + row*32 + eh] = lo;
    }
    __syncthreads();
    if (tid < 128) {
        int path = tid >> 6, row = tid & 63;
        const uint32_t* uT = path ? uTq : uTk;
        float s = 0.f;
#pragma unroll
        for (int eh = 0; eh < 32; ++eh) {
            uint32_t hu = uT[row*36 + eh], lu = uT[2304 + row*36 + eh];
            float x0 = bf16lo_f(hu) + bf16lo_f(lu);
            float x1 = bf16hi_f(hu) + bf16hi_f(lu);
            s += x0*x0 + x1*x1;
        }
        sDiag[tid] = 0.0625f * s;
    }
    __syncthreads();
    float dg0 = sDiag[r0], dg1 = sDiag[r1];   // k diag for this warp's rows

    uint32_t* kpb = g_kpb + (size_t)bidx * 8192;
    uint32_t* qpb = g_qpb + (size_t)bidx * 8192;

    // 4 chunks of 64 features: shared proj staging, k GEMM + q GEMM, chunk-local writeout
#pragma unroll 1
    for (int c = 0; c < 4; ++c) {
        __syncthreads();
        {
            const uint4* pb = (const uint4*)(g_pbf + c*4096);
            for (int i = tid; i < 1024; i += 256) {
                uint4 v4 = pb[i];
                int pl = (i >> 9);            // 0 hi, 1 lo
                int i2 = i & 511;
                int mm = i2 >> 3, e4 = (i2 & 7)*4;
                *(uint4*)(uP + pl*2304 + mm*36 + e4) = v4;
            }
        }
        __syncthreads();

        float Ck[4][4], Cq[4][4];
#pragma unroll
        for (int mt = 0; mt < 4; ++mt)
#pragma unroll
            for (int k = 0; k < 4; ++k) { Ck[mt][k] = 0.f; Cq[mt][k] = 0.f; }

#pragma unroll
        for (int kc = 0; kc < 4; ++kc) {
            int k8 = kc*8;
            uint32_t kh0 = uTk[r0*36 + k8 + t],     kh1 = uTk[r1*36 + k8 + t];
            uint32_t kh2 = uTk[r0*36 + k8 + t + 4], kh3 = uTk[r1*36 + k8 + t + 4];
            uint32_t kl0 = uTk[2304 + r0*36 + k8 + t],     kl1 = uTk[2304 + r1*36 + k8 + t];
            uint32_t kl2 = uTk[2304 + r0*36 + k8 + t + 4], kl3 = uTk[2304 + r1*36 + k8 + t + 4];
            uint32_t qh0 = uTq[r0*36 + k8 + t],     qh1 = uTq[r1*36 + k8 + t];
            uint32_t qh2 = uTq[r0*36 + k8 + t + 4], qh3 = uTq[r1*36 + k8 + t + 4];
            uint32_t ql0 = uTq[2304 + r0*36 + k8 + t],     ql1 = uTq[2304 + r1*36 + k8 + t];
            uint32_t ql2 = uTq[2304 + r0*36 + k8 + t + 4], ql3 = uTq[2304 + r1*36 + k8 + t + 4];
#pragma unroll
            for (int mt = 0; mt < 4; ++mt) {
                int mc = mh*32 + mt*8 + g;
                uint32_t bh0 = uP[mc*36 + k8 + t],        bh1 = uP[mc*36 + k8 + t + 4];
                uint32_t bl0 = uP[2304 + mc*36 + k8 + t], bl1 = uP[2304 + mc*36 + k8 + t + 4];
                mma_bf16(Ck[mt], kh0,kh1,kh2,kh3, bh0,bh1);
                mma_bf16(Ck[mt], kh0,kh1,kh2,kh3, bl0,bl1);
                mma_bf16(Ck[mt], kl0,kl1,kl2,kl3, bh0,bh1);
                mma_bf16(Cq[mt], qh0,qh1,qh2,qh3, bh0,bh1);
                mma_bf16(Cq[mt], qh0,qh1,qh2,qh3, bl0,bl1);
                mma_bf16(Cq[mt], ql0,ql1,ql2,ql3, bh0,bh1);
            }
        }

        // chunk-local writeout (k': exp - diag, *KS; q': exp(. - SQ))
#pragma unroll
        for (int mt = 0; mt < 4; ++mt) {
            int m0 = c*64 + mh*32 + mt*8 + 2*t;
            int mp = m0 >> 1;
            float e0 = __expf(Ck[mt][0] - dg0);
            float e1 = __expf(Ck[mt][1] - dg0);
            float e2 = __expf(Ck[mt][2] - dg1);
            float e3 = __expf(Ck[mt][3] - dg1);
            uint32_t p0 = pack_f16(e0*KS, e1*KS);
            uint32_t p1 = pack_f16(e2*KS, e3*KS);
            kpb[r0*128 + mp] = p0;
            kpb[r1*128 + mp] = p1;
            sKp16[m0*72 + r0]     = (unsigned short)(p0 & 0xffffu);
            sKp16[(m0+1)*72 + r0] = (unsigned short)(p0 >> 16);
            sKp16[m0*72 + r1]     = (unsigned short)(p1 & 0xffffu);
            sKp16[(m0+1)*72 + r1] = (unsigned short)(p1 >> 16);
            float pm0 = f16lo(p0) + f16lo(p1);
            float pm1 = f16hi(p0) + f16hi(p1);
            pm0 += __shfl_xor_sync(0xffffffffu, pm0, 4);
            pm0 += __shfl_xor_sync(0xffffffffu, pm0, 8);
            pm0 += __shfl_xor_sync(0xffffffffu, pm0, 16);
            pm1 += __shfl_xor_sync(0xffffffffu, pm1, 4);
            pm1 += __shfl_xor_sync(0xffffffffu, pm1, 8);
            pm1 += __shfl_xor_sync(0xffffffffu, pm1, 16);
            if (g == 0) {
                sPart[rt*256 + m0]     = pm0;
                sPart[rt*256 + m0 + 1] = pm1;
            }
            qpb[r0*128 + mp] = pack_f16(__expf(Cq[mt][0] - SQ), __expf(Cq[mt][1] - SQ));
            qpb[r1*128 + mp] = pack_f16(__expf(Cq[mt][2] - SQ), __expf(Cq[mt][3] - SQ));
        }
    }

    // stage v transposed fp16 [d][j]
    {
        const float* vb = value + ((size_t)(b*Tq + t0)*Hq + h)*Eq;
        for (int i2 = tid; i2 < 1024; i2 += 256) {
            int j = i2 >> 4, d0 = (i2 & 15)*4;
            float4 v4 = *(const float4*)(vb + (size_t)j*ROWSTRIDE + d0);
            sVt16[(d0+0)*72 + j] = __half_as_ushort(__float2half_rn(v4.x));
            sVt16[(d0+1)*72 + j] = __half_as_ushort(__float2half_rn(v4.y));
            sVt16[(d0+2)*72 + j] = __half_as_ushort(__float2half_rn(v4.z));
            sVt16[(d0+3)*72 + j] = __half_as_ushort(__float2half_rn(v4.w));
        }
    }
    __syncthreads();

    g_kpspart[(size_t)bidx*256 + tid] =
        sPart[tid] + sPart[256+tid] + sPart[512+tid] + sPart[768+tid];
    if (tid < 64)
        g_qls[bh*Tq + t0 + tid] = SQ - sDiag[64 + tid] - HALF_LOG_M;   // fixed shift SQ

    // kv partials: KC[m][d] = sum_j k'[m][j]*v[j][d]  (fp16 MMA, f32 accum)
    float KC[2][8][4];
#pragma unroll
    for (int it = 0; it < 2; ++it)
#pragma unroll
        for (int nt = 0; nt < 8; ++nt)
#pragma unroll
            for (int k = 0; k < 4; ++k) KC[it][nt][k] = 0.f;

#pragma unroll
    for (int kc = 0; kc < 4; ++kc) {
        int k8 = kc*8;
        uint32_t a[2][4];
#pragma unroll
        for (int it = 0; it < 2; ++it) {
            int rb = wid*32 + it*16;
            a[it][0] = sKp32[(rb+g)*36 + k8 + t];
            a[it][1] = sKp32[(rb+g+8)*36 + k8 + t];
            a[it][2] = sKp32[(rb+g)*36 + k8 + t + 4];
            a[it][3] = sKp32[(rb+g+8)*36 + k8 + t + 4];
        }
#pragma unroll
        for (int nt = 0; nt < 8; ++nt) {
            int d = nt*8 + g;
            uint32_t b0 = sVt32[d*36 + k8 + t], b1 = sVt32[d*36 + k8 + t + 4];
#pragma unroll
            for (int it = 0; it < 2; ++it)
                mma_f16(KC[it][nt], a[it][0],a[it][1],a[it][2],a[it][3], b0,b1);
        }
    }
    float* kvp = g_kvpart + (size_t)bidx * 16384;
#pragma unroll
    for (int it = 0; it < 2; ++it) {
        int m0 = wid*32 + it*16 + g;
#pragma unroll
        for (int nt = 0; nt < 8; ++nt) {
            int d = nt*8 + 2*t;
            *(float2*)(kvp + (size_t)m0*64 + d)     = make_float2(KC[it][nt][0], KC[it][nt][1]);
            *(float2*)(kvp + (size_t)(m0+8)*64 + d) = make_float2(KC[it][nt][2], KC[it][nt][3]);
        }
    }
}

// ---------------- kernel 2b: reduce partials (fp16 kv transpose, scaled) ----------------
__global__ void reduce_kernel() {
    int idx = blockIdx.x*256 + threadIdx.x;
    if (idx < BH*Mq*Eq) {
        int bh = idx >> 14;
        int rem = idx & 16383;
        float s = 0.f;
#pragma unroll
        for (int p = 0; p < 32; ++p) s += g_kvpart[(size_t)(bh*32 + p)*16384 + rem];
        int m = rem >> 6, d = rem & 63;
        g_kvf16[bh*16384 + d*256 + m] = __half_as_ushort(__float2half_rn(s));
    }
    if (idx < BH*Mq) {
        int bh = idx >> 8; int m = idx & 255;
        float s = 0.f;
#pragma unroll
        for (int p = 0; p < 32; ++p) s += g_kpspart[(bh*32 + p)*256 + m];
        g_kps[idx] = s;
    }
}

// ---------------- kernel 4: main — packed fp16 data path (unchanged from R11) ----------------
#define O_QT  0
#define O_KT  4608
#define O_QPP 9216
#define O_KPP 17664
#define O_KPS 26112
#define O_QLS 26368
#define O_SSE 26432
#define O_SDP 26688
#define O_QPK 26944
#define O_LN  27456
#define O_PS  27520
#define SM_MAIN_FLOATS 27584

__global__ __launch_bounds__(512,2) void main_kernel(const float* __restrict__ value,
                                                     float* __restrict__ out) {
    extern __shared__ float smm[];
    uint32_t* uQT  = (uint32_t*)(smm + O_QT);
    uint32_t* uKT  = (uint32_t*)(smm + O_KT);
    uint32_t* sQPp = (uint32_t*)(smm + O_QPP);
    uint32_t* sKPp = (uint32_t*)(smm + O_KPP);
    uint32_t* sE16 = sKPp;
    uint32_t* sD16 = sKPp + 2304;
    uint32_t* sVt  = sKPp + 4608;
    unsigned short* sVt16 = (unsigned short*)sVt;
    uint32_t* sKVp = sKPp;
    float* sKps = smm + O_KPS;
    float* sQls = smm + O_QLS;
    float* sSe  = smm + O_SSE;
    float* sDp  = smm + O_SDP;
    float* sQpk = smm + O_QPK;
    float* sLn  = smm + O_LN;
    float* sPs  = smm + O_PS;

    int tid = threadIdx.x;
    int lane = tid & 31, wid = tid >> 5;
    int g = lane >> 2, t = lane & 3;
    int iw = wid & 3, jh = wid >> 2;
    int i0 = iw * 16;
    int bidx = blockIdx.x, blk = bidx & 31, bh = bidx >> 5;
    int b = bh / Hq, h = bh % Hq;
    int t0 = blk * 64;
    int r0 = i0 + g, r1 = r0 + 8;

    // ---- phase 0 ----
    {
        const uint32_t* gq = g_qbf + (size_t)bidx*4096;
        for (int i = tid; i < 2048; i += 512) {
            int row = i >> 5, eh = i & 31;
            uQT[row*36 + eh]        = gq[i];
            uQT[2304 + row*36 + eh] = gq[2048 + i];
        }
        const uint4* qp4 = (const uint4*)(g_qpb + (size_t)bidx*8192);
        for (int i = tid; i < 2048; i += 512) {
            int row = i >> 5, mp0 = (i & 31)*4;
            *(uint4*)(sQPp + row*132 + mp0) = qp4[i];
        }
        if (tid < 256) sKps[tid] = g_kps[bh*Mq + tid];
        if (tid < 64)  sQls[tid] = g_qls[bh*Tq + t0 + tid];
    }

    float accE[2][4], accD[2][4];
#pragma unroll
    for (int dt = 0; dt < 2; ++dt)
#pragma unroll
        for (int c = 0; c < 4; ++c) { accE[dt][c] = 0.f; accD[dt][c] = 0.f; }
    float seR0 = 0.f, seR1 = 0.f, dpR0 = 0.f, dpR1 = 0.f;

    // ---- neighbor loop ----
#pragma unroll 1
    for (int nw = 0; nw < 3; ++nw) {
        int nb = blk - 1 + nw;
        if (nb < 0 || nb >= NB) continue;
        size_t kb = (size_t)(bh*32 + nb);
        __syncthreads();   // S0
        {
            const uint32_t* gk = g_kbf + kb*4096;
            for (int i = tid; i < 2048; i += 512) {
                int row = i >> 5, eh = i & 31;
                uKT[row*36 + eh]        = gk[i];
                uKT[2304 + row*36 + eh] = gk[2048 + i];
            }
            const uint4* kp4 = (const uint4*)(g_kpb + kb*8192);
            for (int i = tid; i < 2048; i += 512) {
                int row = i >> 5, mp0 = (i & 31)*4;
                *(uint4*)(sKPp + row*132 + mp0) = kp4[i];
            }
        }
        __syncthreads();   // S1

        float Cqk[2][4], Cdp[2][4];
#pragma unroll
        for (int jt = 0; jt < 2; ++jt)
#pragma unroll
            for (int c = 0; c < 4; ++c) { Cqk[jt][c] = 0.f; Cdp[jt][c] = 0.f; }

        // QK: bf16 3-term split
#pragma unroll
        for (int kc = 0; kc < 4; ++kc) {
            int k8 = kc*8;
            uint32_t ah0 = uQT[r0*36 + k8 + t],     ah1 = uQT[r1*36 + k8 + t];
            uint32_t ah2 = uQT[r0*36 + k8 + t + 4], ah3 = uQT[r1*36 + k8 + t + 4];
            uint32_t al0 = uQT[2304 + r0*36 + k8 + t],     al1 = uQT[2304 + r1*36 + k8 + t];
            uint32_t al2 = uQT[2304 + r0*36 + k8 + t + 4], al3 = uQT[2304 + r1*36 + k8 + t + 4];
#pragma unroll
            for (int jt = 0; jt < 2; ++jt) {
                int j = jh*16 + jt*8 + g;
                uint32_t bh0 = uKT[j*36 + k8 + t],        bh1 = uKT[j*36 + k8 + t + 4];
                uint32_t bl0 = uKT[2304 + j*36 + k8 + t], bl1 = uKT[2304 + j*36 + k8 + t + 4];
                mma_bf16(Cqk[jt], ah0,ah1,ah2,ah3, bh0,bh1);
                mma_bf16(Cqk[jt], ah0,ah1,ah2,ah3, bl0,bl1);
                mma_bf16(Cqk[jt], al0,al1,al2,al3, bh0,bh1);
            }
        }
        // dp (KS & SQ scaled): packed fp16, K=256
#pragma unroll
        for (int kc = 0; kc < 16; ++kc) {
            int k8 = kc*8;
            uint32_t a0 = sQPp[r0*132 + k8 + t],     a1 = sQPp[r1*132 + k8 + t];
            uint32_t a2 = sQPp[r0*132 + k8 + t + 4], a3 = sQPp[r1*132 + k8 + t + 4];
#pragma unroll
            for (int jt = 0; jt < 2; ++jt) {
                int j = jh*16 + jt*8 + g;
                uint32_t b0 = sKPp[j*132 + k8 + t], b1 = sKPp[j*132 + k8 + t + 4];
                mma_f16(Cdp[jt], a0,a1,a2,a3, b0,b1);
            }
        }
        __syncthreads();   // S2

        // E/DP pack (fp16) + row sums; stage V transposed fp16
#pragma unroll
        for (int jt = 0; jt < 2; ++jt) {
            int j0 = jh*16 + jt*8;
            float e00 = __expf(TEMP*Cqk[jt][0]);
            float e01 = __expf(TEMP*Cqk[jt][1]);
            float e10 = __expf(TEMP*Cqk[jt][2]);
            float e11 = __expf(TEMP*Cqk[jt][3]);
            seR0 += e00 + e01;  seR1 += e10 + e11;
            dpR0 += Cdp[jt][0] + Cdp[jt][1];
            dpR1 += Cdp[jt][2] + Cdp[jt][3];
            int jp = (j0 >> 1) + t;
            sE16[r0*36 + jp] = pack_f16(e00, e01);
            sE16[r1*36 + jp] = pack_f16(e10, e11);
            sD16[r0*36 + jp] = pack_f16(Cdp[jt][0], Cdp[jt][1]);
            sD16[r1*36 + jp] = pack_f16(Cdp[jt][2], Cdp[jt][3]);
        }
        {
            const float* vb = value + ((size_t)(b*Tq + nb*64)*Hq + h)*Eq;
            for (int i2 = tid; i2 < 1024; i2 += 512) {
                int j = i2 >> 4, d0 = (i2 & 15)*4;
                float4 v4 = *(const float4*)(vb + (size_t)j*ROWSTRIDE + d0);
                sVt16[(d0+0)*72 + j] = __half_as_ushort(__float2half_rn(v4.x));
                sVt16[(d0+1)*72 + j] = __half_as_ushort(__float2half_rn(v4.y));
                sVt16[(d0+2)*72 + j] = __half_as_ushort(__float2half_rn(v4.z));
                sVt16[(d0+3)*72 + j] = __half_as_ushort(__float2half_rn(v4.w));
            }
        }
        __syncthreads();   // S3

        // accE += E.V ; accD += DP.V   (fp16)
#pragma unroll
        for (int kc = 0; kc < 4; ++kc) {
            int k8 = kc*8;
            uint32_t aE0 = sE16[r0*36 + k8 + t],     aE1 = sE16[r1*36 + k8 + t];
            uint32_t aE2 = sE16[r0*36 + k8 + t + 4], aE3 = sE16[r1*36 + k8 + t + 4];
            uint32_t aD0 = sD16[r0*36 + k8 + t],     aD1 = sD16[r1*36 + k8 + t];
            uint32_t aD2 = sD16[r0*36 + k8 + t + 4], aD3 = sD16[r1*36 + k8 + t + 4];
#pragma unroll
            for (int dt = 0; dt < 2; ++dt) {
                int d = jh*16 + dt*8 + g;
                uint32_t b0 = sVt[d*36 + k8 + t], b1 = sVt[d*36 + k8 + t + 4];
                mma_f16(accE[dt], aE0,aE1,aE2,aE3, b0,b1);
                mma_f16(accD[dt], aD0,aD1,aD2,aD3, b0,b1);
            }
        }
    }

    // ---- row stats ----
    seR0 += __shfl_xor_sync(0xffffffffu, seR0, 1);
    seR0 += __shfl_xor_sync(0xffffffffu, seR0, 2);
    seR1 += __shfl_xor_sync(0xffffffffu, seR1, 1);
    seR1 += __shfl_xor_sync(0xffffffffu, seR1, 2);
    dpR0 += __shfl_xor_sync(0xffffffffu, dpR0, 1);
    dpR0 += __shfl_xor_sync(0xffffffffu, dpR0, 2);
    dpR1 += __shfl_xor_sync(0xffffffffu, dpR1, 1);
    dpR1 += __shfl_xor_sync(0xffffffffu, dpR1, 2);
    if (t == 0) {
        sSe[jh*64 + r0] = seR0; sSe[jh*64 + r1] = seR1;
        sDp[jh*64 + r0] = dpR0; sDp[jh*64 + r1] = dpR1;
    }
    __syncthreads();
    // stage kv fp16 (scaled) [d][132]
    {
        const uint4* kv4 = (const uint4*)(g_kvf16 + (size_t)bh*16384);
        for (int i = tid; i < 2048; i += 512) {
            int row = i >> 5, mp0 = (i & 31)*4;
            *(uint4*)(sKVp + row*132 + mp0) = kv4[i];
        }
    }
    __syncthreads();

    // qp_kp_1 partials (fp16 q' x scaled kps — consistent with dp)
    {
        int part = tid >> 6, ii = tid & 63;
        float s = 0.f;
#pragma unroll
        for (int k = 0; k < 16; ++k) {
            uint32_t u = sQPp[ii*132 + part*16 + k];
            int m2 = (part*16 + k)*2;
            s += f16lo(u) * sKps[m2] + f16hi(u) * sKps[m2+1];
        }
        sQpk[part*64 + ii] = s;
    }

    // C2 = q'.kv (fp16, scaled)
    float C2[2][4];
#pragma unroll
    for (int dt = 0; dt < 2; ++dt)
#pragma unroll
        for (int c = 0; c < 4; ++c) C2[dt][c] = 0.f;
#pragma unroll
    for (int kc = 0; kc < 16; ++kc) {
        int k8 = kc*8;
        uint32_t a0 = sQPp[r0*132 + k8 + t],     a1 = sQPp[r1*132 + k8 + t];
        uint32_t a2 = sQPp[r0*132 + k8 + t + 4], a3 = sQPp[r1*132 + k8 + t + 4];
#pragma unroll
        for (int dt = 0; dt < 2; ++dt) {
            int d = jh*16 + dt*8 + g;
            uint32_t b0 = sKVp[d*132 + k8 + t], b1 = sKVp[d*132 + k8 + t + 4];
            mma_f16(C2[dt], a0,a1,a2,a3, b0,b1);
        }
    }

    __syncthreads();
    if (tid < 64) {
        float qpk1 = 0.f;
#pragma unroll
        for (int p = 0; p < 8; ++p) qpk1 += sQpk[p*64 + tid];
        float se = sSe[tid] + sSe[64+tid] + sSe[128+tid] + sSe[192+tid];
        float dp = sDp[tid] + sDp[64+tid] + sDp[128+tid] + sDp[192+tid];
        float lse = __logf(se);
        float pls = sQls[tid] - HALF_LOG_M;
        float lr  = __logf(fmaxf(qpk1 - dp, 1e-30f)) + LOG_KS + pls;
        float mxv = fmaxf(lse, lr);
        float ln  = mxv + log1pf(__expf(-fabsf(lse - lr)));
        sLn[tid] = ln;
        sPs[tid] = __expf(pls - ln);
    }
    __syncthreads();
    float iE0 = __expf(-sLn[r0]), iE1 = __expf(-sLn[r1]);
    float ps0 = sPs[r0] * 256.f, ps1 = sPs[r1] * 256.f;

    // ---- epilogue ----
    float* ob = out + ((size_t)(b*Tq + t0)*Hq + h)*Eq;
#pragma unroll
    for (int dt = 0; dt < 2; ++dt) {
        int d = jh*16 + dt*8 + 2*t;
        float2 o0, o1;
        o0.x = accE[dt][0]*iE0 + (C2[dt][0] - accD[dt][0])*ps0;
        o0.y = accE[dt][1]*iE0 + (C2[dt][1] - accD[dt][1])*ps0;
        o1.x = accE[dt][2]*iE1 + (C2[dt][2] - accD[dt][2])*ps1;
        o1.y = accE[dt][3]*iE1 + (C2[dt][3] - accD[dt][3])*ps1;
        *(float2*)(ob + (size_t)r0*ROWSTRIDE + d) = o0;
        *(float2*)(ob + (size_t)r1*ROWSTRIDE + d) = o1;
    }
}

// ---------------- launch ----------------
extern "C" void kernel_launch(void* const* d_in, const int* in_sizes, int n_in,
                              void* d_out, int out_size) {
    const float* query = (const float*)d_in[0];
    const float* key   = (const float*)d_in[1];
    const float* value = (const float*)d_in[2];
    const float* proj  = (const float*)d_in[3];
    float* out = (float*)d_out;

    const int SM_SIDES = SM_SIDES_FLOATS * 4;  // 105984
    const int SM_MAIN  = SM_MAIN_FLOATS * 4;   // 110336

    cudaFuncSetAttribute(sides_kernel, cudaFuncAttributeMaxDynamicSharedMemorySize, SM_SIDES);
    cudaFuncSetAttribute(main_kernel,  cudaFuncAttributeMaxDynamicSharedMemorySize, SM_MAIN);

    pinit_kernel<<<32, 256>>>(proj);
    sides_kernel<<<BH*NB, 256, SM_SIDES>>>(key, query, value);
    reduce_kernel<<<(BH*Mq*Eq + 255)/256, 256>>>();
    main_kernel<<<BH*NB, 512, SM_MAIN>>>(value, out);
}